// round 1
// baseline (speedup 1.0000x reference)
#include <cuda_runtime.h>
#include <math.h>

#define HID    1024
#define FFDIM  4096
#define NHEAD  16
#define HD     64
#define BATCH  4
#define SEQ    1024
#define NTOK   (BATCH*SEQ)      // 4096
#define MAXPOS 1024

// ---------------- scratch (device globals: allocation-free) ----------------
__device__ float g_q[NTOK * HID];
__device__ float g_k[NTOK * HID];
__device__ float g_v[NTOK * HID];
__device__ float g_ctx[NTOK * HID];
__device__ float g_tmp[NTOK * HID];       // attn-dense out, then ff2 out
__device__ float g_attnout[NTOK * HID];   // LN1 output (FFN input + residual)
__device__ float g_inter[NTOK * FFDIM];   // GELU(ff1)

// ---------------- SGEMM: C[M,N] = A[M,K] @ B[K,N] + bias, opt. exact GELU ----
// 128x128 tile, BK=8, 256 threads, 8x8 per thread (split 4+4 for cf-free LDS.128)
template <int GELU>
__global__ void __launch_bounds__(256) sgemm_bias(
    const float* __restrict__ A, const float* __restrict__ Bm,
    const float* __restrict__ bias, float* __restrict__ C,
    int M, int N, int K)
{
    __shared__ float As[8][128];
    __shared__ float Bs[8][132];

    const int tid = threadIdx.x;
    const int tx  = tid & 15;
    const int ty  = tid >> 4;
    const int row0 = blockIdx.y * 128;
    const int col0 = blockIdx.x * 128;

    const int arow = tid >> 1;          // 0..127
    const int acol = (tid & 1) << 2;    // 0 or 4
    const int brow = tid >> 5;          // 0..7
    const int bcol = (tid & 31) << 2;   // 0..124

    const float* Ag = A  + (size_t)(row0 + arow) * K + acol;
    const float* Bg = Bm + (size_t)brow * N + col0 + bcol;

    float acc[8][8];
#pragma unroll
    for (int i = 0; i < 8; i++)
#pragma unroll
        for (int j = 0; j < 8; j++) acc[i][j] = 0.f;

    for (int k0 = 0; k0 < K; k0 += 8) {
        float4 av = *(const float4*)(Ag + k0);
        float4 bv = *(const float4*)(Bg + (size_t)k0 * N);
        __syncthreads();
        As[acol + 0][arow] = av.x;
        As[acol + 1][arow] = av.y;
        As[acol + 2][arow] = av.z;
        As[acol + 3][arow] = av.w;
        *(float4*)&Bs[brow][bcol] = bv;
        __syncthreads();
#pragma unroll
        for (int k = 0; k < 8; k++) {
            float a[8], b[8];
            float4 t0 = *(const float4*)&As[k][ty * 4];
            float4 t1 = *(const float4*)&As[k][ty * 4 + 64];
            a[0]=t0.x; a[1]=t0.y; a[2]=t0.z; a[3]=t0.w;
            a[4]=t1.x; a[5]=t1.y; a[6]=t1.z; a[7]=t1.w;
            float4 u0 = *(const float4*)&Bs[k][tx * 4];
            float4 u1 = *(const float4*)&Bs[k][tx * 4 + 64];
            b[0]=u0.x; b[1]=u0.y; b[2]=u0.z; b[3]=u0.w;
            b[4]=u1.x; b[5]=u1.y; b[6]=u1.z; b[7]=u1.w;
#pragma unroll
            for (int i = 0; i < 8; i++)
#pragma unroll
                for (int j = 0; j < 8; j++)
                    acc[i][j] = fmaf(a[i], b[j], acc[i][j]);
        }
    }

#pragma unroll
    for (int i = 0; i < 8; i++) {
        int r = row0 + ty * 4 + ((i < 4) ? i : (64 + i - 4));
#pragma unroll
        for (int j = 0; j < 8; j++) {
            int c = col0 + tx * 4 + ((j < 4) ? j : (64 + j - 4));
            float v = acc[i][j] + bias[c];
            if (GELU) v = 0.5f * v * (1.0f + erff(v * 0.70710678118654752f));
            C[(size_t)r * N + c] = v;
        }
    }
}

// ---------------- LayerNorm(x + res) * g + b ----------------
__global__ void __launch_bounds__(256) ln_residual(
    const float* __restrict__ x, const float* __restrict__ res,
    const float* __restrict__ g, const float* __restrict__ b,
    float* __restrict__ out)
{
    __shared__ float buf[HID];
    __shared__ float red[8];
    const int row = blockIdx.x;
    const int tid = threadIdx.x;
    const size_t base = (size_t)row * HID;

    float s = 0.f;
    for (int c = tid; c < HID; c += 256) {
        float v = x[base + c] + res[base + c];
        buf[c] = v;
        s += v;
    }
#pragma unroll
    for (int o = 16; o; o >>= 1) s += __shfl_xor_sync(0xffffffffu, s, o);
    if ((tid & 31) == 0) red[tid >> 5] = s;
    __syncthreads();
    if (tid < 8) {
        s = red[tid];
#pragma unroll
        for (int o = 4; o; o >>= 1) s += __shfl_xor_sync(0xffu, s, o, 8);
        if (tid == 0) red[0] = s;
    }
    __syncthreads();
    float mean = red[0] * (1.0f / HID);
    __syncthreads();

    float vs = 0.f;
    for (int c = tid; c < HID; c += 256) {
        float d = buf[c] - mean;
        vs += d * d;
    }
#pragma unroll
    for (int o = 16; o; o >>= 1) vs += __shfl_xor_sync(0xffffffffu, vs, o);
    if ((tid & 31) == 0) red[tid >> 5] = vs;
    __syncthreads();
    if (tid < 8) {
        vs = red[tid];
#pragma unroll
        for (int o = 4; o; o >>= 1) vs += __shfl_xor_sync(0xffu, vs, o, 8);
        if (tid == 0) red[0] = vs;
    }
    __syncthreads();
    float inv = rsqrtf(red[0] * (1.0f / HID) + 1e-12f);
    __syncthreads();

    for (int c = tid; c < HID; c += 256)
        out[base + c] = (buf[c] - mean) * inv * g[c] + b[c];
}

// ---------------- fused attention with Toeplitz relative-position bias -------
// block = (l-tile 64 rows, one (b,h)); online softmax over 16 r-tiles of 64.
// S[l,r] = q.k + q.E[l-r] + k.E[l-r]; E band (127 rows) lives in smem.
#define ASTR 65
#define SMEM_FLOATS (4 * 64 * ASTR + 127 * ASTR)

__global__ void __launch_bounds__(256) attn_kernel(
    const float* __restrict__ Q, const float* __restrict__ K,
    const float* __restrict__ V, const float* __restrict__ dist,
    const float* __restrict__ mask, const float* __restrict__ hm,
    float* __restrict__ ctx)
{
    extern __shared__ float sm[];
    float* Qs = sm;                    // 64 x 65
    float* Ks = Qs + 64 * ASTR;        // 64 x 65
    float* Vs = Ks + 64 * ASTR;        // 64 x 65
    float* Ps = Vs + 64 * ASTR;        // 64 x 65
    float* Es = Ps + 64 * ASTR;        // 127 x 65

    const int lt = blockIdx.x;          // 0..15
    const int bh = blockIdx.y;          // 0..63
    const int b  = bh >> 4;
    const int h  = bh & 15;
    const int l0 = lt * 64;
    const int tid = threadIdx.x;
    const int tx  = tid & 15;
    const int ty  = tid >> 4;

    const float* Qbase = Q + (size_t)(b * SEQ) * HID + h * HD;
    const float* Kbase = K + (size_t)(b * SEQ) * HID + h * HD;
    const float* Vbase = V + (size_t)(b * SEQ) * HID + h * HD;

    for (int idx = tid; idx < 64 * 64; idx += 256) {
        int r = idx >> 6, c = idx & 63;
        Qs[r * ASTR + c] = Qbase[(size_t)(l0 + r) * HID + c];
    }

    float m[4], lsum[4], O[4][4];
#pragma unroll
    for (int i = 0; i < 4; i++) {
        m[i] = -1e30f; lsum[i] = 0.f;
#pragma unroll
        for (int j = 0; j < 4; j++) O[i][j] = 0.f;
    }
    const int ebase = 4 * (ty - tx) + 60;   // E band row base for this thread

    for (int rt = 0; rt < 16; rt++) {
        const int r0 = rt * 64;
        __syncthreads();   // prev PV done before overwriting K/V/E
        for (int idx = tid; idx < 64 * 64; idx += 256) {
            int r = idx >> 6, c = idx & 63;
            Ks[r * ASTR + c] = Kbase[(size_t)(r0 + r) * HID + c];
            Vs[r * ASTR + c] = Vbase[(size_t)(r0 + r) * HID + c];
        }
        const int dbase = l0 - r0 + 960;   // dist row = dbase + (li - rj + 63), in [0,2046]
        for (int idx = tid; idx < 127 * 64; idx += 256) {
            int r = idx >> 6, c = idx & 63;
            Es[r * ASTR + c] = dist[(size_t)(dbase + r) * HD + c];
        }
        __syncthreads();

        float acc[4][4];
#pragma unroll
        for (int i = 0; i < 4; i++)
#pragma unroll
            for (int j = 0; j < 4; j++) acc[i][j] = 0.f;

        for (int d = 0; d < 64; d++) {
            float q[4], k[4], e[7];
#pragma unroll
            for (int i = 0; i < 4; i++) q[i] = Qs[(ty * 4 + i) * ASTR + d];
#pragma unroll
            for (int j = 0; j < 4; j++) k[j] = Ks[(tx * 4 + j) * ASTR + d];
#pragma unroll
            for (int t = 0; t < 7; t++) e[t] = Es[(ebase + t) * ASTR + d];
#pragma unroll
            for (int i = 0; i < 4; i++)
#pragma unroll
                for (int j = 0; j < 4; j++) {
                    float ee = e[i - j + 3];
                    acc[i][j] = fmaf(q[i], k[j] + ee, fmaf(k[j], ee, acc[i][j]));
                }
        }

        // scale + additive mask, online softmax over 16-lane row groups
#pragma unroll
        for (int i = 0; i < 4; i++) {
#pragma unroll
            for (int j = 0; j < 4; j++)
                acc[i][j] = acc[i][j] * 0.125f + mask[b * SEQ + r0 + tx * 4 + j];
            float tmax = fmaxf(fmaxf(acc[i][0], acc[i][1]), fmaxf(acc[i][2], acc[i][3]));
#pragma unroll
            for (int o = 8; o; o >>= 1)
                tmax = fmaxf(tmax, __shfl_xor_sync(0xffffffffu, tmax, o, 16));
            float newm = fmaxf(m[i], tmax);
            float corr = __expf(m[i] - newm);
            float ts = 0.f;
#pragma unroll
            for (int j = 0; j < 4; j++) {
                float p = __expf(acc[i][j] - newm);
                Ps[(ty * 4 + i) * ASTR + tx * 4 + j] = p;
                ts += p;
            }
#pragma unroll
            for (int o = 8; o; o >>= 1)
                ts += __shfl_xor_sync(0xffffffffu, ts, o, 16);
            lsum[i] = lsum[i] * corr + ts;
            m[i] = newm;
#pragma unroll
            for (int j = 0; j < 4; j++) O[i][j] *= corr;
        }
        __syncthreads();   // P visible before PV

        for (int r = 0; r < 64; r++) {
            float p[4], v[4];
#pragma unroll
            for (int i = 0; i < 4; i++) p[i] = Ps[(ty * 4 + i) * ASTR + r];
#pragma unroll
            for (int j = 0; j < 4; j++) v[j] = Vs[r * ASTR + tx * 4 + j];
#pragma unroll
            for (int i = 0; i < 4; i++)
#pragma unroll
                for (int j = 0; j < 4; j++) O[i][j] = fmaf(p[i], v[j], O[i][j]);
        }
    }

    const float hscale = hm[h];
#pragma unroll
    for (int i = 0; i < 4; i++) {
        float inv = hscale / lsum[i];
        size_t row = (size_t)(b * SEQ + l0 + ty * 4 + i) * HID + h * HD + tx * 4;
#pragma unroll
        for (int j = 0; j < 4; j++)
            ctx[row + j] = O[i][j] * inv;
    }
}

// ---------------- launch ----------------
extern "C" void kernel_launch(void* const* d_in, const int* in_sizes, int n_in,
                              void* d_out, int out_size)
{
    const float* hs   = (const float*)d_in[0];
    const float* mask = (const float*)d_in[1];
    const float* hm   = (const float*)d_in[2];
    const float* Wq   = (const float*)d_in[3];
    const float* bq   = (const float*)d_in[4];
    const float* Wk   = (const float*)d_in[5];
    const float* bk   = (const float*)d_in[6];
    const float* Wv   = (const float*)d_in[7];
    const float* bv   = (const float*)d_in[8];
    const float* dist = (const float*)d_in[9];
    const float* Wo   = (const float*)d_in[10];
    const float* bo   = (const float*)d_in[11];
    const float* ln1g = (const float*)d_in[12];
    const float* ln1b = (const float*)d_in[13];
    const float* Wi   = (const float*)d_in[14];
    const float* bi   = (const float*)d_in[15];
    const float* Wo2  = (const float*)d_in[16];
    const float* bo2  = (const float*)d_in[17];
    const float* ln2g = (const float*)d_in[18];
    const float* ln2b = (const float*)d_in[19];
    float* out = (float*)d_out;

    float *q, *k, *v, *ctx, *tmp, *attnout, *inter;
    cudaGetSymbolAddress((void**)&q,       g_q);
    cudaGetSymbolAddress((void**)&k,       g_k);
    cudaGetSymbolAddress((void**)&v,       g_v);
    cudaGetSymbolAddress((void**)&ctx,     g_ctx);
    cudaGetSymbolAddress((void**)&tmp,     g_tmp);
    cudaGetSymbolAddress((void**)&attnout, g_attnout);
    cudaGetSymbolAddress((void**)&inter,   g_inter);

    const size_t attn_smem = SMEM_FLOATS * sizeof(float);
    cudaFuncSetAttribute(attn_kernel, cudaFuncAttributeMaxDynamicSharedMemorySize,
                         (int)attn_smem);

    dim3 blk(256);
    dim3 g_1024(HID / 128, NTOK / 128);     // (8, 32)
    dim3 g_ff1(FFDIM / 128, NTOK / 128);    // (32, 32)

    // QKV projections
    sgemm_bias<0><<<g_1024, blk>>>(hs, Wq, bq, q, NTOK, HID, HID);
    sgemm_bias<0><<<g_1024, blk>>>(hs, Wk, bk, k, NTOK, HID, HID);
    sgemm_bias<0><<<g_1024, blk>>>(hs, Wv, bv, v, NTOK, HID, HID);

    // fused attention (QK^T + relative_key_query bias + softmax + PV)
    attn_kernel<<<dim3(SEQ / 64, BATCH * NHEAD), blk, attn_smem>>>(
        q, k, v, dist, mask, hm, ctx);

    // output projection + residual LN
    sgemm_bias<0><<<g_1024, blk>>>(ctx, Wo, bo, tmp, NTOK, HID, HID);
    ln_residual<<<NTOK, blk>>>(tmp, hs, ln1g, ln1b, attnout);

    // FFN: GELU(attnout @ Wi + bi) @ Wo2 + bo2, residual LN
    sgemm_bias<1><<<g_ff1, blk>>>(attnout, Wi, bi, inter, NTOK, FFDIM, HID);
    sgemm_bias<0><<<g_1024, blk>>>(inter, Wo2, bo2, tmp, NTOK, HID, FFDIM);
    ln_residual<<<NTOK, blk>>>(tmp, attnout, ln2g, ln2b, out);
}

// round 2
// speedup vs baseline: 1.7626x; 1.7626x over previous
#include <cuda_runtime.h>
#include <math.h>
#include <stdint.h>

#define HID    1024
#define FFDIM  4096
#define NHEAD  16
#define HD     64
#define BATCH  4
#define SEQ    1024
#define NTOK   (BATCH*SEQ)      // 4096
#define MAXPOS 1024

// ---------------- scratch (device globals: allocation-free) ----------------
__device__ float g_q[NTOK * HID];
__device__ float g_k[NTOK * HID];
__device__ float g_v[NTOK * HID];
__device__ float g_ctx[NTOK * HID];
__device__ float g_tmp[NTOK * HID];       // attn-dense out, then ff2 out
__device__ float g_attnout[NTOK * HID];   // LN1 output (FFN input + residual)
__device__ float g_inter[NTOK * FFDIM];   // GELU(ff1)

// ---------------- TF32 tensor-core GEMM --------------------------------------
// C[M,N] = A[M,K] @ B[K,N] + bias, optional exact GELU.
// 128x128 block tile, BK=32, 256 threads (8 warps, 2x4), warp tile 64x32.
// mma.sync.aligned.m16n8k8.row.col.f32.tf32.tf32.f32

__device__ __forceinline__ uint32_t f2tf(float f) {
    uint32_t u;
    asm("cvt.rna.tf32.f32 %0, %1;" : "=r"(u) : "f"(f));
    return u;
}

__device__ __forceinline__ void mma_tf32(float c[4], const uint32_t a[4],
                                         const uint32_t b[2]) {
    asm volatile(
        "mma.sync.aligned.m16n8k8.row.col.f32.tf32.tf32.f32 "
        "{%0,%1,%2,%3}, {%4,%5,%6,%7}, {%8,%9}, {%0,%1,%2,%3};"
        : "+f"(c[0]), "+f"(c[1]), "+f"(c[2]), "+f"(c[3])
        : "r"(a[0]), "r"(a[1]), "r"(a[2]), "r"(a[3]), "r"(b[0]), "r"(b[1]));
}

template <int GELU>
__global__ void __launch_bounds__(256) gemm_tc(
    const float* __restrict__ A, const float* __restrict__ Bm,
    const float* __restrict__ bias, float* __restrict__ C,
    int M, int N, int K)
{
    __shared__ uint32_t As[128][36];   // [m][k], pad 36 -> frag loads conflict-free
    __shared__ uint32_t Bs[32][136];   // [k][n], pad 136 -> frag loads conflict-free

    const int tid = threadIdx.x;
    const int w   = tid >> 5;
    const int l   = tid & 31;
    const int wr  = w >> 2;            // 0..1
    const int wc  = w & 3;             // 0..3
    const int m0  = blockIdx.y * 128;
    const int n0  = blockIdx.x * 128;

    const int g   = l >> 2;            // 0..7
    const int t4  = l & 3;             // 0..3

    // staging coords
    const int ar = tid >> 3;           // 0..31   (A rows ar + 32*i)
    const int ac = (tid & 7) << 2;     // 0..28   (A col group, float4)
    const int br = tid >> 5;           // 0..7    (B rows br + 8*i)
    const int bc = (tid & 31) << 2;    // 0..124  (B col group, float4)

    float c[4][4][4];
#pragma unroll
    for (int mi = 0; mi < 4; mi++)
#pragma unroll
        for (int ni = 0; ni < 4; ni++)
#pragma unroll
            for (int r = 0; r < 4; r++) c[mi][ni][r] = 0.f;

    for (int k0 = 0; k0 < K; k0 += 32) {
        __syncthreads();
#pragma unroll
        for (int i = 0; i < 4; i++) {
            float4 v = *(const float4*)&A[(size_t)(m0 + ar + 32 * i) * K + k0 + ac];
            uint4 u = make_uint4(f2tf(v.x), f2tf(v.y), f2tf(v.z), f2tf(v.w));
            *(uint4*)&As[ar + 32 * i][ac] = u;
        }
#pragma unroll
        for (int i = 0; i < 4; i++) {
            float4 v = *(const float4*)&Bm[(size_t)(k0 + br + 8 * i) * N + n0 + bc];
            uint4 u = make_uint4(f2tf(v.x), f2tf(v.y), f2tf(v.z), f2tf(v.w));
            *(uint4*)&Bs[br + 8 * i][bc] = u;
        }
        __syncthreads();

#pragma unroll
        for (int kk = 0; kk < 4; kk++) {
            const int kb = kk * 8;
            uint32_t a[4][4], b[4][2];
#pragma unroll
            for (int mi = 0; mi < 4; mi++) {
                const int mrow = wr * 64 + mi * 16 + g;
                a[mi][0] = As[mrow][kb + t4];
                a[mi][1] = As[mrow + 8][kb + t4];
                a[mi][2] = As[mrow][kb + t4 + 4];
                a[mi][3] = As[mrow + 8][kb + t4 + 4];
            }
#pragma unroll
            for (int ni = 0; ni < 4; ni++) {
                const int ncol = wc * 32 + ni * 8 + g;
                b[ni][0] = Bs[kb + t4][ncol];
                b[ni][1] = Bs[kb + t4 + 4][ncol];
            }
#pragma unroll
            for (int mi = 0; mi < 4; mi++)
#pragma unroll
                for (int ni = 0; ni < 4; ni++)
                    mma_tf32(c[mi][ni], a[mi], b[ni]);
        }
    }

    // epilogue
#pragma unroll
    for (int mi = 0; mi < 4; mi++) {
#pragma unroll
        for (int ni = 0; ni < 4; ni++) {
            const int row = m0 + wr * 64 + mi * 16 + g;
            const int col = n0 + wc * 32 + ni * 8 + t4 * 2;
            const float b0 = bias[col], b1 = bias[col + 1];
            float v0 = c[mi][ni][0] + b0;
            float v1 = c[mi][ni][1] + b1;
            float v2 = c[mi][ni][2] + b0;
            float v3 = c[mi][ni][3] + b1;
            if (GELU) {
                v0 = 0.5f * v0 * (1.0f + erff(v0 * 0.70710678118654752f));
                v1 = 0.5f * v1 * (1.0f + erff(v1 * 0.70710678118654752f));
                v2 = 0.5f * v2 * (1.0f + erff(v2 * 0.70710678118654752f));
                v3 = 0.5f * v3 * (1.0f + erff(v3 * 0.70710678118654752f));
            }
            *(float2*)&C[(size_t)row * N + col]       = make_float2(v0, v1);
            *(float2*)&C[(size_t)(row + 8) * N + col] = make_float2(v2, v3);
        }
    }
}

// ---------------- LayerNorm(x + res) * g + b ----------------
__global__ void __launch_bounds__(256) ln_residual(
    const float* __restrict__ x, const float* __restrict__ res,
    const float* __restrict__ g, const float* __restrict__ b,
    float* __restrict__ out)
{
    __shared__ float buf[HID];
    __shared__ float red[8];
    const int row = blockIdx.x;
    const int tid = threadIdx.x;
    const size_t base = (size_t)row * HID;

    float s = 0.f;
    for (int c = tid; c < HID; c += 256) {
        float v = x[base + c] + res[base + c];
        buf[c] = v;
        s += v;
    }
#pragma unroll
    for (int o = 16; o; o >>= 1) s += __shfl_xor_sync(0xffffffffu, s, o);
    if ((tid & 31) == 0) red[tid >> 5] = s;
    __syncthreads();
    if (tid < 8) {
        s = red[tid];
#pragma unroll
        for (int o = 4; o; o >>= 1) s += __shfl_xor_sync(0xffu, s, o, 8);
        if (tid == 0) red[0] = s;
    }
    __syncthreads();
    float mean = red[0] * (1.0f / HID);
    __syncthreads();

    float vs = 0.f;
    for (int c = tid; c < HID; c += 256) {
        float d = buf[c] - mean;
        vs += d * d;
    }
#pragma unroll
    for (int o = 16; o; o >>= 1) vs += __shfl_xor_sync(0xffffffffu, vs, o);
    if ((tid & 31) == 0) red[tid >> 5] = vs;
    __syncthreads();
    if (tid < 8) {
        vs = red[tid];
#pragma unroll
        for (int o = 4; o; o >>= 1) vs += __shfl_xor_sync(0xffu, vs, o, 8);
        if (tid == 0) red[0] = vs;
    }
    __syncthreads();
    float inv = rsqrtf(red[0] * (1.0f / HID) + 1e-12f);
    __syncthreads();

    for (int c = tid; c < HID; c += 256)
        out[base + c] = (buf[c] - mean) * inv * g[c] + b[c];
}

// ---------------- fused attention with Toeplitz relative-position bias -------
#define ASTR 65
#define SMEM_FLOATS (4 * 64 * ASTR + 127 * ASTR)

__global__ void __launch_bounds__(256) attn_kernel(
    const float* __restrict__ Q, const float* __restrict__ K,
    const float* __restrict__ V, const float* __restrict__ dist,
    const float* __restrict__ mask, const float* __restrict__ hm,
    float* __restrict__ ctx)
{
    extern __shared__ float sm[];
    float* Qs = sm;                    // 64 x 65
    float* Ks = Qs + 64 * ASTR;        // 64 x 65
    float* Vs = Ks + 64 * ASTR;        // 64 x 65
    float* Ps = Vs + 64 * ASTR;        // 64 x 65
    float* Es = Ps + 64 * ASTR;        // 127 x 65

    const int lt = blockIdx.x;          // 0..15
    const int bh = blockIdx.y;          // 0..63
    const int b  = bh >> 4;
    const int h  = bh & 15;
    const int l0 = lt * 64;
    const int tid = threadIdx.x;
    const int tx  = tid & 15;
    const int ty  = tid >> 4;

    const float* Qbase = Q + (size_t)(b * SEQ) * HID + h * HD;
    const float* Kbase = K + (size_t)(b * SEQ) * HID + h * HD;
    const float* Vbase = V + (size_t)(b * SEQ) * HID + h * HD;

    for (int idx = tid; idx < 64 * 64; idx += 256) {
        int r = idx >> 6, c = idx & 63;
        Qs[r * ASTR + c] = Qbase[(size_t)(l0 + r) * HID + c];
    }

    float m[4], lsum[4], O[4][4];
#pragma unroll
    for (int i = 0; i < 4; i++) {
        m[i] = -1e30f; lsum[i] = 0.f;
#pragma unroll
        for (int j = 0; j < 4; j++) O[i][j] = 0.f;
    }
    const int ebase = 4 * (ty - tx) + 60;

    for (int rt = 0; rt < 16; rt++) {
        const int r0 = rt * 64;
        __syncthreads();
        for (int idx = tid; idx < 64 * 64; idx += 256) {
            int r = idx >> 6, c = idx & 63;
            Ks[r * ASTR + c] = Kbase[(size_t)(r0 + r) * HID + c];
            Vs[r * ASTR + c] = Vbase[(size_t)(r0 + r) * HID + c];
        }
        const int dbase = l0 - r0 + 960;
        for (int idx = tid; idx < 127 * 64; idx += 256) {
            int r = idx >> 6, c = idx & 63;
            Es[r * ASTR + c] = dist[(size_t)(dbase + r) * HD + c];
        }
        __syncthreads();

        float acc[4][4];
#pragma unroll
        for (int i = 0; i < 4; i++)
#pragma unroll
            for (int j = 0; j < 4; j++) acc[i][j] = 0.f;

        for (int d = 0; d < 64; d++) {
            float q[4], k[4], e[7];
#pragma unroll
            for (int i = 0; i < 4; i++) q[i] = Qs[(ty * 4 + i) * ASTR + d];
#pragma unroll
            for (int j = 0; j < 4; j++) k[j] = Ks[(tx * 4 + j) * ASTR + d];
#pragma unroll
            for (int t = 0; t < 7; t++) e[t] = Es[(ebase + t) * ASTR + d];
#pragma unroll
            for (int i = 0; i < 4; i++)
#pragma unroll
                for (int j = 0; j < 4; j++) {
                    float ee = e[i - j + 3];
                    acc[i][j] = fmaf(q[i], k[j] + ee, fmaf(k[j], ee, acc[i][j]));
                }
        }

#pragma unroll
        for (int i = 0; i < 4; i++) {
#pragma unroll
            for (int j = 0; j < 4; j++)
                acc[i][j] = acc[i][j] * 0.125f + mask[b * SEQ + r0 + tx * 4 + j];
            float tmax = fmaxf(fmaxf(acc[i][0], acc[i][1]), fmaxf(acc[i][2], acc[i][3]));
#pragma unroll
            for (int o = 8; o; o >>= 1)
                tmax = fmaxf(tmax, __shfl_xor_sync(0xffffffffu, tmax, o, 16));
            float newm = fmaxf(m[i], tmax);
            float corr = __expf(m[i] - newm);
            float ts = 0.f;
#pragma unroll
            for (int j = 0; j < 4; j++) {
                float p = __expf(acc[i][j] - newm);
                Ps[(ty * 4 + i) * ASTR + tx * 4 + j] = p;
                ts += p;
            }
#pragma unroll
            for (int o = 8; o; o >>= 1)
                ts += __shfl_xor_sync(0xffffffffu, ts, o, 16);
            lsum[i] = lsum[i] * corr + ts;
            m[i] = newm;
#pragma unroll
            for (int j = 0; j < 4; j++) O[i][j] *= corr;
        }
        __syncthreads();

        for (int r = 0; r < 64; r++) {
            float p[4], v[4];
#pragma unroll
            for (int i = 0; i < 4; i++) p[i] = Ps[(ty * 4 + i) * ASTR + r];
#pragma unroll
            for (int j = 0; j < 4; j++) v[j] = Vs[r * ASTR + tx * 4 + j];
#pragma unroll
            for (int i = 0; i < 4; i++)
#pragma unroll
                for (int j = 0; j < 4; j++) O[i][j] = fmaf(p[i], v[j], O[i][j]);
        }
    }

    const float hscale = hm[h];
#pragma unroll
    for (int i = 0; i < 4; i++) {
        float inv = hscale / lsum[i];
        size_t row = (size_t)(b * SEQ + l0 + ty * 4 + i) * HID + h * HD + tx * 4;
#pragma unroll
        for (int j = 0; j < 4; j++)
            ctx[row + j] = O[i][j] * inv;
    }
}

// ---------------- launch ----------------
extern "C" void kernel_launch(void* const* d_in, const int* in_sizes, int n_in,
                              void* d_out, int out_size)
{
    const float* hs   = (const float*)d_in[0];
    const float* mask = (const float*)d_in[1];
    const float* hm   = (const float*)d_in[2];
    const float* Wq   = (const float*)d_in[3];
    const float* bq   = (const float*)d_in[4];
    const float* Wk   = (const float*)d_in[5];
    const float* bk   = (const float*)d_in[6];
    const float* Wv   = (const float*)d_in[7];
    const float* bv   = (const float*)d_in[8];
    const float* dist = (const float*)d_in[9];
    const float* Wo   = (const float*)d_in[10];
    const float* bo   = (const float*)d_in[11];
    const float* ln1g = (const float*)d_in[12];
    const float* ln1b = (const float*)d_in[13];
    const float* Wi   = (const float*)d_in[14];
    const float* bi   = (const float*)d_in[15];
    const float* Wo2  = (const float*)d_in[16];
    const float* bo2  = (const float*)d_in[17];
    const float* ln2g = (const float*)d_in[18];
    const float* ln2b = (const float*)d_in[19];
    float* out = (float*)d_out;

    float *q, *k, *v, *ctx, *tmp, *attnout, *inter;
    cudaGetSymbolAddress((void**)&q,       g_q);
    cudaGetSymbolAddress((void**)&k,       g_k);
    cudaGetSymbolAddress((void**)&v,       g_v);
    cudaGetSymbolAddress((void**)&ctx,     g_ctx);
    cudaGetSymbolAddress((void**)&tmp,     g_tmp);
    cudaGetSymbolAddress((void**)&attnout, g_attnout);
    cudaGetSymbolAddress((void**)&inter,   g_inter);

    const size_t attn_smem = SMEM_FLOATS * sizeof(float);
    cudaFuncSetAttribute(attn_kernel, cudaFuncAttributeMaxDynamicSharedMemorySize,
                         (int)attn_smem);

    dim3 blk(256);
    dim3 g_1024(HID / 128, NTOK / 128);     // (8, 32)
    dim3 g_ff1(FFDIM / 128, NTOK / 128);    // (32, 32)

    // QKV projections (tensor cores, tf32)
    gemm_tc<0><<<g_1024, blk>>>(hs, Wq, bq, q, NTOK, HID, HID);
    gemm_tc<0><<<g_1024, blk>>>(hs, Wk, bk, k, NTOK, HID, HID);
    gemm_tc<0><<<g_1024, blk>>>(hs, Wv, bv, v, NTOK, HID, HID);

    // fused attention (QK^T + relative_key_query bias + softmax + PV)
    attn_kernel<<<dim3(SEQ / 64, BATCH * NHEAD), blk, attn_smem>>>(
        q, k, v, dist, mask, hm, ctx);

    // output projection + residual LN
    gemm_tc<0><<<g_1024, blk>>>(ctx, Wo, bo, tmp, NTOK, HID, HID);
    ln_residual<<<NTOK, blk>>>(tmp, hs, ln1g, ln1b, attnout);

    // FFN: GELU(attnout @ Wi + bi) @ Wo2 + bo2, residual LN
    gemm_tc<1><<<g_ff1, blk>>>(attnout, Wi, bi, inter, NTOK, FFDIM, HID);
    gemm_tc<0><<<g_1024, blk>>>(inter, Wo2, bo2, tmp, NTOK, HID, FFDIM);
    ln_residual<<<NTOK, blk>>>(tmp, attnout, ln2g, ln2b, out);
}

// round 3
// speedup vs baseline: 2.4806x; 1.4073x over previous
#include <cuda_runtime.h>
#include <math.h>
#include <stdint.h>

#define HID    1024
#define FFDIM  4096
#define NHEAD  16
#define HD     64
#define BATCH  4
#define SEQ    1024
#define NTOK   (BATCH*SEQ)      // 4096
#define MAXPOS 1024

// ---------------- scratch (device globals: allocation-free) ----------------
__device__ float g_q[NTOK * HID];
__device__ float g_k[NTOK * HID];
__device__ float g_v[NTOK * HID];
__device__ float g_ctx[NTOK * HID];
__device__ float g_tmp[NTOK * HID];
__device__ float g_attnout[NTOK * HID];
__device__ float g_inter[NTOK * FFDIM];

// ---------------- tf32 helpers ----------------
__device__ __forceinline__ uint32_t f2tf(float f) {
    uint32_t u;
    asm("cvt.rna.tf32.f32 %0, %1;" : "=r"(u) : "f"(f));
    return u;
}

__device__ __forceinline__ void mma_tf32(float c[4], const uint32_t a[4],
                                         const uint32_t b[2]) {
    asm volatile(
        "mma.sync.aligned.m16n8k8.row.col.f32.tf32.tf32.f32 "
        "{%0,%1,%2,%3}, {%4,%5,%6,%7}, {%8,%9}, {%0,%1,%2,%3};"
        : "+f"(c[0]), "+f"(c[1]), "+f"(c[2]), "+f"(c[3])
        : "r"(a[0]), "r"(a[1]), "r"(a[2]), "r"(a[3]), "r"(b[0]), "r"(b[1]));
}

// ---------------- TF32 tensor-core GEMM (unchanged from R2) -------------------
template <int GELU>
__global__ void __launch_bounds__(256) gemm_tc(
    const float* __restrict__ A, const float* __restrict__ Bm,
    const float* __restrict__ bias, float* __restrict__ C,
    int M, int N, int K)
{
    __shared__ uint32_t As[128][36];
    __shared__ uint32_t Bs[32][136];

    const int tid = threadIdx.x;
    const int w   = tid >> 5;
    const int l   = tid & 31;
    const int wr  = w >> 2;
    const int wc  = w & 3;
    const int m0  = blockIdx.y * 128;
    const int n0  = blockIdx.x * 128;

    const int g   = l >> 2;
    const int t4  = l & 3;

    const int ar = tid >> 3;
    const int ac = (tid & 7) << 2;
    const int br = tid >> 5;
    const int bc = (tid & 31) << 2;

    float c[4][4][4];
#pragma unroll
    for (int mi = 0; mi < 4; mi++)
#pragma unroll
        for (int ni = 0; ni < 4; ni++)
#pragma unroll
            for (int r = 0; r < 4; r++) c[mi][ni][r] = 0.f;

    for (int k0 = 0; k0 < K; k0 += 32) {
        __syncthreads();
#pragma unroll
        for (int i = 0; i < 4; i++) {
            float4 v = *(const float4*)&A[(size_t)(m0 + ar + 32 * i) * K + k0 + ac];
            uint4 u = make_uint4(f2tf(v.x), f2tf(v.y), f2tf(v.z), f2tf(v.w));
            *(uint4*)&As[ar + 32 * i][ac] = u;
        }
#pragma unroll
        for (int i = 0; i < 4; i++) {
            float4 v = *(const float4*)&Bm[(size_t)(k0 + br + 8 * i) * N + n0 + bc];
            uint4 u = make_uint4(f2tf(v.x), f2tf(v.y), f2tf(v.z), f2tf(v.w));
            *(uint4*)&Bs[br + 8 * i][bc] = u;
        }
        __syncthreads();

#pragma unroll
        for (int kk = 0; kk < 4; kk++) {
            const int kb = kk * 8;
            uint32_t a[4][4], b[4][2];
#pragma unroll
            for (int mi = 0; mi < 4; mi++) {
                const int mrow = wr * 64 + mi * 16 + g;
                a[mi][0] = As[mrow][kb + t4];
                a[mi][1] = As[mrow + 8][kb + t4];
                a[mi][2] = As[mrow][kb + t4 + 4];
                a[mi][3] = As[mrow + 8][kb + t4 + 4];
            }
#pragma unroll
            for (int ni = 0; ni < 4; ni++) {
                const int ncol = wc * 32 + ni * 8 + g;
                b[ni][0] = Bs[kb + t4][ncol];
                b[ni][1] = Bs[kb + t4 + 4][ncol];
            }
#pragma unroll
            for (int mi = 0; mi < 4; mi++)
#pragma unroll
                for (int ni = 0; ni < 4; ni++)
                    mma_tf32(c[mi][ni], a[mi], b[ni]);
        }
    }

#pragma unroll
    for (int mi = 0; mi < 4; mi++) {
#pragma unroll
        for (int ni = 0; ni < 4; ni++) {
            const int row = m0 + wr * 64 + mi * 16 + g;
            const int col = n0 + wc * 32 + ni * 8 + t4 * 2;
            const float b0 = bias[col], b1 = bias[col + 1];
            float v0 = c[mi][ni][0] + b0;
            float v1 = c[mi][ni][1] + b1;
            float v2 = c[mi][ni][2] + b0;
            float v3 = c[mi][ni][3] + b1;
            if (GELU) {
                v0 = 0.5f * v0 * (1.0f + erff(v0 * 0.70710678118654752f));
                v1 = 0.5f * v1 * (1.0f + erff(v1 * 0.70710678118654752f));
                v2 = 0.5f * v2 * (1.0f + erff(v2 * 0.70710678118654752f));
                v3 = 0.5f * v3 * (1.0f + erff(v3 * 0.70710678118654752f));
            }
            *(float2*)&C[(size_t)row * N + col]       = make_float2(v0, v1);
            *(float2*)&C[(size_t)(row + 8) * N + col] = make_float2(v2, v3);
        }
    }
}

// ---------------- LayerNorm(x + res) * g + b (unchanged) ----------------
__global__ void __launch_bounds__(256) ln_residual(
    const float* __restrict__ x, const float* __restrict__ res,
    const float* __restrict__ g, const float* __restrict__ b,
    float* __restrict__ out)
{
    __shared__ float buf[HID];
    __shared__ float red[8];
    const int row = blockIdx.x;
    const int tid = threadIdx.x;
    const size_t base = (size_t)row * HID;

    float s = 0.f;
    for (int c = tid; c < HID; c += 256) {
        float v = x[base + c] + res[base + c];
        buf[c] = v;
        s += v;
    }
#pragma unroll
    for (int o = 16; o; o >>= 1) s += __shfl_xor_sync(0xffffffffu, s, o);
    if ((tid & 31) == 0) red[tid >> 5] = s;
    __syncthreads();
    if (tid < 8) {
        s = red[tid];
#pragma unroll
        for (int o = 4; o; o >>= 1) s += __shfl_xor_sync(0xffu, s, o, 8);
        if (tid == 0) red[0] = s;
    }
    __syncthreads();
    float mean = red[0] * (1.0f / HID);
    __syncthreads();

    float vs = 0.f;
    for (int c = tid; c < HID; c += 256) {
        float d = buf[c] - mean;
        vs += d * d;
    }
#pragma unroll
    for (int o = 16; o; o >>= 1) vs += __shfl_xor_sync(0xffffffffu, vs, o);
    if ((tid & 31) == 0) red[tid >> 5] = vs;
    __syncthreads();
    if (tid < 8) {
        vs = red[tid];
#pragma unroll
        for (int o = 4; o; o >>= 1) vs += __shfl_xor_sync(0xffu, vs, o, 8);
        if (tid == 0) red[0] = vs;
    }
    __syncthreads();
    float inv = rsqrtf(red[0] * (1.0f / HID) + 1e-12f);
    __syncthreads();

    for (int c = tid; c < HID; c += 256)
        out[base + c] = (buf[c] - mean) * inv * g[c] + b[c];
}

// ---------------- tensor-core attention with Toeplitz bias -------------------
// Block = 128 threads (4 warps), one (b,h) and one 64-row l-tile.
// Per r-tile: B2=K@Ebandᵀ, B1=Q@Ebandᵀ (64x128 each), S=Q@Kᵀ, bias gather,
// online softmax on fragments, PV=P@V. All matmuls tf32 mma.sync.
#define AST 68          // stride for Qs/Ks/Es/Ps (4 mod 32 -> cf-free frag reads)
#define VST 72          // stride for Vs (8 mod 32 -> cf-free B-operand reads)
#define BST 132
#define ATTN_SMEM_FLOATS (64*AST /*Q*/ + 64*AST /*K*/ + 128*AST /*E|V*/ \
                          + 64*BST /*B1*/ + 64*BST /*B2*/ + 64*AST /*P*/)

__global__ void __launch_bounds__(128) attn_tc(
    const float* __restrict__ Q, const float* __restrict__ K,
    const float* __restrict__ V, const float* __restrict__ dist,
    const float* __restrict__ mask, const float* __restrict__ hm,
    float* __restrict__ ctx)
{
    extern __shared__ float smf[];
    float* Qs  = smf;                    // [64][AST]
    float* Ks  = Qs + 64 * AST;          // [64][AST]
    float* EVs = Ks + 64 * AST;          // E: [128][AST]  /  V: [64][VST]
    float* B1s = EVs + 128 * AST;        // [64][BST] fp32
    float* B2s = B1s + 64 * BST;         // [64][BST] fp32
    float* Ps  = B2s + 64 * BST;         // [64][AST] tf32

    const int tid = threadIdx.x;
    const int w   = tid >> 5;
    const int l   = tid & 31;
    const int g   = l >> 2;
    const int t4  = l & 3;
    const int bh  = blockIdx.y;
    const int b   = bh >> 4;
    const int h   = bh & 15;
    const int l0  = blockIdx.x * 64;

    const int li0 = 16 * w + g;          // local rows this thread owns
    const int li1 = li0 + 8;

    const float* Qg = Q + (size_t)(b * SEQ) * HID + h * HD;
    const float* Kg = K + (size_t)(b * SEQ) * HID + h * HD;
    const float* Vg = V + (size_t)(b * SEQ) * HID + h * HD;
    const float* mg = mask + b * SEQ;

    // load Q tile (64 x 64), tf32
    for (int idx = tid; idx < 64 * 16; idx += 128) {
        int r = idx >> 4, c4 = (idx & 15) << 2;
        float4 v = *(const float4*)&Qg[(size_t)(l0 + r) * HID + c4];
        uint4* d = (uint4*)&Qs[r * AST + c4];
        *d = make_uint4(f2tf(v.x), f2tf(v.y), f2tf(v.z), f2tf(v.w));
    }

    float O[8][4];
#pragma unroll
    for (int ni = 0; ni < 8; ni++)
#pragma unroll
        for (int r = 0; r < 4; r++) O[ni][r] = 0.f;
    float mrow[2] = {-1e30f, -1e30f};
    float lrow[2] = {0.f, 0.f};

    for (int rt = 0; rt < 16; rt++) {
        const int r0 = rt * 64;
        __syncthreads();   // prev PV done before K/E overwrite

        for (int idx = tid; idx < 64 * 16; idx += 128) {
            int r = idx >> 4, c4 = (idx & 15) << 2;
            float4 v = *(const float4*)&Kg[(size_t)(r0 + r) * HID + c4];
            *(uint4*)&Ks[r * AST + c4] =
                make_uint4(f2tf(v.x), f2tf(v.y), f2tf(v.z), f2tf(v.w));
        }
        const int dbase = l0 - r0 + 960;
        for (int idx = tid; idx < 127 * 16; idx += 128) {
            int r = idx >> 4, c4 = (idx & 15) << 2;
            float4 v = *(const float4*)&dist[(size_t)(dbase + r) * HD + c4];
            *(uint4*)&EVs[r * AST + c4] =
                make_uint4(f2tf(v.x), f2tf(v.y), f2tf(v.z), f2tf(v.w));
        }
        __syncthreads();

        // ---- phase A: B2 = K@E^T, then B1 = Q@E^T (a-frags of Q reused for S)
        uint32_t a[8][4];
#pragma unroll
        for (int mat = 0; mat < 2; mat++) {
            const float* Asrc = mat ? Qs : Ks;
            float* Dst = mat ? B1s : B2s;
#pragma unroll
            for (int kk = 0; kk < 8; kk++) {
                const int kb = kk * 8;
                a[kk][0] = __float_as_uint(Asrc[li0 * AST + kb + t4]);
                a[kk][1] = __float_as_uint(Asrc[li1 * AST + kb + t4]);
                a[kk][2] = __float_as_uint(Asrc[li0 * AST + kb + t4 + 4]);
                a[kk][3] = __float_as_uint(Asrc[li1 * AST + kb + t4 + 4]);
            }
#pragma unroll
            for (int half = 0; half < 2; half++) {
                float c[8][4];
#pragma unroll
                for (int ni = 0; ni < 8; ni++)
#pragma unroll
                    for (int r = 0; r < 4; r++) c[ni][r] = 0.f;
#pragma unroll
                for (int kk = 0; kk < 8; kk++) {
                    const int kb = kk * 8;
#pragma unroll
                    for (int ni = 0; ni < 8; ni++) {
                        const int ncol = half * 64 + ni * 8 + g;
                        uint32_t bf[2];
                        bf[0] = __float_as_uint(EVs[ncol * AST + kb + t4]);
                        bf[1] = __float_as_uint(EVs[ncol * AST + kb + t4 + 4]);
                        mma_tf32(c[ni], a[kk], bf);
                    }
                }
#pragma unroll
                for (int ni = 0; ni < 8; ni++) {
                    const int col = half * 64 + ni * 8 + 2 * t4;
                    *(float2*)&Dst[li0 * BST + col] = make_float2(c[ni][0], c[ni][1]);
                    *(float2*)&Dst[li1 * BST + col] = make_float2(c[ni][2], c[ni][3]);
                }
            }
        }

        // ---- S = Q@K^T (a still holds Q frags)
        float cS[8][4];
#pragma unroll
        for (int ni = 0; ni < 8; ni++)
#pragma unroll
            for (int r = 0; r < 4; r++) cS[ni][r] = 0.f;
#pragma unroll
        for (int kk = 0; kk < 8; kk++) {
            const int kb = kk * 8;
#pragma unroll
            for (int ni = 0; ni < 8; ni++) {
                const int ncol = ni * 8 + g;
                uint32_t bf[2];
                bf[0] = __float_as_uint(Ks[ncol * AST + kb + t4]);
                bf[1] = __float_as_uint(Ks[ncol * AST + kb + t4 + 4]);
                mma_tf32(cS[ni], a[kk], bf);
            }
        }
        __syncthreads();   // B1s/B2s visible; E reads done -> can overwrite with V

        // ---- V load (into E buffer, stride VST)
        for (int idx = tid; idx < 64 * 16; idx += 128) {
            int r = idx >> 4, c4 = (idx & 15) << 2;
            float4 v = *(const float4*)&Vg[(size_t)(r0 + r) * HID + c4];
            *(uint4*)&EVs[r * VST + c4] =
                make_uint4(f2tf(v.x), f2tf(v.y), f2tf(v.z), f2tf(v.w));
        }

        // ---- bias gather + scale + mask
        float vmax0 = -1e30f, vmax1 = -1e30f;
#pragma unroll
        for (int ni = 0; ni < 8; ni++) {
#pragma unroll
            for (int e = 0; e < 2; e++) {
                const int rj = ni * 8 + 2 * t4 + e;
                const float mv = mg[r0 + rj];
                const int ib0 = li0 - rj + 63;
                const int ib1 = li1 - rj + 63;
                float v0 = (cS[ni][e]     + B1s[li0 * BST + ib0] + B2s[rj * BST + ib0]) * 0.125f + mv;
                float v1 = (cS[ni][2 + e] + B1s[li1 * BST + ib1] + B2s[rj * BST + ib1]) * 0.125f + mv;
                cS[ni][e]     = v0;
                cS[ni][2 + e] = v1;
                vmax0 = fmaxf(vmax0, v0);
                vmax1 = fmaxf(vmax1, v1);
            }
        }
        vmax0 = fmaxf(vmax0, __shfl_xor_sync(0xffffffffu, vmax0, 1));
        vmax0 = fmaxf(vmax0, __shfl_xor_sync(0xffffffffu, vmax0, 2));
        vmax1 = fmaxf(vmax1, __shfl_xor_sync(0xffffffffu, vmax1, 1));
        vmax1 = fmaxf(vmax1, __shfl_xor_sync(0xffffffffu, vmax1, 2));

        const float nm0 = fmaxf(mrow[0], vmax0);
        const float nm1 = fmaxf(mrow[1], vmax1);
        const float corr0 = __expf(mrow[0] - nm0);
        const float corr1 = __expf(mrow[1] - nm1);

        float ts0 = 0.f, ts1 = 0.f;
#pragma unroll
        for (int ni = 0; ni < 8; ni++) {
#pragma unroll
            for (int e = 0; e < 2; e++) {
                const int cj = ni * 8 + 2 * t4 + e;
                float p0 = __expf(cS[ni][e]     - nm0);
                float p1 = __expf(cS[ni][2 + e] - nm1);
                Ps[li0 * AST + cj] = __uint_as_float(f2tf(p0));
                Ps[li1 * AST + cj] = __uint_as_float(f2tf(p1));
                ts0 += p0;
                ts1 += p1;
            }
        }
        ts0 += __shfl_xor_sync(0xffffffffu, ts0, 1);
        ts0 += __shfl_xor_sync(0xffffffffu, ts0, 2);
        ts1 += __shfl_xor_sync(0xffffffffu, ts1, 1);
        ts1 += __shfl_xor_sync(0xffffffffu, ts1, 2);

        lrow[0] = lrow[0] * corr0 + ts0;
        lrow[1] = lrow[1] * corr1 + ts1;
        mrow[0] = nm0;
        mrow[1] = nm1;
#pragma unroll
        for (int ni = 0; ni < 8; ni++) {
            O[ni][0] *= corr0;
            O[ni][1] *= corr0;
            O[ni][2] *= corr1;
            O[ni][3] *= corr1;
        }
        __syncthreads();   // P, V visible

        // ---- PV: O += P@V
#pragma unroll
        for (int kk = 0; kk < 8; kk++) {
            const int kb = kk * 8;
            uint32_t ap[4];
            ap[0] = __float_as_uint(Ps[li0 * AST + kb + t4]);
            ap[1] = __float_as_uint(Ps[li1 * AST + kb + t4]);
            ap[2] = __float_as_uint(Ps[li0 * AST + kb + t4 + 4]);
            ap[3] = __float_as_uint(Ps[li1 * AST + kb + t4 + 4]);
#pragma unroll
            for (int ni = 0; ni < 8; ni++) {
                const int ncol = ni * 8 + g;
                uint32_t bf[2];
                bf[0] = __float_as_uint(EVs[(kb + t4) * VST + ncol]);
                bf[1] = __float_as_uint(EVs[(kb + t4 + 4) * VST + ncol]);
                mma_tf32(O[ni], ap, bf);
            }
        }
    }

    // ---- epilogue
    const float hscale = hm[h];
    const float inv0 = hscale / lrow[0];
    const float inv1 = hscale / lrow[1];
#pragma unroll
    for (int ni = 0; ni < 8; ni++) {
        const int col = h * HD + ni * 8 + 2 * t4;
        const size_t row0g = (size_t)(b * SEQ + l0 + li0) * HID + col;
        const size_t row1g = (size_t)(b * SEQ + l0 + li1) * HID + col;
        *(float2*)&ctx[row0g] = make_float2(O[ni][0] * inv0, O[ni][1] * inv0);
        *(float2*)&ctx[row1g] = make_float2(O[ni][2] * inv1, O[ni][3] * inv1);
    }
}

// ---------------- launch ----------------
extern "C" void kernel_launch(void* const* d_in, const int* in_sizes, int n_in,
                              void* d_out, int out_size)
{
    const float* hs   = (const float*)d_in[0];
    const float* mask = (const float*)d_in[1];
    const float* hm   = (const float*)d_in[2];
    const float* Wq   = (const float*)d_in[3];
    const float* bq   = (const float*)d_in[4];
    const float* Wk   = (const float*)d_in[5];
    const float* bk   = (const float*)d_in[6];
    const float* Wv   = (const float*)d_in[7];
    const float* bv   = (const float*)d_in[8];
    const float* dist = (const float*)d_in[9];
    const float* Wo   = (const float*)d_in[10];
    const float* bo   = (const float*)d_in[11];
    const float* ln1g = (const float*)d_in[12];
    const float* ln1b = (const float*)d_in[13];
    const float* Wi   = (const float*)d_in[14];
    const float* bi   = (const float*)d_in[15];
    const float* Wo2  = (const float*)d_in[16];
    const float* bo2  = (const float*)d_in[17];
    const float* ln2g = (const float*)d_in[18];
    const float* ln2b = (const float*)d_in[19];
    float* out = (float*)d_out;

    float *q, *k, *v, *ctx, *tmp, *attnout, *inter;
    cudaGetSymbolAddress((void**)&q,       g_q);
    cudaGetSymbolAddress((void**)&k,       g_k);
    cudaGetSymbolAddress((void**)&v,       g_v);
    cudaGetSymbolAddress((void**)&ctx,     g_ctx);
    cudaGetSymbolAddress((void**)&tmp,     g_tmp);
    cudaGetSymbolAddress((void**)&attnout, g_attnout);
    cudaGetSymbolAddress((void**)&inter,   g_inter);

    const size_t attn_smem = ATTN_SMEM_FLOATS * sizeof(float);
    static int attr_set = 0;
    cudaFuncSetAttribute(attn_tc, cudaFuncAttributeMaxDynamicSharedMemorySize,
                         (int)attn_smem);
    (void)attr_set;

    dim3 blk(256);
    dim3 g_1024(HID / 128, NTOK / 128);
    dim3 g_ff1(FFDIM / 128, NTOK / 128);

    gemm_tc<0><<<g_1024, blk>>>(hs, Wq, bq, q, NTOK, HID, HID);
    gemm_tc<0><<<g_1024, blk>>>(hs, Wk, bk, k, NTOK, HID, HID);
    gemm_tc<0><<<g_1024, blk>>>(hs, Wv, bv, v, NTOK, HID, HID);

    attn_tc<<<dim3(SEQ / 64, BATCH * NHEAD), dim3(128), attn_smem>>>(
        q, k, v, dist, mask, hm, ctx);

    gemm_tc<0><<<g_1024, blk>>>(ctx, Wo, bo, tmp, NTOK, HID, HID);
    ln_residual<<<NTOK, dim3(256)>>>(tmp, hs, ln1g, ln1b, attnout);

    gemm_tc<1><<<g_ff1, blk>>>(attnout, Wi, bi, inter, NTOK, FFDIM, HID);
    gemm_tc<0><<<g_1024, blk>>>(inter, Wo2, bo2, tmp, NTOK, HID, FFDIM);
    ln_residual<<<NTOK, dim3(256)>>>(tmp, attnout, ln2g, ln2b, out);
}

// round 4
// speedup vs baseline: 2.5423x; 1.0249x over previous
#include <cuda_runtime.h>
#include <math.h>
#include <stdint.h>

#define HID    1024
#define FFDIM  4096
#define NHEAD  16
#define HD     64
#define BATCH  4
#define SEQ    1024
#define NTOK   (BATCH*SEQ)
#define MAXPOS 1024

// ---------------- scratch ----------------
__device__ float g_q[NTOK * HID];
__device__ float g_k[NTOK * HID];
__device__ float g_v[NTOK * HID];
__device__ float g_ctx[NTOK * HID];
__device__ float g_tmp[NTOK * HID];
__device__ float g_attnout[NTOK * HID];
__device__ float g_inter[NTOK * FFDIM];

// ---------------- helpers ----------------
__device__ __forceinline__ uint32_t f2tf(float f) {
    uint32_t u;
    asm("cvt.rna.tf32.f32 %0, %1;" : "=r"(u) : "f"(f));
    return u;
}

__device__ __forceinline__ void mma_tf32(float c[4], const uint32_t a[4],
                                         const uint32_t b[2]) {
    asm volatile(
        "mma.sync.aligned.m16n8k8.row.col.f32.tf32.tf32.f32 "
        "{%0,%1,%2,%3}, {%4,%5,%6,%7}, {%8,%9}, {%0,%1,%2,%3};"
        : "+f"(c[0]), "+f"(c[1]), "+f"(c[2]), "+f"(c[3])
        : "r"(a[0]), "r"(a[1]), "r"(a[2]), "r"(a[3]), "r"(b[0]), "r"(b[1]));
}

__device__ __forceinline__ void cp16(float* smem, const float* gmem) {
    uint32_t s = (uint32_t)__cvta_generic_to_shared(smem);
    asm volatile("cp.async.cg.shared.global [%0], [%1], 16;" :: "r"(s), "l"(gmem));
}
#define CP_COMMIT() asm volatile("cp.async.commit_group;")
#define CP_WAIT0()  asm volatile("cp.async.wait_group 0;")

// ---------------- double-buffered tf32 GEMM body ------------------------------
// 128x128 tile, BK=32, 256 thr, 2-stage cp.async. Raw fp32 bits -> tf32 mma.
#define GA(s,r,c) ((( (s)*128 + (r) )*36) + (c))
#define GB(s,r,c) ((( (s)*32  + (r) )*136) + (c))
#define GEMM_SMEM_BYTES ((2*128*36 + 2*32*136) * 4)

template <int GELU>
__device__ __forceinline__ void gemm_body(
    const float* __restrict__ A, const float* __restrict__ Bm,
    const float* __restrict__ bias, float* __restrict__ C,
    int M, int N, int K, float* sm)
{
    float* As = sm;
    float* Bs = sm + 2 * 128 * 36;

    const int tid = threadIdx.x;
    const int w   = tid >> 5;
    const int l   = tid & 31;
    const int wr  = w >> 2;
    const int wc  = w & 3;
    const int m0  = blockIdx.y * 128;
    const int n0  = blockIdx.x * 128;
    const int g   = l >> 2;
    const int t4  = l & 3;

    const int ar = tid >> 3;
    const int ac = (tid & 7) << 2;
    const int br = tid >> 5;
    const int bc = (tid & 31) << 2;

    float c[4][4][4];
#pragma unroll
    for (int mi = 0; mi < 4; mi++)
#pragma unroll
        for (int ni = 0; ni < 4; ni++)
#pragma unroll
            for (int r = 0; r < 4; r++) c[mi][ni][r] = 0.f;

    // prologue: stage 0
#pragma unroll
    for (int i = 0; i < 4; i++)
        cp16(&As[GA(0, ar + 32 * i, ac)], &A[(size_t)(m0 + ar + 32 * i) * K + ac]);
#pragma unroll
    for (int i = 0; i < 4; i++)
        cp16(&Bs[GB(0, br + 8 * i, bc)], &Bm[(size_t)(br + 8 * i) * N + n0 + bc]);
    CP_COMMIT();

    for (int k0 = 0; k0 < K; k0 += 32) {
        const int s = (k0 >> 5) & 1;
        CP_WAIT0();
        __syncthreads();
        if (k0 + 32 < K) {
            const int ns = s ^ 1;
            const int nk = k0 + 32;
#pragma unroll
            for (int i = 0; i < 4; i++)
                cp16(&As[GA(ns, ar + 32 * i, ac)],
                     &A[(size_t)(m0 + ar + 32 * i) * K + nk + ac]);
#pragma unroll
            for (int i = 0; i < 4; i++)
                cp16(&Bs[GB(ns, br + 8 * i, bc)],
                     &Bm[(size_t)(nk + br + 8 * i) * N + n0 + bc]);
            CP_COMMIT();
        }

#pragma unroll
        for (int kk = 0; kk < 4; kk++) {
            const int kb = kk * 8;
            uint32_t a[4][4], b[4][2];
#pragma unroll
            for (int mi = 0; mi < 4; mi++) {
                const int mrow = wr * 64 + mi * 16 + g;
                a[mi][0] = __float_as_uint(As[GA(s, mrow,     kb + t4)]);
                a[mi][1] = __float_as_uint(As[GA(s, mrow + 8, kb + t4)]);
                a[mi][2] = __float_as_uint(As[GA(s, mrow,     kb + t4 + 4)]);
                a[mi][3] = __float_as_uint(As[GA(s, mrow + 8, kb + t4 + 4)]);
            }
#pragma unroll
            for (int ni = 0; ni < 4; ni++) {
                const int ncol = wc * 32 + ni * 8 + g;
                b[ni][0] = __float_as_uint(Bs[GB(s, kb + t4,     ncol)]);
                b[ni][1] = __float_as_uint(Bs[GB(s, kb + t4 + 4, ncol)]);
            }
#pragma unroll
            for (int mi = 0; mi < 4; mi++)
#pragma unroll
                for (int ni = 0; ni < 4; ni++)
                    mma_tf32(c[mi][ni], a[mi], b[ni]);
        }
    }

#pragma unroll
    for (int mi = 0; mi < 4; mi++) {
#pragma unroll
        for (int ni = 0; ni < 4; ni++) {
            const int row = m0 + wr * 64 + mi * 16 + g;
            const int col = n0 + wc * 32 + ni * 8 + t4 * 2;
            const float b0 = bias[col], b1 = bias[col + 1];
            float v0 = c[mi][ni][0] + b0;
            float v1 = c[mi][ni][1] + b1;
            float v2 = c[mi][ni][2] + b0;
            float v3 = c[mi][ni][3] + b1;
            if (GELU) {
                v0 = 0.5f * v0 * (1.0f + erff(v0 * 0.70710678118654752f));
                v1 = 0.5f * v1 * (1.0f + erff(v1 * 0.70710678118654752f));
                v2 = 0.5f * v2 * (1.0f + erff(v2 * 0.70710678118654752f));
                v3 = 0.5f * v3 * (1.0f + erff(v3 * 0.70710678118654752f));
            }
            *(float2*)&C[(size_t)row * N + col]       = make_float2(v0, v1);
            *(float2*)&C[(size_t)(row + 8) * N + col] = make_float2(v2, v3);
        }
    }
}

template <int GELU>
__global__ void __launch_bounds__(256) gemm_db(
    const float* __restrict__ A, const float* __restrict__ Bm,
    const float* __restrict__ bias, float* __restrict__ C,
    int M, int N, int K)
{
    extern __shared__ float sm[];
    gemm_body<GELU>(A, Bm, bias, C, M, N, K, sm);
}

// fused QKV: blockIdx.z selects weight/bias/output
__global__ void __launch_bounds__(256) qkv_db(
    const float* __restrict__ A,
    const float* __restrict__ W0, const float* __restrict__ W1, const float* __restrict__ W2,
    const float* __restrict__ b0, const float* __restrict__ b1, const float* __restrict__ b2,
    float* __restrict__ o0, float* __restrict__ o1, float* __restrict__ o2)
{
    extern __shared__ float sm[];
    const int z = blockIdx.z;
    const float* W = (z == 0) ? W0 : (z == 1) ? W1 : W2;
    const float* bb = (z == 0) ? b0 : (z == 1) ? b1 : b2;
    float* O = (z == 0) ? o0 : (z == 1) ? o1 : o2;
    gemm_body<0>(A, W, bb, O, NTOK, HID, HID, sm);
}

// ---------------- LayerNorm(x + res) * g + b ----------------
__global__ void __launch_bounds__(256) ln_residual(
    const float* __restrict__ x, const float* __restrict__ res,
    const float* __restrict__ g, const float* __restrict__ b,
    float* __restrict__ out)
{
    __shared__ float buf[HID];
    __shared__ float red[8];
    const int row = blockIdx.x;
    const int tid = threadIdx.x;
    const size_t base = (size_t)row * HID;

    float s = 0.f;
    for (int c = tid; c < HID; c += 256) {
        float v = x[base + c] + res[base + c];
        buf[c] = v;
        s += v;
    }
#pragma unroll
    for (int o = 16; o; o >>= 1) s += __shfl_xor_sync(0xffffffffu, s, o);
    if ((tid & 31) == 0) red[tid >> 5] = s;
    __syncthreads();
    if (tid < 8) {
        s = red[tid];
#pragma unroll
        for (int o = 4; o; o >>= 1) s += __shfl_xor_sync(0xffu, s, o, 8);
        if (tid == 0) red[0] = s;
    }
    __syncthreads();
    float mean = red[0] * (1.0f / HID);
    __syncthreads();

    float vs = 0.f;
    for (int c = tid; c < HID; c += 256) {
        float d = buf[c] - mean;
        vs += d * d;
    }
#pragma unroll
    for (int o = 16; o; o >>= 1) vs += __shfl_xor_sync(0xffffffffu, vs, o);
    if ((tid & 31) == 0) red[tid >> 5] = vs;
    __syncthreads();
    if (tid < 8) {
        vs = red[tid];
#pragma unroll
        for (int o = 4; o; o >>= 1) vs += __shfl_xor_sync(0xffu, vs, o, 8);
        if (tid == 0) red[0] = vs;
    }
    __syncthreads();
    float inv = rsqrtf(red[0] * (1.0f / HID) + 1e-12f);
    __syncthreads();

    for (int c = tid; c < HID; c += 256)
        out[base + c] = (buf[c] - mean) * inv * g[c] + b[c];
}

// ---------------- tensor-core attention, 8 warps (4 m x 2 n-split) -----------
#define AST 68
#define VST 72
#define BST 132
#define ATTN_SMEM_FLOATS (64*AST + 64*AST + 128*AST + 64*BST + 64*BST + 64*AST + 256)

__global__ void __launch_bounds__(256) attn_tc(
    const float* __restrict__ Q, const float* __restrict__ K,
    const float* __restrict__ V, const float* __restrict__ dist,
    const float* __restrict__ mask, const float* __restrict__ hm,
    float* __restrict__ ctx)
{
    extern __shared__ float smf[];
    float* Qs   = smf;                   // [64][AST]
    float* Ks   = Qs + 64 * AST;         // [64][AST]
    float* EVs  = Ks + 64 * AST;         // E: [128][AST] / V: [64][VST]
    float* B1s  = EVs + 128 * AST;       // [64][BST]
    float* B2s  = B1s + 64 * BST;        // [64][BST]
    float* Ps   = B2s + 64 * BST;        // [64][AST]
    float* Rmax = Ps + 64 * AST;         // [2][64]
    float* Rsum = Rmax + 128;            // [2][64]

    const int tid = threadIdx.x;
    const int w   = tid >> 5;
    const int wm  = w & 3;               // m-warp: rows [16*wm, 16*wm+16)
    const int wn  = w >> 2;              // n-half: 0 or 1
    const int l   = tid & 31;
    const int g   = l >> 2;
    const int t4  = l & 3;
    const int bh  = blockIdx.y;
    const int b   = bh >> 4;
    const int h   = bh & 15;
    const int l0  = blockIdx.x * 64;

    const int li0 = 16 * wm + g;
    const int li1 = li0 + 8;

    const float* Qg = Q + (size_t)(b * SEQ) * HID + h * HD;
    const float* Kg = K + (size_t)(b * SEQ) * HID + h * HD;
    const float* Vg = V + (size_t)(b * SEQ) * HID + h * HD;
    const float* mg = mask + b * SEQ;

    for (int idx = tid; idx < 64 * 16; idx += 256) {
        int r = idx >> 4, c4 = (idx & 15) << 2;
        float4 v = *(const float4*)&Qg[(size_t)(l0 + r) * HID + c4];
        *(uint4*)&Qs[r * AST + c4] =
            make_uint4(f2tf(v.x), f2tf(v.y), f2tf(v.z), f2tf(v.w));
    }

    float O[4][4];
#pragma unroll
    for (int ni = 0; ni < 4; ni++)
#pragma unroll
        for (int r = 0; r < 4; r++) O[ni][r] = 0.f;
    float mrow[2] = {-1e30f, -1e30f};
    float lrow[2] = {0.f, 0.f};

    for (int rt = 0; rt < 16; rt++) {
        const int r0 = rt * 64;
        __syncthreads();   // prev PV done

        for (int idx = tid; idx < 64 * 16; idx += 256) {
            int r = idx >> 4, c4 = (idx & 15) << 2;
            float4 v = *(const float4*)&Kg[(size_t)(r0 + r) * HID + c4];
            *(uint4*)&Ks[r * AST + c4] =
                make_uint4(f2tf(v.x), f2tf(v.y), f2tf(v.z), f2tf(v.w));
        }
        const int dbase = l0 - r0 + 960;
        for (int idx = tid; idx < 127 * 16; idx += 256) {
            int r = idx >> 4, c4 = (idx & 15) << 2;
            float4 v = *(const float4*)&dist[(size_t)(dbase + r) * HD + c4];
            *(uint4*)&EVs[r * AST + c4] =
                make_uint4(f2tf(v.x), f2tf(v.y), f2tf(v.z), f2tf(v.w));
        }
        __syncthreads();

        // ---- B2 = K@E^T (warp n-half), then B1 = Q@E^T; Q a-frags reused for S
        uint32_t a[8][4];
#pragma unroll
        for (int mat = 0; mat < 2; mat++) {
            const float* Asrc = mat ? Qs : Ks;
            float* Dst = mat ? B1s : B2s;
#pragma unroll
            for (int kk = 0; kk < 8; kk++) {
                const int kb = kk * 8;
                a[kk][0] = __float_as_uint(Asrc[li0 * AST + kb + t4]);
                a[kk][1] = __float_as_uint(Asrc[li1 * AST + kb + t4]);
                a[kk][2] = __float_as_uint(Asrc[li0 * AST + kb + t4 + 4]);
                a[kk][3] = __float_as_uint(Asrc[li1 * AST + kb + t4 + 4]);
            }
            float c[8][4];
#pragma unroll
            for (int ni = 0; ni < 8; ni++)
#pragma unroll
                for (int r = 0; r < 4; r++) c[ni][r] = 0.f;
#pragma unroll
            for (int kk = 0; kk < 8; kk++) {
                const int kb = kk * 8;
#pragma unroll
                for (int ni = 0; ni < 8; ni++) {
                    const int ncol = wn * 64 + ni * 8 + g;
                    uint32_t bf[2];
                    bf[0] = __float_as_uint(EVs[ncol * AST + kb + t4]);
                    bf[1] = __float_as_uint(EVs[ncol * AST + kb + t4 + 4]);
                    mma_tf32(c[ni], a[kk], bf);
                }
            }
#pragma unroll
            for (int ni = 0; ni < 8; ni++) {
                const int col = wn * 64 + ni * 8 + 2 * t4;
                *(float2*)&Dst[li0 * BST + col] = make_float2(c[ni][0], c[ni][1]);
                *(float2*)&Dst[li1 * BST + col] = make_float2(c[ni][2], c[ni][3]);
            }
        }

        // ---- S = Q@K^T : warp computes cols [wn*32, wn*32+32)
        float cS[4][4];
#pragma unroll
        for (int ni = 0; ni < 4; ni++)
#pragma unroll
            for (int r = 0; r < 4; r++) cS[ni][r] = 0.f;
#pragma unroll
        for (int kk = 0; kk < 8; kk++) {
            const int kb = kk * 8;
#pragma unroll
            for (int ni = 0; ni < 4; ni++) {
                const int ncol = wn * 32 + ni * 8 + g;
                uint32_t bf[2];
                bf[0] = __float_as_uint(Ks[ncol * AST + kb + t4]);
                bf[1] = __float_as_uint(Ks[ncol * AST + kb + t4 + 4]);
                mma_tf32(cS[ni], a[kk], bf);
            }
        }
        __syncthreads();   // B1/B2 visible; E reads done

        // ---- V load (overwrites E region, stride VST)
        for (int idx = tid; idx < 64 * 16; idx += 256) {
            int r = idx >> 4, c4 = (idx & 15) << 2;
            float4 v = *(const float4*)&Vg[(size_t)(r0 + r) * HID + c4];
            *(uint4*)&EVs[r * VST + c4] =
                make_uint4(f2tf(v.x), f2tf(v.y), f2tf(v.z), f2tf(v.w));
        }

        // ---- bias gather + scale + mask, partial row max
        float vmax0 = -1e30f, vmax1 = -1e30f;
#pragma unroll
        for (int ni = 0; ni < 4; ni++) {
#pragma unroll
            for (int e = 0; e < 2; e++) {
                const int rj = wn * 32 + ni * 8 + 2 * t4 + e;
                const float mv = mg[r0 + rj];
                const int ib0 = li0 - rj + 63;
                const int ib1 = li1 - rj + 63;
                float v0 = (cS[ni][e]     + B1s[li0 * BST + ib0] + B2s[rj * BST + ib0]) * 0.125f + mv;
                float v1 = (cS[ni][2 + e] + B1s[li1 * BST + ib1] + B2s[rj * BST + ib1]) * 0.125f + mv;
                cS[ni][e]     = v0;
                cS[ni][2 + e] = v1;
                vmax0 = fmaxf(vmax0, v0);
                vmax1 = fmaxf(vmax1, v1);
            }
        }
        vmax0 = fmaxf(vmax0, __shfl_xor_sync(0xffffffffu, vmax0, 1));
        vmax0 = fmaxf(vmax0, __shfl_xor_sync(0xffffffffu, vmax0, 2));
        vmax1 = fmaxf(vmax1, __shfl_xor_sync(0xffffffffu, vmax1, 1));
        vmax1 = fmaxf(vmax1, __shfl_xor_sync(0xffffffffu, vmax1, 2));
        if (t4 == 0) {
            Rmax[wn * 64 + li0] = vmax0;
            Rmax[wn * 64 + li1] = vmax1;
        }
        __syncthreads();
        vmax0 = fmaxf(vmax0, Rmax[(wn ^ 1) * 64 + li0]);
        vmax1 = fmaxf(vmax1, Rmax[(wn ^ 1) * 64 + li1]);

        const float nm0 = fmaxf(mrow[0], vmax0);
        const float nm1 = fmaxf(mrow[1], vmax1);
        const float corr0 = __expf(mrow[0] - nm0);
        const float corr1 = __expf(mrow[1] - nm1);

        float ts0 = 0.f, ts1 = 0.f;
#pragma unroll
        for (int ni = 0; ni < 4; ni++) {
#pragma unroll
            for (int e = 0; e < 2; e++) {
                const int cj = wn * 32 + ni * 8 + 2 * t4 + e;
                float p0 = __expf(cS[ni][e]     - nm0);
                float p1 = __expf(cS[ni][2 + e] - nm1);
                Ps[li0 * AST + cj] = __uint_as_float(f2tf(p0));
                Ps[li1 * AST + cj] = __uint_as_float(f2tf(p1));
                ts0 += p0;
                ts1 += p1;
            }
        }
        ts0 += __shfl_xor_sync(0xffffffffu, ts0, 1);
        ts0 += __shfl_xor_sync(0xffffffffu, ts0, 2);
        ts1 += __shfl_xor_sync(0xffffffffu, ts1, 1);
        ts1 += __shfl_xor_sync(0xffffffffu, ts1, 2);
        if (t4 == 0) {
            Rsum[wn * 64 + li0] = ts0;
            Rsum[wn * 64 + li1] = ts1;
        }
        __syncthreads();   // Rsum, Ps, V all visible
        ts0 += Rsum[(wn ^ 1) * 64 + li0];
        ts1 += Rsum[(wn ^ 1) * 64 + li1];

        lrow[0] = lrow[0] * corr0 + ts0;
        lrow[1] = lrow[1] * corr1 + ts1;
        mrow[0] = nm0;
        mrow[1] = nm1;
#pragma unroll
        for (int ni = 0; ni < 4; ni++) {
            O[ni][0] *= corr0;
            O[ni][1] *= corr0;
            O[ni][2] *= corr1;
            O[ni][3] *= corr1;
        }

        // ---- PV: O += P@V   (warp cols [wn*32, wn*32+32))
#pragma unroll
        for (int kk = 0; kk < 8; kk++) {
            const int kb = kk * 8;
            uint32_t ap[4];
            ap[0] = __float_as_uint(Ps[li0 * AST + kb + t4]);
            ap[1] = __float_as_uint(Ps[li1 * AST + kb + t4]);
            ap[2] = __float_as_uint(Ps[li0 * AST + kb + t4 + 4]);
            ap[3] = __float_as_uint(Ps[li1 * AST + kb + t4 + 4]);
#pragma unroll
            for (int ni = 0; ni < 4; ni++) {
                const int ncol = wn * 32 + ni * 8 + g;
                uint32_t bf[2];
                bf[0] = __float_as_uint(EVs[(kb + t4) * VST + ncol]);
                bf[1] = __float_as_uint(EVs[(kb + t4 + 4) * VST + ncol]);
                mma_tf32(O[ni], ap, bf);
            }
        }
    }

    const float hscale = hm[h];
    const float inv0 = hscale / lrow[0];
    const float inv1 = hscale / lrow[1];
#pragma unroll
    for (int ni = 0; ni < 4; ni++) {
        const int col = h * HD + wn * 32 + ni * 8 + 2 * t4;
        const size_t row0g = (size_t)(b * SEQ + l0 + li0) * HID + col;
        const size_t row1g = (size_t)(b * SEQ + l0 + li1) * HID + col;
        *(float2*)&ctx[row0g] = make_float2(O[ni][0] * inv0, O[ni][1] * inv0);
        *(float2*)&ctx[row1g] = make_float2(O[ni][2] * inv1, O[ni][3] * inv1);
    }
}

// ---------------- launch ----------------
extern "C" void kernel_launch(void* const* d_in, const int* in_sizes, int n_in,
                              void* d_out, int out_size)
{
    const float* hs   = (const float*)d_in[0];
    const float* mask = (const float*)d_in[1];
    const float* hm   = (const float*)d_in[2];
    const float* Wq   = (const float*)d_in[3];
    const float* bq   = (const float*)d_in[4];
    const float* Wk   = (const float*)d_in[5];
    const float* bk   = (const float*)d_in[6];
    const float* Wv   = (const float*)d_in[7];
    const float* bv   = (const float*)d_in[8];
    const float* dist = (const float*)d_in[9];
    const float* Wo   = (const float*)d_in[10];
    const float* bo   = (const float*)d_in[11];
    const float* ln1g = (const float*)d_in[12];
    const float* ln1b = (const float*)d_in[13];
    const float* Wi   = (const float*)d_in[14];
    const float* bi   = (const float*)d_in[15];
    const float* Wo2  = (const float*)d_in[16];
    const float* bo2  = (const float*)d_in[17];
    const float* ln2g = (const float*)d_in[18];
    const float* ln2b = (const float*)d_in[19];
    float* out = (float*)d_out;

    float *q, *k, *v, *ctx, *tmp, *attnout, *inter;
    cudaGetSymbolAddress((void**)&q,       g_q);
    cudaGetSymbolAddress((void**)&k,       g_k);
    cudaGetSymbolAddress((void**)&v,       g_v);
    cudaGetSymbolAddress((void**)&ctx,     g_ctx);
    cudaGetSymbolAddress((void**)&tmp,     g_tmp);
    cudaGetSymbolAddress((void**)&attnout, g_attnout);
    cudaGetSymbolAddress((void**)&inter,   g_inter);

    const size_t attn_smem = ATTN_SMEM_FLOATS * sizeof(float);
    cudaFuncSetAttribute(attn_tc, cudaFuncAttributeMaxDynamicSharedMemorySize,
                         (int)attn_smem);
    cudaFuncSetAttribute(gemm_db<0>, cudaFuncAttributeMaxDynamicSharedMemorySize,
                         GEMM_SMEM_BYTES);
    cudaFuncSetAttribute(gemm_db<1>, cudaFuncAttributeMaxDynamicSharedMemorySize,
                         GEMM_SMEM_BYTES);
    cudaFuncSetAttribute(qkv_db, cudaFuncAttributeMaxDynamicSharedMemorySize,
                         GEMM_SMEM_BYTES);

    dim3 blk(256);
    dim3 g_qkv(HID / 128, NTOK / 128, 3);
    dim3 g_1024(HID / 128, NTOK / 128);
    dim3 g_ff1(FFDIM / 128, NTOK / 128);

    qkv_db<<<g_qkv, blk, GEMM_SMEM_BYTES>>>(hs, Wq, Wk, Wv, bq, bk, bv, q, k, v);

    attn_tc<<<dim3(SEQ / 64, BATCH * NHEAD), blk, attn_smem>>>(
        q, k, v, dist, mask, hm, ctx);

    gemm_db<0><<<g_1024, blk, GEMM_SMEM_BYTES>>>(ctx, Wo, bo, tmp, NTOK, HID, HID);
    ln_residual<<<NTOK, blk>>>(tmp, hs, ln1g, ln1b, attnout);

    gemm_db<1><<<g_ff1, blk, GEMM_SMEM_BYTES>>>(attnout, Wi, bi, inter, NTOK, FFDIM, HID);
    gemm_db<0><<<g_1024, blk, GEMM_SMEM_BYTES>>>(inter, Wo2, bo2, tmp, NTOK, HID, FFDIM);
    ln_residual<<<NTOK, blk>>>(tmp, attnout, ln2g, ln2b, out);
}

// round 5
// speedup vs baseline: 2.8614x; 1.1255x over previous
#include <cuda_runtime.h>
#include <cuda_bf16.h>
#include <math.h>
#include <stdint.h>

#define HID    1024
#define FFDIM  4096
#define NHEAD  16
#define HD     64
#define BATCH  4
#define SEQ    1024
#define NTOK   (BATCH*SEQ)
#define MAXPOS 1024

// ---------------- scratch ----------------
__device__ float g_q[NTOK * HID];
__device__ float g_k[NTOK * HID];
__device__ float g_v[NTOK * HID];
__device__ float g_ctx[NTOK * HID];
__device__ float g_tmp[NTOK * HID];
__device__ float g_attnout[NTOK * HID];
__device__ float g_inter[NTOK * FFDIM];

// ---------------- helpers ----------------
__device__ __forceinline__ uint32_t f2tf(float f) {
    uint32_t u;
    asm("cvt.rna.tf32.f32 %0, %1;" : "=r"(u) : "f"(f));
    return u;
}

__device__ __forceinline__ uint32_t pack_bf2(float x, float y) {
    __nv_bfloat162 h = __floats2bfloat162_rn(x, y);
    return *(uint32_t*)&h;
}

__device__ __forceinline__ void mma_tf32(float c[4], const uint32_t a[4],
                                         const uint32_t b[2]) {
    asm volatile(
        "mma.sync.aligned.m16n8k8.row.col.f32.tf32.tf32.f32 "
        "{%0,%1,%2,%3}, {%4,%5,%6,%7}, {%8,%9}, {%0,%1,%2,%3};"
        : "+f"(c[0]), "+f"(c[1]), "+f"(c[2]), "+f"(c[3])
        : "r"(a[0]), "r"(a[1]), "r"(a[2]), "r"(a[3]), "r"(b[0]), "r"(b[1]));
}

__device__ __forceinline__ void mma_bf16(float c[4], const uint32_t a[4],
                                         const uint32_t b[2]) {
    asm volatile(
        "mma.sync.aligned.m16n8k16.row.col.f32.bf16.bf16.f32 "
        "{%0,%1,%2,%3}, {%4,%5,%6,%7}, {%8,%9}, {%0,%1,%2,%3};"
        : "+f"(c[0]), "+f"(c[1]), "+f"(c[2]), "+f"(c[3])
        : "r"(a[0]), "r"(a[1]), "r"(a[2]), "r"(a[3]), "r"(b[0]), "r"(b[1]));
}

__device__ __forceinline__ void cp16(float* smem, const float* gmem) {
    uint32_t s = (uint32_t)__cvta_generic_to_shared(smem);
    asm volatile("cp.async.cg.shared.global [%0], [%1], 16;" :: "r"(s), "l"(gmem));
}
#define CP_COMMIT() asm volatile("cp.async.commit_group;")
#define CP_WAIT0()  asm volatile("cp.async.wait_group 0;")

// ---------------- double-buffered tf32 GEMM (rna rounding at frag load) ------
#define GA(s,r,c) ((( (s)*128 + (r) )*36) + (c))
#define GB(s,r,c) ((( (s)*32  + (r) )*136) + (c))
#define GEMM_SMEM_BYTES ((2*128*36 + 2*32*136) * 4)

template <int GELU>
__device__ __forceinline__ void gemm_body(
    const float* __restrict__ A, const float* __restrict__ Bm,
    const float* __restrict__ bias, float* __restrict__ C,
    int M, int N, int K, float* sm)
{
    float* As = sm;
    float* Bs = sm + 2 * 128 * 36;

    const int tid = threadIdx.x;
    const int w   = tid >> 5;
    const int l   = tid & 31;
    const int wr  = w >> 2;
    const int wc  = w & 3;
    const int m0  = blockIdx.y * 128;
    const int n0  = blockIdx.x * 128;
    const int g   = l >> 2;
    const int t4  = l & 3;

    const int ar = tid >> 3;
    const int ac = (tid & 7) << 2;
    const int br = tid >> 5;
    const int bc = (tid & 31) << 2;

    float c[4][4][4];
#pragma unroll
    for (int mi = 0; mi < 4; mi++)
#pragma unroll
        for (int ni = 0; ni < 4; ni++)
#pragma unroll
            for (int r = 0; r < 4; r++) c[mi][ni][r] = 0.f;

#pragma unroll
    for (int i = 0; i < 4; i++)
        cp16(&As[GA(0, ar + 32 * i, ac)], &A[(size_t)(m0 + ar + 32 * i) * K + ac]);
#pragma unroll
    for (int i = 0; i < 4; i++)
        cp16(&Bs[GB(0, br + 8 * i, bc)], &Bm[(size_t)(br + 8 * i) * N + n0 + bc]);
    CP_COMMIT();

    for (int k0 = 0; k0 < K; k0 += 32) {
        const int s = (k0 >> 5) & 1;
        CP_WAIT0();
        __syncthreads();
        if (k0 + 32 < K) {
            const int ns = s ^ 1;
            const int nk = k0 + 32;
#pragma unroll
            for (int i = 0; i < 4; i++)
                cp16(&As[GA(ns, ar + 32 * i, ac)],
                     &A[(size_t)(m0 + ar + 32 * i) * K + nk + ac]);
#pragma unroll
            for (int i = 0; i < 4; i++)
                cp16(&Bs[GB(ns, br + 8 * i, bc)],
                     &Bm[(size_t)(nk + br + 8 * i) * N + n0 + bc]);
            CP_COMMIT();
        }

#pragma unroll
        for (int kk = 0; kk < 4; kk++) {
            const int kb = kk * 8;
            uint32_t a[4][4], b[4][2];
#pragma unroll
            for (int mi = 0; mi < 4; mi++) {
                const int mrow = wr * 64 + mi * 16 + g;
                a[mi][0] = f2tf(As[GA(s, mrow,     kb + t4)]);
                a[mi][1] = f2tf(As[GA(s, mrow + 8, kb + t4)]);
                a[mi][2] = f2tf(As[GA(s, mrow,     kb + t4 + 4)]);
                a[mi][3] = f2tf(As[GA(s, mrow + 8, kb + t4 + 4)]);
            }
#pragma unroll
            for (int ni = 0; ni < 4; ni++) {
                const int ncol = wc * 32 + ni * 8 + g;
                b[ni][0] = f2tf(Bs[GB(s, kb + t4,     ncol)]);
                b[ni][1] = f2tf(Bs[GB(s, kb + t4 + 4, ncol)]);
            }
#pragma unroll
            for (int mi = 0; mi < 4; mi++)
#pragma unroll
                for (int ni = 0; ni < 4; ni++)
                    mma_tf32(c[mi][ni], a[mi], b[ni]);
        }
    }

#pragma unroll
    for (int mi = 0; mi < 4; mi++) {
#pragma unroll
        for (int ni = 0; ni < 4; ni++) {
            const int row = m0 + wr * 64 + mi * 16 + g;
            const int col = n0 + wc * 32 + ni * 8 + t4 * 2;
            const float b0 = bias[col], b1 = bias[col + 1];
            float v0 = c[mi][ni][0] + b0;
            float v1 = c[mi][ni][1] + b1;
            float v2 = c[mi][ni][2] + b0;
            float v3 = c[mi][ni][3] + b1;
            if (GELU) {
                v0 = 0.5f * v0 * (1.0f + erff(v0 * 0.70710678118654752f));
                v1 = 0.5f * v1 * (1.0f + erff(v1 * 0.70710678118654752f));
                v2 = 0.5f * v2 * (1.0f + erff(v2 * 0.70710678118654752f));
                v3 = 0.5f * v3 * (1.0f + erff(v3 * 0.70710678118654752f));
            }
            *(float2*)&C[(size_t)row * N + col]       = make_float2(v0, v1);
            *(float2*)&C[(size_t)(row + 8) * N + col] = make_float2(v2, v3);
        }
    }
}

template <int GELU>
__global__ void __launch_bounds__(256) gemm_db(
    const float* __restrict__ A, const float* __restrict__ Bm,
    const float* __restrict__ bias, float* __restrict__ C,
    int M, int N, int K)
{
    extern __shared__ float sm[];
    gemm_body<GELU>(A, Bm, bias, C, M, N, K, sm);
}

__global__ void __launch_bounds__(256) qkv_db(
    const float* __restrict__ A,
    const float* __restrict__ W0, const float* __restrict__ W1, const float* __restrict__ W2,
    const float* __restrict__ b0, const float* __restrict__ b1, const float* __restrict__ b2,
    float* __restrict__ o0, float* __restrict__ o1, float* __restrict__ o2)
{
    extern __shared__ float sm[];
    const int z = blockIdx.z;
    const float* W = (z == 0) ? W0 : (z == 1) ? W1 : W2;
    const float* bb = (z == 0) ? b0 : (z == 1) ? b1 : b2;
    float* O = (z == 0) ? o0 : (z == 1) ? o1 : o2;
    gemm_body<0>(A, W, bb, O, NTOK, HID, HID, sm);
}

// ---------------- LayerNorm(x + res) * g + b ----------------
__global__ void __launch_bounds__(256) ln_residual(
    const float* __restrict__ x, const float* __restrict__ res,
    const float* __restrict__ g, const float* __restrict__ b,
    float* __restrict__ out)
{
    __shared__ float buf[HID];
    __shared__ float red[8];
    const int row = blockIdx.x;
    const int tid = threadIdx.x;
    const size_t base = (size_t)row * HID;

    float s = 0.f;
    for (int c = tid; c < HID; c += 256) {
        float v = x[base + c] + res[base + c];
        buf[c] = v;
        s += v;
    }
#pragma unroll
    for (int o = 16; o; o >>= 1) s += __shfl_xor_sync(0xffffffffu, s, o);
    if ((tid & 31) == 0) red[tid >> 5] = s;
    __syncthreads();
    if (tid < 8) {
        s = red[tid];
#pragma unroll
        for (int o = 4; o; o >>= 1) s += __shfl_xor_sync(0xffu, s, o, 8);
        if (tid == 0) red[0] = s;
    }
    __syncthreads();
    float mean = red[0] * (1.0f / HID);
    __syncthreads();

    float vs = 0.f;
    for (int c = tid; c < HID; c += 256) {
        float d = buf[c] - mean;
        vs += d * d;
    }
#pragma unroll
    for (int o = 16; o; o >>= 1) vs += __shfl_xor_sync(0xffffffffu, vs, o);
    if ((tid & 31) == 0) red[tid >> 5] = vs;
    __syncthreads();
    if (tid < 8) {
        vs = red[tid];
#pragma unroll
        for (int o = 4; o; o >>= 1) vs += __shfl_xor_sync(0xffu, vs, o, 8);
        if (tid == 0) red[0] = vs;
    }
    __syncthreads();
    float inv = rsqrtf(red[0] * (1.0f / HID) + 1e-12f);
    __syncthreads();

    for (int c = tid; c < HID; c += 256)
        out[base + c] = (buf[c] - mean) * inv * g[c] + b[c];
}

// ---------------- bf16 tensor-core attention (m16n8k16) ----------------------
// 8 warps: 4 m-warps x 2 n-halves. Q/K/E/V/P bf16 in SMEM (stride 72 halfs),
// B1/B2 fp32 (stride 130). V staged transposed for the PV B-operand.
#define HST 72
#define BST 130
// bytes: Q 9216 + K 9216 + EV 18432 + B1 33280 + B2 33280 + P 9216 + red 1024
#define ATTN_SMEM_BYTES (9216 + 9216 + 18432 + 33280 + 33280 + 9216 + 1024)

__global__ void __launch_bounds__(256, 2) attn_tc(
    const float* __restrict__ Q, const float* __restrict__ K,
    const float* __restrict__ V, const float* __restrict__ dist,
    const float* __restrict__ mask, const float* __restrict__ hm,
    float* __restrict__ ctx)
{
    extern __shared__ char smb[];
    __nv_bfloat16* Qh  = (__nv_bfloat16*)smb;                   // [64][HST]
    __nv_bfloat16* Kh  = Qh + 64 * HST;                         // [64][HST]
    __nv_bfloat16* EVh = Kh + 64 * HST;                         // E:[127][HST] / Vt:[64][HST]
    float*         B1f = (float*)(EVh + 128 * HST);             // [64][BST]
    float*         B2f = B1f + 64 * BST;                        // [64][BST]
    __nv_bfloat16* Ph  = (__nv_bfloat16*)(B2f + 64 * BST);      // [64][HST]
    float*         Rmax = (float*)(Ph + 64 * HST);              // [2][64]
    float*         Rsum = Rmax + 128;                           // [2][64]

    const int tid = threadIdx.x;
    const int w   = tid >> 5;
    const int wm  = w & 3;
    const int wn  = w >> 2;
    const int l   = tid & 31;
    const int g   = l >> 2;
    const int t4  = l & 3;
    const int bh  = blockIdx.y;
    const int b   = bh >> 4;
    const int h   = bh & 15;
    const int l0  = blockIdx.x * 64;

    const int li0 = 16 * wm + g;
    const int li1 = li0 + 8;

    const float* Qg = Q + (size_t)(b * SEQ) * HID + h * HD;
    const float* Kg = K + (size_t)(b * SEQ) * HID + h * HD;
    const float* Vg = V + (size_t)(b * SEQ) * HID + h * HD;
    const float* mg = mask + b * SEQ;

    for (int idx = tid; idx < 64 * 16; idx += 256) {
        int r = idx >> 4, c4 = (idx & 15) << 2;
        float4 v = *(const float4*)&Qg[(size_t)(l0 + r) * HID + c4];
        uint2 u = make_uint2(pack_bf2(v.x, v.y), pack_bf2(v.z, v.w));
        *(uint2*)&Qh[r * HST + c4] = u;
    }

    float O[4][4];
#pragma unroll
    for (int ni = 0; ni < 4; ni++)
#pragma unroll
        for (int r = 0; r < 4; r++) O[ni][r] = 0.f;
    float mrow[2] = {-1e30f, -1e30f};
    float lrow[2] = {0.f, 0.f};

    for (int rt = 0; rt < 16; rt++) {
        const int r0 = rt * 64;
        __syncthreads();   // prev PV done

        for (int idx = tid; idx < 64 * 16; idx += 256) {
            int r = idx >> 4, c4 = (idx & 15) << 2;
            float4 v = *(const float4*)&Kg[(size_t)(r0 + r) * HID + c4];
            *(uint2*)&Kh[r * HST + c4] =
                make_uint2(pack_bf2(v.x, v.y), pack_bf2(v.z, v.w));
        }
        const int dbase = l0 - r0 + 960;
        for (int idx = tid; idx < 127 * 16; idx += 256) {
            int r = idx >> 4, c4 = (idx & 15) << 2;
            float4 v = *(const float4*)&dist[(size_t)(dbase + r) * HD + c4];
            *(uint2*)&EVh[r * HST + c4] =
                make_uint2(pack_bf2(v.x, v.y), pack_bf2(v.z, v.w));
        }
        __syncthreads();

        // ---- B2 = K@E^T, B1 = Q@E^T (each warp does its n-half of 128 cols)
        uint32_t a[4][4];
#pragma unroll
        for (int mat = 0; mat < 2; mat++) {
            const __nv_bfloat16* Asrc = mat ? Qh : Kh;
            float* Dst = mat ? B1f : B2f;
#pragma unroll
            for (int kk = 0; kk < 4; kk++) {
                const int kb = kk * 16;
                a[kk][0] = *(const uint32_t*)&Asrc[li0 * HST + kb + 2 * t4];
                a[kk][1] = *(const uint32_t*)&Asrc[li1 * HST + kb + 2 * t4];
                a[kk][2] = *(const uint32_t*)&Asrc[li0 * HST + kb + 8 + 2 * t4];
                a[kk][3] = *(const uint32_t*)&Asrc[li1 * HST + kb + 8 + 2 * t4];
            }
            float c[8][4];
#pragma unroll
            for (int ni = 0; ni < 8; ni++)
#pragma unroll
                for (int r = 0; r < 4; r++) c[ni][r] = 0.f;
#pragma unroll
            for (int kk = 0; kk < 4; kk++) {
                const int kb = kk * 16;
#pragma unroll
                for (int ni = 0; ni < 8; ni++) {
                    const int ncol = wn * 64 + ni * 8 + g;
                    uint32_t bf[2];
                    bf[0] = *(const uint32_t*)&EVh[ncol * HST + kb + 2 * t4];
                    bf[1] = *(const uint32_t*)&EVh[ncol * HST + kb + 8 + 2 * t4];
                    mma_bf16(c[ni], a[kk], bf);
                }
            }
#pragma unroll
            for (int ni = 0; ni < 8; ni++) {
                const int col = wn * 64 + ni * 8 + 2 * t4;
                *(float2*)&Dst[li0 * BST + col] = make_float2(c[ni][0], c[ni][1]);
                *(float2*)&Dst[li1 * BST + col] = make_float2(c[ni][2], c[ni][3]);
            }
        }

        // ---- S = Q@K^T (a holds Q frags), warp cols [wn*32, wn*32+32)
        float cS[4][4];
#pragma unroll
        for (int ni = 0; ni < 4; ni++)
#pragma unroll
            for (int r = 0; r < 4; r++) cS[ni][r] = 0.f;
#pragma unroll
        for (int kk = 0; kk < 4; kk++) {
            const int kb = kk * 16;
#pragma unroll
            for (int ni = 0; ni < 4; ni++) {
                const int ncol = wn * 32 + ni * 8 + g;
                uint32_t bf[2];
                bf[0] = *(const uint32_t*)&Kh[ncol * HST + kb + 2 * t4];
                bf[1] = *(const uint32_t*)&Kh[ncol * HST + kb + 8 + 2 * t4];
                mma_bf16(cS[ni], a[kk], bf);
            }
        }
        __syncthreads();   // B1/B2 written; E reads done

        // ---- V load transposed: Vt[d][r]
        for (int idx = tid; idx < 64 * 16; idx += 256) {
            int r = idx >> 4, c4 = (idx & 15) << 2;
            float4 v = *(const float4*)&Vg[(size_t)(r0 + r) * HID + c4];
            EVh[(c4 + 0) * HST + r] = __float2bfloat16(v.x);
            EVh[(c4 + 1) * HST + r] = __float2bfloat16(v.y);
            EVh[(c4 + 2) * HST + r] = __float2bfloat16(v.z);
            EVh[(c4 + 3) * HST + r] = __float2bfloat16(v.w);
        }

        // ---- bias gather + scale + mask
        float vmax0 = -1e30f, vmax1 = -1e30f;
#pragma unroll
        for (int ni = 0; ni < 4; ni++) {
#pragma unroll
            for (int e = 0; e < 2; e++) {
                const int rj = wn * 32 + ni * 8 + 2 * t4 + e;
                const float mv = mg[r0 + rj];
                const int ib0 = li0 - rj + 63;
                const int ib1 = li1 - rj + 63;
                float v0 = (cS[ni][e]     + B1f[li0 * BST + ib0] + B2f[rj * BST + ib0]) * 0.125f + mv;
                float v1 = (cS[ni][2 + e] + B1f[li1 * BST + ib1] + B2f[rj * BST + ib1]) * 0.125f + mv;
                cS[ni][e]     = v0;
                cS[ni][2 + e] = v1;
                vmax0 = fmaxf(vmax0, v0);
                vmax1 = fmaxf(vmax1, v1);
            }
        }
        vmax0 = fmaxf(vmax0, __shfl_xor_sync(0xffffffffu, vmax0, 1));
        vmax0 = fmaxf(vmax0, __shfl_xor_sync(0xffffffffu, vmax0, 2));
        vmax1 = fmaxf(vmax1, __shfl_xor_sync(0xffffffffu, vmax1, 1));
        vmax1 = fmaxf(vmax1, __shfl_xor_sync(0xffffffffu, vmax1, 2));
        if (t4 == 0) {
            Rmax[wn * 64 + li0] = vmax0;
            Rmax[wn * 64 + li1] = vmax1;
        }
        __syncthreads();
        vmax0 = fmaxf(vmax0, Rmax[(wn ^ 1) * 64 + li0]);
        vmax1 = fmaxf(vmax1, Rmax[(wn ^ 1) * 64 + li1]);

        const float nm0 = fmaxf(mrow[0], vmax0);
        const float nm1 = fmaxf(mrow[1], vmax1);
        const float corr0 = __expf(mrow[0] - nm0);
        const float corr1 = __expf(mrow[1] - nm1);

        float ts0 = 0.f, ts1 = 0.f;
#pragma unroll
        for (int ni = 0; ni < 4; ni++) {
            const int cj = wn * 32 + ni * 8 + 2 * t4;
            float p00 = __expf(cS[ni][0] - nm0);
            float p01 = __expf(cS[ni][1] - nm0);
            float p10 = __expf(cS[ni][2] - nm1);
            float p11 = __expf(cS[ni][3] - nm1);
            *(uint32_t*)&Ph[li0 * HST + cj] = pack_bf2(p00, p01);
            *(uint32_t*)&Ph[li1 * HST + cj] = pack_bf2(p10, p11);
            ts0 += p00 + p01;
            ts1 += p10 + p11;
        }
        ts0 += __shfl_xor_sync(0xffffffffu, ts0, 1);
        ts0 += __shfl_xor_sync(0xffffffffu, ts0, 2);
        ts1 += __shfl_xor_sync(0xffffffffu, ts1, 1);
        ts1 += __shfl_xor_sync(0xffffffffu, ts1, 2);
        if (t4 == 0) {
            Rsum[wn * 64 + li0] = ts0;
            Rsum[wn * 64 + li1] = ts1;
        }
        __syncthreads();   // Rsum, P, Vt all visible
        ts0 += Rsum[(wn ^ 1) * 64 + li0];
        ts1 += Rsum[(wn ^ 1) * 64 + li1];

        lrow[0] = lrow[0] * corr0 + ts0;
        lrow[1] = lrow[1] * corr1 + ts1;
        mrow[0] = nm0;
        mrow[1] = nm1;
#pragma unroll
        for (int ni = 0; ni < 4; ni++) {
            O[ni][0] *= corr0;
            O[ni][1] *= corr0;
            O[ni][2] *= corr1;
            O[ni][3] *= corr1;
        }

        // ---- PV: O += P@V, B operand from Vt[d][r]
#pragma unroll
        for (int kk = 0; kk < 4; kk++) {
            const int kb = kk * 16;
            uint32_t ap[4];
            ap[0] = *(const uint32_t*)&Ph[li0 * HST + kb + 2 * t4];
            ap[1] = *(const uint32_t*)&Ph[li1 * HST + kb + 2 * t4];
            ap[2] = *(const uint32_t*)&Ph[li0 * HST + kb + 8 + 2 * t4];
            ap[3] = *(const uint32_t*)&Ph[li1 * HST + kb + 8 + 2 * t4];
#pragma unroll
            for (int ni = 0; ni < 4; ni++) {
                const int ncol = wn * 32 + ni * 8 + g;
                uint32_t bf[2];
                bf[0] = *(const uint32_t*)&EVh[ncol * HST + kb + 2 * t4];
                bf[1] = *(const uint32_t*)&EVh[ncol * HST + kb + 8 + 2 * t4];
                mma_bf16(O[ni], ap, bf);
            }
        }
    }

    const float hscale = hm[h];
    const float inv0 = hscale / lrow[0];
    const float inv1 = hscale / lrow[1];
#pragma unroll
    for (int ni = 0; ni < 4; ni++) {
        const int col = h * HD + wn * 32 + ni * 8 + 2 * t4;
        const size_t row0g = (size_t)(b * SEQ + l0 + li0) * HID + col;
        const size_t row1g = (size_t)(b * SEQ + l0 + li1) * HID + col;
        *(float2*)&ctx[row0g] = make_float2(O[ni][0] * inv0, O[ni][1] * inv0);
        *(float2*)&ctx[row1g] = make_float2(O[ni][2] * inv1, O[ni][3] * inv1);
    }
}

// ---------------- launch ----------------
extern "C" void kernel_launch(void* const* d_in, const int* in_sizes, int n_in,
                              void* d_out, int out_size)
{
    const float* hs   = (const float*)d_in[0];
    const float* mask = (const float*)d_in[1];
    const float* hm   = (const float*)d_in[2];
    const float* Wq   = (const float*)d_in[3];
    const float* bq   = (const float*)d_in[4];
    const float* Wk   = (const float*)d_in[5];
    const float* bk   = (const float*)d_in[6];
    const float* Wv   = (const float*)d_in[7];
    const float* bv   = (const float*)d_in[8];
    const float* dist = (const float*)d_in[9];
    const float* Wo   = (const float*)d_in[10];
    const float* bo   = (const float*)d_in[11];
    const float* ln1g = (const float*)d_in[12];
    const float* ln1b = (const float*)d_in[13];
    const float* Wi   = (const float*)d_in[14];
    const float* bi   = (const float*)d_in[15];
    const float* Wo2  = (const float*)d_in[16];
    const float* bo2  = (const float*)d_in[17];
    const float* ln2g = (const float*)d_in[18];
    const float* ln2b = (const float*)d_in[19];
    float* out = (float*)d_out;

    float *q, *k, *v, *ctx, *tmp, *attnout, *inter;
    cudaGetSymbolAddress((void**)&q,       g_q);
    cudaGetSymbolAddress((void**)&k,       g_k);
    cudaGetSymbolAddress((void**)&v,       g_v);
    cudaGetSymbolAddress((void**)&ctx,     g_ctx);
    cudaGetSymbolAddress((void**)&tmp,     g_tmp);
    cudaGetSymbolAddress((void**)&attnout, g_attnout);
    cudaGetSymbolAddress((void**)&inter,   g_inter);

    cudaFuncSetAttribute(attn_tc, cudaFuncAttributeMaxDynamicSharedMemorySize,
                         ATTN_SMEM_BYTES);
    cudaFuncSetAttribute(gemm_db<0>, cudaFuncAttributeMaxDynamicSharedMemorySize,
                         GEMM_SMEM_BYTES);
    cudaFuncSetAttribute(gemm_db<1>, cudaFuncAttributeMaxDynamicSharedMemorySize,
                         GEMM_SMEM_BYTES);
    cudaFuncSetAttribute(qkv_db, cudaFuncAttributeMaxDynamicSharedMemorySize,
                         GEMM_SMEM_BYTES);

    dim3 blk(256);
    dim3 g_qkv(HID / 128, NTOK / 128, 3);
    dim3 g_1024(HID / 128, NTOK / 128);
    dim3 g_ff1(FFDIM / 128, NTOK / 128);

    qkv_db<<<g_qkv, blk, GEMM_SMEM_BYTES>>>(hs, Wq, Wk, Wv, bq, bk, bv, q, k, v);

    attn_tc<<<dim3(SEQ / 64, BATCH * NHEAD), blk, ATTN_SMEM_BYTES>>>(
        q, k, v, dist, mask, hm, ctx);

    gemm_db<0><<<g_1024, blk, GEMM_SMEM_BYTES>>>(ctx, Wo, bo, tmp, NTOK, HID, HID);
    ln_residual<<<NTOK, blk>>>(tmp, hs, ln1g, ln1b, attnout);

    gemm_db<1><<<g_ff1, blk, GEMM_SMEM_BYTES>>>(attnout, Wi, bi, inter, NTOK, FFDIM, HID);
    gemm_db<0><<<g_1024, blk, GEMM_SMEM_BYTES>>>(inter, Wo2, bo2, tmp, NTOK, HID, FFDIM);
    ln_residual<<<NTOK, blk>>>(tmp, attnout, ln2g, ln2b, out);
}

// round 6
// speedup vs baseline: 2.9863x; 1.0436x over previous
#include <cuda_runtime.h>
#include <cuda_bf16.h>
#include <math.h>
#include <stdint.h>

#define HID    1024
#define FFDIM  4096
#define NHEAD  16
#define HD     64
#define BATCH  4
#define SEQ    1024
#define NTOK   (BATCH*SEQ)
#define MAXPOS 1024

// ---------------- scratch ----------------
__device__ float g_q[NTOK * HID];
__device__ float g_k[NTOK * HID];
__device__ float g_v[NTOK * HID];
__device__ float g_ctx[NTOK * HID];
__device__ float g_tmp[NTOK * HID];
__device__ float g_attnout[NTOK * HID];
__device__ float g_inter[NTOK * FFDIM];

// ---------------- helpers ----------------
__device__ __forceinline__ uint32_t f2tf(float f) {
    uint32_t u;
    asm("cvt.rna.tf32.f32 %0, %1;" : "=r"(u) : "f"(f));
    return u;
}

__device__ __forceinline__ uint32_t pack_bf2(float x, float y) {
    __nv_bfloat162 h = __floats2bfloat162_rn(x, y);
    return *(uint32_t*)&h;
}

__device__ __forceinline__ uint32_t smem_u32(const void* p) {
    return (uint32_t)__cvta_generic_to_shared(p);
}

__device__ __forceinline__ void mma_tf32(float c[4], const uint32_t a[4],
                                         const uint32_t b[2]) {
    asm volatile(
        "mma.sync.aligned.m16n8k8.row.col.f32.tf32.tf32.f32 "
        "{%0,%1,%2,%3}, {%4,%5,%6,%7}, {%8,%9}, {%0,%1,%2,%3};"
        : "+f"(c[0]), "+f"(c[1]), "+f"(c[2]), "+f"(c[3])
        : "r"(a[0]), "r"(a[1]), "r"(a[2]), "r"(a[3]), "r"(b[0]), "r"(b[1]));
}

__device__ __forceinline__ void mma_bf16(float c[4], const uint32_t a[4],
                                         const uint32_t b[2]) {
    asm volatile(
        "mma.sync.aligned.m16n8k16.row.col.f32.bf16.bf16.f32 "
        "{%0,%1,%2,%3}, {%4,%5,%6,%7}, {%8,%9}, {%0,%1,%2,%3};"
        : "+f"(c[0]), "+f"(c[1]), "+f"(c[2]), "+f"(c[3])
        : "r"(a[0]), "r"(a[1]), "r"(a[2]), "r"(a[3]), "r"(b[0]), "r"(b[1]));
}

__device__ __forceinline__ void ldsm_x4(uint32_t* r, uint32_t a) {
    asm volatile("ldmatrix.sync.aligned.m8n8.x4.shared.b16 {%0,%1,%2,%3}, [%4];"
        : "=r"(r[0]), "=r"(r[1]), "=r"(r[2]), "=r"(r[3]) : "r"(a));
}
__device__ __forceinline__ void ldsm_x2(uint32_t* r, uint32_t a) {
    asm volatile("ldmatrix.sync.aligned.m8n8.x2.shared.b16 {%0,%1}, [%2];"
        : "=r"(r[0]), "=r"(r[1]) : "r"(a));
}
__device__ __forceinline__ void ldsm_x2t(uint32_t* r, uint32_t a) {
    asm volatile("ldmatrix.sync.aligned.m8n8.x2.trans.shared.b16 {%0,%1}, [%2];"
        : "=r"(r[0]), "=r"(r[1]) : "r"(a));
}

__device__ __forceinline__ void cp16(float* smem, const float* gmem) {
    uint32_t s = (uint32_t)__cvta_generic_to_shared(smem);
    asm volatile("cp.async.cg.shared.global [%0], [%1], 16;" :: "r"(s), "l"(gmem));
}
#define CP_COMMIT() asm volatile("cp.async.commit_group;")
#define CP_WAIT0()  asm volatile("cp.async.wait_group 0;")

// ---------------- double-buffered tf32 GEMM (unchanged from R5) --------------
#define GA(s,r,c) ((( (s)*128 + (r) )*36) + (c))
#define GB(s,r,c) ((( (s)*32  + (r) )*136) + (c))
#define GEMM_SMEM_BYTES ((2*128*36 + 2*32*136) * 4)

template <int GELU>
__device__ __forceinline__ void gemm_body(
    const float* __restrict__ A, const float* __restrict__ Bm,
    const float* __restrict__ bias, float* __restrict__ C,
    int M, int N, int K, float* sm)
{
    float* As = sm;
    float* Bs = sm + 2 * 128 * 36;

    const int tid = threadIdx.x;
    const int w   = tid >> 5;
    const int l   = tid & 31;
    const int wr  = w >> 2;
    const int wc  = w & 3;
    const int m0  = blockIdx.y * 128;
    const int n0  = blockIdx.x * 128;
    const int g   = l >> 2;
    const int t4  = l & 3;

    const int ar = tid >> 3;
    const int ac = (tid & 7) << 2;
    const int br = tid >> 5;
    const int bc = (tid & 31) << 2;

    float c[4][4][4];
#pragma unroll
    for (int mi = 0; mi < 4; mi++)
#pragma unroll
        for (int ni = 0; ni < 4; ni++)
#pragma unroll
            for (int r = 0; r < 4; r++) c[mi][ni][r] = 0.f;

#pragma unroll
    for (int i = 0; i < 4; i++)
        cp16(&As[GA(0, ar + 32 * i, ac)], &A[(size_t)(m0 + ar + 32 * i) * K + ac]);
#pragma unroll
    for (int i = 0; i < 4; i++)
        cp16(&Bs[GB(0, br + 8 * i, bc)], &Bm[(size_t)(br + 8 * i) * N + n0 + bc]);
    CP_COMMIT();

    for (int k0 = 0; k0 < K; k0 += 32) {
        const int s = (k0 >> 5) & 1;
        CP_WAIT0();
        __syncthreads();
        if (k0 + 32 < K) {
            const int ns = s ^ 1;
            const int nk = k0 + 32;
#pragma unroll
            for (int i = 0; i < 4; i++)
                cp16(&As[GA(ns, ar + 32 * i, ac)],
                     &A[(size_t)(m0 + ar + 32 * i) * K + nk + ac]);
#pragma unroll
            for (int i = 0; i < 4; i++)
                cp16(&Bs[GB(ns, br + 8 * i, bc)],
                     &Bm[(size_t)(nk + br + 8 * i) * N + n0 + bc]);
            CP_COMMIT();
        }

#pragma unroll
        for (int kk = 0; kk < 4; kk++) {
            const int kb = kk * 8;
            uint32_t a[4][4], b[4][2];
#pragma unroll
            for (int mi = 0; mi < 4; mi++) {
                const int mrow = wr * 64 + mi * 16 + g;
                a[mi][0] = f2tf(As[GA(s, mrow,     kb + t4)]);
                a[mi][1] = f2tf(As[GA(s, mrow + 8, kb + t4)]);
                a[mi][2] = f2tf(As[GA(s, mrow,     kb + t4 + 4)]);
                a[mi][3] = f2tf(As[GA(s, mrow + 8, kb + t4 + 4)]);
            }
#pragma unroll
            for (int ni = 0; ni < 4; ni++) {
                const int ncol = wc * 32 + ni * 8 + g;
                b[ni][0] = f2tf(Bs[GB(s, kb + t4,     ncol)]);
                b[ni][1] = f2tf(Bs[GB(s, kb + t4 + 4, ncol)]);
            }
#pragma unroll
            for (int mi = 0; mi < 4; mi++)
#pragma unroll
                for (int ni = 0; ni < 4; ni++)
                    mma_tf32(c[mi][ni], a[mi], b[ni]);
        }
    }

#pragma unroll
    for (int mi = 0; mi < 4; mi++) {
#pragma unroll
        for (int ni = 0; ni < 4; ni++) {
            const int row = m0 + wr * 64 + mi * 16 + g;
            const int col = n0 + wc * 32 + ni * 8 + t4 * 2;
            const float b0 = bias[col], b1 = bias[col + 1];
            float v0 = c[mi][ni][0] + b0;
            float v1 = c[mi][ni][1] + b1;
            float v2 = c[mi][ni][2] + b0;
            float v3 = c[mi][ni][3] + b1;
            if (GELU) {
                v0 = 0.5f * v0 * (1.0f + erff(v0 * 0.70710678118654752f));
                v1 = 0.5f * v1 * (1.0f + erff(v1 * 0.70710678118654752f));
                v2 = 0.5f * v2 * (1.0f + erff(v2 * 0.70710678118654752f));
                v3 = 0.5f * v3 * (1.0f + erff(v3 * 0.70710678118654752f));
            }
            *(float2*)&C[(size_t)row * N + col]       = make_float2(v0, v1);
            *(float2*)&C[(size_t)(row + 8) * N + col] = make_float2(v2, v3);
        }
    }
}

template <int GELU>
__global__ void __launch_bounds__(256) gemm_db(
    const float* __restrict__ A, const float* __restrict__ Bm,
    const float* __restrict__ bias, float* __restrict__ C,
    int M, int N, int K)
{
    extern __shared__ float sm[];
    gemm_body<GELU>(A, Bm, bias, C, M, N, K, sm);
}

__global__ void __launch_bounds__(256) qkv_db(
    const float* __restrict__ A,
    const float* __restrict__ W0, const float* __restrict__ W1, const float* __restrict__ W2,
    const float* __restrict__ b0, const float* __restrict__ b1, const float* __restrict__ b2,
    float* __restrict__ o0, float* __restrict__ o1, float* __restrict__ o2)
{
    extern __shared__ float sm[];
    const int z = blockIdx.z;
    const float* W = (z == 0) ? W0 : (z == 1) ? W1 : W2;
    const float* bb = (z == 0) ? b0 : (z == 1) ? b1 : b2;
    float* O = (z == 0) ? o0 : (z == 1) ? o1 : o2;
    gemm_body<0>(A, W, bb, O, NTOK, HID, HID, sm);
}

// ---------------- LayerNorm(x + res) * g + b, float4 ----------------
__global__ void __launch_bounds__(256) ln_residual(
    const float* __restrict__ x, const float* __restrict__ res,
    const float* __restrict__ g, const float* __restrict__ b,
    float* __restrict__ out)
{
    __shared__ float red[8];
    const int row = blockIdx.x;
    const int tid = threadIdx.x;
    const size_t base = (size_t)row * HID + tid * 4;

    float4 xv = *(const float4*)&x[base];
    float4 rv = *(const float4*)&res[base];
    float v0 = xv.x + rv.x, v1 = xv.y + rv.y, v2 = xv.z + rv.z, v3 = xv.w + rv.w;

    float s = v0 + v1 + v2 + v3;
#pragma unroll
    for (int o = 16; o; o >>= 1) s += __shfl_xor_sync(0xffffffffu, s, o);
    if ((tid & 31) == 0) red[tid >> 5] = s;
    __syncthreads();
    if (tid < 8) {
        s = red[tid];
#pragma unroll
        for (int o = 4; o; o >>= 1) s += __shfl_xor_sync(0xffu, s, o, 8);
        if (tid == 0) red[0] = s;
    }
    __syncthreads();
    const float mean = red[0] * (1.0f / HID);
    __syncthreads();

    float d0 = v0 - mean, d1 = v1 - mean, d2 = v2 - mean, d3 = v3 - mean;
    float vs = d0 * d0 + d1 * d1 + d2 * d2 + d3 * d3;
#pragma unroll
    for (int o = 16; o; o >>= 1) vs += __shfl_xor_sync(0xffffffffu, vs, o);
    if ((tid & 31) == 0) red[tid >> 5] = vs;
    __syncthreads();
    if (tid < 8) {
        vs = red[tid];
#pragma unroll
        for (int o = 4; o; o >>= 1) vs += __shfl_xor_sync(0xffu, vs, o, 8);
        if (tid == 0) red[0] = vs;
    }
    __syncthreads();
    const float inv = rsqrtf(red[0] * (1.0f / HID) + 1e-12f);

    float4 gv = *(const float4*)&g[tid * 4];
    float4 bv = *(const float4*)&b[tid * 4];
    float4 ov;
    ov.x = d0 * inv * gv.x + bv.x;
    ov.y = d1 * inv * gv.y + bv.y;
    ov.z = d2 * inv * gv.z + bv.z;
    ov.w = d3 * inv * gv.w + bv.w;
    *(float4*)&out[base] = ov;
}

// ---------------- bf16 tensor-core attention (ldmatrix fragments) ------------
#define HST 72
#define BST 130
#define ATTN_SMEM_BYTES (9216 + 9216 + 18432 + 33280 + 33280 + 9216 + 1024)

__global__ void __launch_bounds__(256, 2) attn_tc(
    const float* __restrict__ Q, const float* __restrict__ K,
    const float* __restrict__ V, const float* __restrict__ dist,
    const float* __restrict__ mask, const float* __restrict__ hm,
    float* __restrict__ ctx)
{
    extern __shared__ char smb[];
    __nv_bfloat16* Qh  = (__nv_bfloat16*)smb;                   // [64][HST]
    __nv_bfloat16* Kh  = Qh + 64 * HST;                         // [64][HST]
    __nv_bfloat16* EVh = Kh + 64 * HST;                         // E:[127][HST] / V:[64][HST] row-major
    float*         B1f = (float*)(EVh + 128 * HST);             // [64][BST]
    float*         B2f = B1f + 64 * BST;                        // [64][BST]
    __nv_bfloat16* Ph  = (__nv_bfloat16*)(B2f + 64 * BST);      // [64][HST]
    float*         Rmax = (float*)(Ph + 64 * HST);              // [2][64]
    float*         Rsum = Rmax + 128;                           // [2][64]

    const int tid = threadIdx.x;
    const int w   = tid >> 5;
    const int wm  = w & 3;
    const int wn  = w >> 2;
    const int l   = tid & 31;
    const int g   = l >> 2;
    const int t4  = l & 3;
    const int bh  = blockIdx.y;
    const int b   = bh >> 4;
    const int h   = bh & 15;
    const int l0  = blockIdx.x * 64;

    const int li0 = 16 * wm + g;
    const int li1 = li0 + 8;

    // ldmatrix per-lane base addresses
    const int arow = 16 * wm + (l & 15);
    const int acol = (l >> 4) << 3;                 // 0 or 8
    const uint32_t aQ = smem_u32(&Qh[arow * HST + acol]);
    const uint32_t aK = smem_u32(&Kh[arow * HST + acol]);
    const uint32_t aP = smem_u32(&Ph[arow * HST + acol]);
    const int brow = l & 7;
    const int bcol = ((l >> 3) & 1) << 3;           // 0 or 8
    const uint32_t bK = smem_u32(&Kh[brow * HST + bcol]);
    const uint32_t bE = smem_u32(&EVh[brow * HST + bcol]);
    const uint32_t bV = smem_u32(&EVh[(l & 15) * HST]);

    const float* Qg = Q + (size_t)(b * SEQ) * HID + h * HD;
    const float* Kg = K + (size_t)(b * SEQ) * HID + h * HD;
    const float* Vg = V + (size_t)(b * SEQ) * HID + h * HD;
    const float* mg = mask + b * SEQ;

    for (int idx = tid; idx < 64 * 16; idx += 256) {
        int r = idx >> 4, c4 = (idx & 15) << 2;
        float4 v = *(const float4*)&Qg[(size_t)(l0 + r) * HID + c4];
        *(uint2*)&Qh[r * HST + c4] =
            make_uint2(pack_bf2(v.x, v.y), pack_bf2(v.z, v.w));
    }

    float O[4][4];
#pragma unroll
    for (int ni = 0; ni < 4; ni++)
#pragma unroll
        for (int r = 0; r < 4; r++) O[ni][r] = 0.f;
    float mrow[2] = {-1e30f, -1e30f};
    float lrow[2] = {0.f, 0.f};

    for (int rt = 0; rt < 16; rt++) {
        const int r0 = rt * 64;
        __syncthreads();   // prev PV done

        for (int idx = tid; idx < 64 * 16; idx += 256) {
            int r = idx >> 4, c4 = (idx & 15) << 2;
            float4 v = *(const float4*)&Kg[(size_t)(r0 + r) * HID + c4];
            *(uint2*)&Kh[r * HST + c4] =
                make_uint2(pack_bf2(v.x, v.y), pack_bf2(v.z, v.w));
        }
        const int dbase = l0 - r0 + 960;
        for (int idx = tid; idx < 127 * 16; idx += 256) {
            int r = idx >> 4, c4 = (idx & 15) << 2;
            float4 v = *(const float4*)&dist[(size_t)(dbase + r) * HD + c4];
            *(uint2*)&EVh[r * HST + c4] =
                make_uint2(pack_bf2(v.x, v.y), pack_bf2(v.z, v.w));
        }
        __syncthreads();

        // ---- B2 = K@E^T, B1 = Q@E^T (warp n-half of 128 cols)
        uint32_t a[4][4];
#pragma unroll
        for (int mat = 0; mat < 2; mat++) {
            const uint32_t aBase = mat ? aQ : aK;
            float* Dst = mat ? B1f : B2f;
#pragma unroll
            for (int kk = 0; kk < 4; kk++) ldsm_x4(a[kk], aBase + kk * 32);
            float c[8][4];
#pragma unroll
            for (int ni = 0; ni < 8; ni++)
#pragma unroll
                for (int r = 0; r < 4; r++) c[ni][r] = 0.f;
#pragma unroll
            for (int kk = 0; kk < 4; kk++) {
#pragma unroll
                for (int ni = 0; ni < 8; ni++) {
                    const int ncol = wn * 64 + ni * 8;
                    uint32_t bf[2];
                    ldsm_x2(bf, bE + (ncol * HST) * 2 + kk * 32);
                    mma_bf16(c[ni], a[kk], bf);
                }
            }
#pragma unroll
            for (int ni = 0; ni < 8; ni++) {
                const int col = wn * 64 + ni * 8 + 2 * t4;
                *(float2*)&Dst[li0 * BST + col] = make_float2(c[ni][0], c[ni][1]);
                *(float2*)&Dst[li1 * BST + col] = make_float2(c[ni][2], c[ni][3]);
            }
        }

        // ---- S = Q@K^T (a holds Q frags), warp cols [wn*32, wn*32+32)
        float cS[4][4];
#pragma unroll
        for (int ni = 0; ni < 4; ni++)
#pragma unroll
            for (int r = 0; r < 4; r++) cS[ni][r] = 0.f;
#pragma unroll
        for (int kk = 0; kk < 4; kk++) {
#pragma unroll
            for (int ni = 0; ni < 4; ni++) {
                const int ncol = wn * 32 + ni * 8;
                uint32_t bf[2];
                ldsm_x2(bf, bK + (ncol * HST) * 2 + kk * 32);
                mma_bf16(cS[ni], a[kk], bf);
            }
        }
        __syncthreads();   // B1/B2 written; E reads done

        // ---- V load (row-major into EV region)
        for (int idx = tid; idx < 64 * 16; idx += 256) {
            int r = idx >> 4, c4 = (idx & 15) << 2;
            float4 v = *(const float4*)&Vg[(size_t)(r0 + r) * HID + c4];
            *(uint2*)&EVh[r * HST + c4] =
                make_uint2(pack_bf2(v.x, v.y), pack_bf2(v.z, v.w));
        }

        // ---- bias gather + scale + mask
        float vmax0 = -1e30f, vmax1 = -1e30f;
#pragma unroll
        for (int ni = 0; ni < 4; ni++) {
#pragma unroll
            for (int e = 0; e < 2; e++) {
                const int rj = wn * 32 + ni * 8 + 2 * t4 + e;
                const float mv = mg[r0 + rj];
                const int ib0 = li0 - rj + 63;
                const int ib1 = li1 - rj + 63;
                float v0 = (cS[ni][e]     + B1f[li0 * BST + ib0] + B2f[rj * BST + ib0]) * 0.125f + mv;
                float v1 = (cS[ni][2 + e] + B1f[li1 * BST + ib1] + B2f[rj * BST + ib1]) * 0.125f + mv;
                cS[ni][e]     = v0;
                cS[ni][2 + e] = v1;
                vmax0 = fmaxf(vmax0, v0);
                vmax1 = fmaxf(vmax1, v1);
            }
        }
        vmax0 = fmaxf(vmax0, __shfl_xor_sync(0xffffffffu, vmax0, 1));
        vmax0 = fmaxf(vmax0, __shfl_xor_sync(0xffffffffu, vmax0, 2));
        vmax1 = fmaxf(vmax1, __shfl_xor_sync(0xffffffffu, vmax1, 1));
        vmax1 = fmaxf(vmax1, __shfl_xor_sync(0xffffffffu, vmax1, 2));
        if (t4 == 0) {
            Rmax[wn * 64 + li0] = vmax0;
            Rmax[wn * 64 + li1] = vmax1;
        }
        __syncthreads();
        vmax0 = fmaxf(vmax0, Rmax[(wn ^ 1) * 64 + li0]);
        vmax1 = fmaxf(vmax1, Rmax[(wn ^ 1) * 64 + li1]);

        const float nm0 = fmaxf(mrow[0], vmax0);
        const float nm1 = fmaxf(mrow[1], vmax1);
        const float corr0 = __expf(mrow[0] - nm0);
        const float corr1 = __expf(mrow[1] - nm1);

        float ts0 = 0.f, ts1 = 0.f;
#pragma unroll
        for (int ni = 0; ni < 4; ni++) {
            const int cj = wn * 32 + ni * 8 + 2 * t4;
            float p00 = __expf(cS[ni][0] - nm0);
            float p01 = __expf(cS[ni][1] - nm0);
            float p10 = __expf(cS[ni][2] - nm1);
            float p11 = __expf(cS[ni][3] - nm1);
            *(uint32_t*)&Ph[li0 * HST + cj] = pack_bf2(p00, p01);
            *(uint32_t*)&Ph[li1 * HST + cj] = pack_bf2(p10, p11);
            ts0 += p00 + p01;
            ts1 += p10 + p11;
        }
        ts0 += __shfl_xor_sync(0xffffffffu, ts0, 1);
        ts0 += __shfl_xor_sync(0xffffffffu, ts0, 2);
        ts1 += __shfl_xor_sync(0xffffffffu, ts1, 1);
        ts1 += __shfl_xor_sync(0xffffffffu, ts1, 2);
        if (t4 == 0) {
            Rsum[wn * 64 + li0] = ts0;
            Rsum[wn * 64 + li1] = ts1;
        }
        __syncthreads();   // Rsum, P, V visible
        ts0 += Rsum[(wn ^ 1) * 64 + li0];
        ts1 += Rsum[(wn ^ 1) * 64 + li1];

        lrow[0] = lrow[0] * corr0 + ts0;
        lrow[1] = lrow[1] * corr1 + ts1;
        mrow[0] = nm0;
        mrow[1] = nm1;
#pragma unroll
        for (int ni = 0; ni < 4; ni++) {
            O[ni][0] *= corr0;
            O[ni][1] *= corr0;
            O[ni][2] *= corr1;
            O[ni][3] *= corr1;
        }

        // ---- PV: O += P@V, A from Ph (x4), B from row-major V (x2.trans)
#pragma unroll
        for (int kk = 0; kk < 4; kk++) {
            const int kb = kk * 16;
            uint32_t ap[4];
            ldsm_x4(ap, aP + kk * 32);
#pragma unroll
            for (int ni = 0; ni < 4; ni++) {
                const int nbase = wn * 32 + ni * 8;
                uint32_t bf[2];
                ldsm_x2t(bf, bV + (kb * HST + nbase) * 2);
                mma_bf16(O[ni], ap, bf);
            }
        }
    }

    const float hscale = hm[h];
    const float inv0 = hscale / lrow[0];
    const float inv1 = hscale / lrow[1];
#pragma unroll
    for (int ni = 0; ni < 4; ni++) {
        const int col = h * HD + wn * 32 + ni * 8 + 2 * t4;
        const size_t row0g = (size_t)(b * SEQ + l0 + li0) * HID + col;
        const size_t row1g = (size_t)(b * SEQ + l0 + li1) * HID + col;
        *(float2*)&ctx[row0g] = make_float2(O[ni][0] * inv0, O[ni][1] * inv0);
        *(float2*)&ctx[row1g] = make_float2(O[ni][2] * inv1, O[ni][3] * inv1);
    }
}

// ---------------- launch ----------------
extern "C" void kernel_launch(void* const* d_in, const int* in_sizes, int n_in,
                              void* d_out, int out_size)
{
    const float* hs   = (const float*)d_in[0];
    const float* mask = (const float*)d_in[1];
    const float* hm   = (const float*)d_in[2];
    const float* Wq   = (const float*)d_in[3];
    const float* bq   = (const float*)d_in[4];
    const float* Wk   = (const float*)d_in[5];
    const float* bk   = (const float*)d_in[6];
    const float* Wv   = (const float*)d_in[7];
    const float* bv   = (const float*)d_in[8];
    const float* dist = (const float*)d_in[9];
    const float* Wo   = (const float*)d_in[10];
    const float* bo   = (const float*)d_in[11];
    const float* ln1g = (const float*)d_in[12];
    const float* ln1b = (const float*)d_in[13];
    const float* Wi   = (const float*)d_in[14];
    const float* bi   = (const float*)d_in[15];
    const float* Wo2  = (const float*)d_in[16];
    const float* bo2  = (const float*)d_in[17];
    const float* ln2g = (const float*)d_in[18];
    const float* ln2b = (const float*)d_in[19];
    float* out = (float*)d_out;

    float *q, *k, *v, *ctx, *tmp, *attnout, *inter;
    cudaGetSymbolAddress((void**)&q,       g_q);
    cudaGetSymbolAddress((void**)&k,       g_k);
    cudaGetSymbolAddress((void**)&v,       g_v);
    cudaGetSymbolAddress((void**)&ctx,     g_ctx);
    cudaGetSymbolAddress((void**)&tmp,     g_tmp);
    cudaGetSymbolAddress((void**)&attnout, g_attnout);
    cudaGetSymbolAddress((void**)&inter,   g_inter);

    cudaFuncSetAttribute(attn_tc, cudaFuncAttributeMaxDynamicSharedMemorySize,
                         ATTN_SMEM_BYTES);
    cudaFuncSetAttribute(gemm_db<0>, cudaFuncAttributeMaxDynamicSharedMemorySize,
                         GEMM_SMEM_BYTES);
    cudaFuncSetAttribute(gemm_db<1>, cudaFuncAttributeMaxDynamicSharedMemorySize,
                         GEMM_SMEM_BYTES);
    cudaFuncSetAttribute(qkv_db, cudaFuncAttributeMaxDynamicSharedMemorySize,
                         GEMM_SMEM_BYTES);

    dim3 blk(256);
    dim3 g_qkv(HID / 128, NTOK / 128, 3);
    dim3 g_1024(HID / 128, NTOK / 128);
    dim3 g_ff1(FFDIM / 128, NTOK / 128);

    qkv_db<<<g_qkv, blk, GEMM_SMEM_BYTES>>>(hs, Wq, Wk, Wv, bq, bk, bv, q, k, v);

    attn_tc<<<dim3(SEQ / 64, BATCH * NHEAD), blk, ATTN_SMEM_BYTES>>>(
        q, k, v, dist, mask, hm, ctx);

    gemm_db<0><<<g_1024, blk, GEMM_SMEM_BYTES>>>(ctx, Wo, bo, tmp, NTOK, HID, HID);
    ln_residual<<<NTOK, blk>>>(tmp, hs, ln1g, ln1b, attnout);

    gemm_db<1><<<g_ff1, blk, GEMM_SMEM_BYTES>>>(attnout, Wi, bi, inter, NTOK, FFDIM, HID);
    gemm_db<0><<<g_1024, blk, GEMM_SMEM_BYTES>>>(inter, Wo2, bo2, tmp, NTOK, HID, FFDIM);
    ln_residual<<<NTOK, blk>>>(tmp, attnout, ln2g, ln2b, out);
}

// round 8
// speedup vs baseline: 3.7569x; 1.2580x over previous
#include <cuda_runtime.h>
#include <cuda_bf16.h>
#include <math.h>
#include <stdint.h>

#define HID    1024
#define FFDIM  4096
#define NHEAD  16
#define HD     64
#define BATCH  4
#define SEQ    1024
#define NTOK   (BATCH*SEQ)
#define MAXPOS 1024

// ---------------- scratch ----------------
__device__ float g_q[NTOK * HID];
__device__ float g_k[NTOK * HID];
__device__ float g_v[NTOK * HID];
__device__ float g_ctx[NTOK * HID];
__device__ float g_tmp[NTOK * HID];
__device__ float g_attnout[NTOK * HID];
__device__ float g_attnout_tf[NTOK * HID];
__device__ float g_inter[NTOK * FFDIM];
__device__ float g_hs_tf[NTOK * HID];
__device__ float g_wq[HID * HID];
__device__ float g_wk[HID * HID];
__device__ float g_wv[HID * HID];
__device__ float g_wo[HID * HID];
__device__ float g_wi[HID * FFDIM];
__device__ float g_wo2[FFDIM * HID];

// ---------------- helpers ----------------
__device__ __forceinline__ uint32_t f2tf(float f) {
    uint32_t u;
    asm("cvt.rna.tf32.f32 %0, %1;" : "=r"(u) : "f"(f));
    return u;
}

__device__ __forceinline__ uint32_t pack_bf2(float x, float y) {
    __nv_bfloat162 h = __floats2bfloat162_rn(x, y);
    return *(uint32_t*)&h;
}

__device__ __forceinline__ uint32_t smem_u32(const void* p) {
    return (uint32_t)__cvta_generic_to_shared(p);
}

__device__ __forceinline__ void mma_tf32(float c[4], const uint32_t a[4],
                                         const uint32_t b[2]) {
    asm volatile(
        "mma.sync.aligned.m16n8k8.row.col.f32.tf32.tf32.f32 "
        "{%0,%1,%2,%3}, {%4,%5,%6,%7}, {%8,%9}, {%0,%1,%2,%3};"
        : "+f"(c[0]), "+f"(c[1]), "+f"(c[2]), "+f"(c[3])
        : "r"(a[0]), "r"(a[1]), "r"(a[2]), "r"(a[3]), "r"(b[0]), "r"(b[1]));
}

__device__ __forceinline__ void mma_bf16(float c[4], const uint32_t a[4],
                                         const uint32_t b[2]) {
    asm volatile(
        "mma.sync.aligned.m16n8k16.row.col.f32.bf16.bf16.f32 "
        "{%0,%1,%2,%3}, {%4,%5,%6,%7}, {%8,%9}, {%0,%1,%2,%3};"
        : "+f"(c[0]), "+f"(c[1]), "+f"(c[2]), "+f"(c[3])
        : "r"(a[0]), "r"(a[1]), "r"(a[2]), "r"(a[3]), "r"(b[0]), "r"(b[1]));
}

__device__ __forceinline__ void ldsm_x4(uint32_t* r, uint32_t a) {
    asm volatile("ldmatrix.sync.aligned.m8n8.x4.shared.b16 {%0,%1,%2,%3}, [%4];"
        : "=r"(r[0]), "=r"(r[1]), "=r"(r[2]), "=r"(r[3]) : "r"(a));
}
__device__ __forceinline__ void ldsm_x2(uint32_t* r, uint32_t a) {
    asm volatile("ldmatrix.sync.aligned.m8n8.x2.shared.b16 {%0,%1}, [%2];"
        : "=r"(r[0]), "=r"(r[1]) : "r"(a));
}
__device__ __forceinline__ void ldsm_x2t(uint32_t* r, uint32_t a) {
    asm volatile("ldmatrix.sync.aligned.m8n8.x2.trans.shared.b16 {%0,%1}, [%2];"
        : "=r"(r[0]), "=r"(r[1]) : "r"(a));
}

__device__ __forceinline__ void cp16(float* smem, const float* gmem) {
    uint32_t s = (uint32_t)__cvta_generic_to_shared(smem);
    asm volatile("cp.async.cg.shared.global [%0], [%1], 16;" :: "r"(s), "l"(gmem));
}
#define CP_COMMIT() asm volatile("cp.async.commit_group;")
#define CP_WAIT0()  asm volatile("cp.async.wait_group 0;")

// ---------------- tf32 rounding kernel (fp32 -> tf32-representable fp32) -----
__global__ void __launch_bounds__(256) tf32_round_k(
    const float* __restrict__ in, float* __restrict__ out, int n4)
{
    int i = blockIdx.x * blockDim.x + threadIdx.x;
    if (i < n4) {
        float4 v = ((const float4*)in)[i];
        v.x = __uint_as_float(f2tf(v.x));
        v.y = __uint_as_float(f2tf(v.y));
        v.z = __uint_as_float(f2tf(v.z));
        v.w = __uint_as_float(f2tf(v.w));
        ((float4*)out)[i] = v;
    }
}

// ---------------- double-buffered tf32 GEMM (operands pre-rounded) -----------
#define GA(s,r,c) ((( (s)*128 + (r) )*36) + (c))
#define GB(s,r,c) ((( (s)*32  + (r) )*136) + (c))
#define GEMM_SMEM_BYTES ((2*128*36 + 2*32*136) * 4)

template <int GELU, int ROUND>
__device__ __forceinline__ void gemm_body(
    const float* __restrict__ A, const float* __restrict__ Bm,
    const float* __restrict__ bias, float* __restrict__ C,
    int M, int N, int K, float* sm)
{
    float* As = sm;
    float* Bs = sm + 2 * 128 * 36;

    const int tid = threadIdx.x;
    const int w   = tid >> 5;
    const int l   = tid & 31;
    const int wr  = w >> 2;
    const int wc  = w & 3;
    const int m0  = blockIdx.y * 128;
    const int n0  = blockIdx.x * 128;
    const int g   = l >> 2;
    const int t4  = l & 3;

    const int ar = tid >> 3;
    const int ac = (tid & 7) << 2;
    const int br = tid >> 5;
    const int bc = (tid & 31) << 2;

    float c[4][4][4];
#pragma unroll
    for (int mi = 0; mi < 4; mi++)
#pragma unroll
        for (int ni = 0; ni < 4; ni++)
#pragma unroll
            for (int r = 0; r < 4; r++) c[mi][ni][r] = 0.f;

#pragma unroll
    for (int i = 0; i < 4; i++)
        cp16(&As[GA(0, ar + 32 * i, ac)], &A[(size_t)(m0 + ar + 32 * i) * K + ac]);
#pragma unroll
    for (int i = 0; i < 4; i++)
        cp16(&Bs[GB(0, br + 8 * i, bc)], &Bm[(size_t)(br + 8 * i) * N + n0 + bc]);
    CP_COMMIT();

    for (int k0 = 0; k0 < K; k0 += 32) {
        const int s = (k0 >> 5) & 1;
        CP_WAIT0();
        __syncthreads();
        if (k0 + 32 < K) {
            const int ns = s ^ 1;
            const int nk = k0 + 32;
#pragma unroll
            for (int i = 0; i < 4; i++)
                cp16(&As[GA(ns, ar + 32 * i, ac)],
                     &A[(size_t)(m0 + ar + 32 * i) * K + nk + ac]);
#pragma unroll
            for (int i = 0; i < 4; i++)
                cp16(&Bs[GB(ns, br + 8 * i, bc)],
                     &Bm[(size_t)(nk + br + 8 * i) * N + n0 + bc]);
            CP_COMMIT();
        }

#pragma unroll
        for (int kk = 0; kk < 4; kk++) {
            const int kb = kk * 8;
            uint32_t a[4][4], b[4][2];
#pragma unroll
            for (int mi = 0; mi < 4; mi++) {
                const int mrow = wr * 64 + mi * 16 + g;
                a[mi][0] = __float_as_uint(As[GA(s, mrow,     kb + t4)]);
                a[mi][1] = __float_as_uint(As[GA(s, mrow + 8, kb + t4)]);
                a[mi][2] = __float_as_uint(As[GA(s, mrow,     kb + t4 + 4)]);
                a[mi][3] = __float_as_uint(As[GA(s, mrow + 8, kb + t4 + 4)]);
            }
#pragma unroll
            for (int ni = 0; ni < 4; ni++) {
                const int ncol = wc * 32 + ni * 8 + g;
                b[ni][0] = __float_as_uint(Bs[GB(s, kb + t4,     ncol)]);
                b[ni][1] = __float_as_uint(Bs[GB(s, kb + t4 + 4, ncol)]);
            }
#pragma unroll
            for (int mi = 0; mi < 4; mi++)
#pragma unroll
                for (int ni = 0; ni < 4; ni++)
                    mma_tf32(c[mi][ni], a[mi], b[ni]);
        }
    }

#pragma unroll
    for (int mi = 0; mi < 4; mi++) {
#pragma unroll
        for (int ni = 0; ni < 4; ni++) {
            const int row = m0 + wr * 64 + mi * 16 + g;
            const int col = n0 + wc * 32 + ni * 8 + t4 * 2;
            const float b0 = bias[col], b1 = bias[col + 1];
            float v0 = c[mi][ni][0] + b0;
            float v1 = c[mi][ni][1] + b1;
            float v2 = c[mi][ni][2] + b0;
            float v3 = c[mi][ni][3] + b1;
            if (GELU) {
                v0 = 0.5f * v0 * (1.0f + erff(v0 * 0.70710678118654752f));
                v1 = 0.5f * v1 * (1.0f + erff(v1 * 0.70710678118654752f));
                v2 = 0.5f * v2 * (1.0f + erff(v2 * 0.70710678118654752f));
                v3 = 0.5f * v3 * (1.0f + erff(v3 * 0.70710678118654752f));
            }
            if (ROUND) {
                v0 = __uint_as_float(f2tf(v0));
                v1 = __uint_as_float(f2tf(v1));
                v2 = __uint_as_float(f2tf(v2));
                v3 = __uint_as_float(f2tf(v3));
            }
            *(float2*)&C[(size_t)row * N + col]       = make_float2(v0, v1);
            *(float2*)&C[(size_t)(row + 8) * N + col] = make_float2(v2, v3);
        }
    }
}

template <int GELU, int ROUND>
__global__ void __launch_bounds__(256) gemm_db(
    const float* __restrict__ A, const float* __restrict__ Bm,
    const float* __restrict__ bias, float* __restrict__ C,
    int M, int N, int K)
{
    extern __shared__ float sm[];
    gemm_body<GELU, ROUND>(A, Bm, bias, C, M, N, K, sm);
}

__global__ void __launch_bounds__(256) qkv_db(
    const float* __restrict__ A,
    const float* __restrict__ W0, const float* __restrict__ W1, const float* __restrict__ W2,
    const float* __restrict__ b0, const float* __restrict__ b1, const float* __restrict__ b2,
    float* __restrict__ o0, float* __restrict__ o1, float* __restrict__ o2)
{
    extern __shared__ float sm[];
    const int z = blockIdx.z;
    const float* W = (z == 0) ? W0 : (z == 1) ? W1 : W2;
    const float* bb = (z == 0) ? b0 : (z == 1) ? b1 : b2;
    float* O = (z == 0) ? o0 : (z == 1) ? o1 : o2;
    gemm_body<0, 0>(A, W, bb, O, NTOK, HID, HID, sm);
}

// ---------------- LayerNorm(x + res) * g + b, float4, optional tf copy -------
__global__ void __launch_bounds__(256) ln_residual(
    const float* __restrict__ x, const float* __restrict__ res,
    const float* __restrict__ g, const float* __restrict__ b,
    float* __restrict__ out, float* __restrict__ out_tf)
{
    __shared__ float red[8];
    const int row = blockIdx.x;
    const int tid = threadIdx.x;
    const size_t base = (size_t)row * HID + tid * 4;

    float4 xv = *(const float4*)&x[base];
    float4 rv = *(const float4*)&res[base];
    float v0 = xv.x + rv.x, v1 = xv.y + rv.y, v2 = xv.z + rv.z, v3 = xv.w + rv.w;

    float s = v0 + v1 + v2 + v3;
#pragma unroll
    for (int o = 16; o; o >>= 1) s += __shfl_xor_sync(0xffffffffu, s, o);
    if ((tid & 31) == 0) red[tid >> 5] = s;
    __syncthreads();
    if (tid < 8) {
        s = red[tid];
#pragma unroll
        for (int o = 4; o; o >>= 1) s += __shfl_xor_sync(0xffu, s, o, 8);
        if (tid == 0) red[0] = s;
    }
    __syncthreads();
    const float mean = red[0] * (1.0f / HID);
    __syncthreads();

    float d0 = v0 - mean, d1 = v1 - mean, d2 = v2 - mean, d3 = v3 - mean;
    float vs = d0 * d0 + d1 * d1 + d2 * d2 + d3 * d3;
#pragma unroll
    for (int o = 16; o; o >>= 1) vs += __shfl_xor_sync(0xffffffffu, vs, o);
    if ((tid & 31) == 0) red[tid >> 5] = vs;
    __syncthreads();
    if (tid < 8) {
        vs = red[tid];
#pragma unroll
        for (int o = 4; o; o >>= 1) vs += __shfl_xor_sync(0xffu, vs, o, 8);
        if (tid == 0) red[0] = vs;
    }
    __syncthreads();
    const float inv = rsqrtf(red[0] * (1.0f / HID) + 1e-12f);

    float4 gv = *(const float4*)&g[tid * 4];
    float4 bv = *(const float4*)&b[tid * 4];
    float4 ov;
    ov.x = d0 * inv * gv.x + bv.x;
    ov.y = d1 * inv * gv.y + bv.y;
    ov.z = d2 * inv * gv.z + bv.z;
    ov.w = d3 * inv * gv.w + bv.w;
    *(float4*)&out[base] = ov;
    if (out_tf) {
        float4 tv;
        tv.x = __uint_as_float(f2tf(ov.x));
        tv.y = __uint_as_float(f2tf(ov.y));
        tv.z = __uint_as_float(f2tf(ov.z));
        tv.w = __uint_as_float(f2tf(ov.w));
        *(float4*)&out_tf[base] = tv;
    }
}

// ---------------- bf16 TC attention with B1/E ring buffer --------------------
#define HST 72
#define BSTH 132
#define ATTN_SMEM_BYTES (9216 + 9216 + 18432 + 9216 + 16896 + 16896 + 9216 + 1024)

__global__ void __launch_bounds__(256, 2) attn_tc(
    const float* __restrict__ Q, const float* __restrict__ K,
    const float* __restrict__ V, const float* __restrict__ dist,
    const float* __restrict__ mask, const float* __restrict__ hm,
    float* __restrict__ ctx)
{
    extern __shared__ char smb[];
    __nv_bfloat16* Qh  = (__nv_bfloat16*)smb;                   // [64][HST]
    __nv_bfloat16* Kh  = Qh + 64 * HST;                         // [64][HST]
    __nv_bfloat16* Er  = Kh + 64 * HST;                         // [128][HST] ring
    __nv_bfloat16* Vh  = Er + 128 * HST;                        // [64][HST]
    __nv_bfloat16* B1h = Vh + 64 * HST;                         // [64][BSTH]
    __nv_bfloat16* B2h = B1h + 64 * BSTH;                       // [64][BSTH]
    __nv_bfloat16* Ph  = B2h + 64 * BSTH;                       // [64][HST]
    float*         Rmax = (float*)(Ph + 64 * HST);              // [2][64]
    float*         Rsum = Rmax + 128;                           // [2][64]

    const int tid = threadIdx.x;
    const int w   = tid >> 5;
    const int wm  = w & 3;
    const int wn  = w >> 2;
    const int l   = tid & 31;
    const int g   = l >> 2;
    const int t4  = l & 3;
    const int bh  = blockIdx.y;
    const int b   = bh >> 4;
    const int h   = bh & 15;
    const int l0  = blockIdx.x * 64;

    const int li0 = 16 * wm + g;
    const int li1 = li0 + 8;

    const int arow = 16 * wm + (l & 15);
    const int acol = (l >> 4) << 3;
    const uint32_t aQ = smem_u32(&Qh[arow * HST + acol]);
    const uint32_t aK = smem_u32(&Kh[arow * HST + acol]);
    const uint32_t aP = smem_u32(&Ph[arow * HST + acol]);
    const int brow = l & 7;
    const int bcol = ((l >> 3) & 1) << 3;
    const uint32_t bK = smem_u32(&Kh[brow * HST + bcol]);
    const uint32_t bEbase = smem_u32(Er) + bcol * 2;
    const uint32_t bV = smem_u32(&Vh[(l & 15) * HST]);

    const float* Qg = Q + (size_t)(b * SEQ) * HID + h * HD;
    const float* Kg = K + (size_t)(b * SEQ) * HID + h * HD;
    const float* Vg = V + (size_t)(b * SEQ) * HID + h * HD;
    const float* mg = mask + b * SEQ;

    for (int idx = tid; idx < 64 * 16; idx += 256) {
        int r = idx >> 4, c4 = (idx & 15) << 2;
        float4 v = *(const float4*)&Qg[(size_t)(l0 + r) * HID + c4];
        *(uint2*)&Qh[r * HST + c4] =
            make_uint2(pack_bf2(v.x, v.y), pack_bf2(v.z, v.w));
    }
    __syncthreads();

    uint32_t aq[4][4];
#pragma unroll
    for (int kk = 0; kk < 4; kk++) ldsm_x4(aq[kk], aQ + kk * 32);

    float O[4][4];
#pragma unroll
    for (int ni = 0; ni < 4; ni++)
#pragma unroll
        for (int r = 0; r < 4; r++) O[ni][r] = 0.f;
    float mrow[2] = {-1e30f, -1e30f};
    float lrow[2] = {0.f, 0.f};

    for (int rt = 0; rt < 16; rt++) {
        const int r0 = rt * 64;
        const int dbase = l0 - r0 + 960;
        __syncthreads();

        for (int idx = tid; idx < 64 * 16; idx += 256) {
            int r = idx >> 4, c4 = (idx & 15) << 2;
            float4 kv = *(const float4*)&Kg[(size_t)(r0 + r) * HID + c4];
            *(uint2*)&Kh[r * HST + c4] =
                make_uint2(pack_bf2(kv.x, kv.y), pack_bf2(kv.z, kv.w));
            float4 vv = *(const float4*)&Vg[(size_t)(r0 + r) * HID + c4];
            *(uint2*)&Vh[r * HST + c4] =
                make_uint2(pack_bf2(vv.x, vv.y), pack_bf2(vv.z, vv.w));
        }
        const int nerows = (rt == 0) ? 128 : 64;
        for (int idx = tid; idx < nerows * 16; idx += 256) {
            int r = idx >> 4, c4 = (idx & 15) << 2;
            int row = dbase + r;
            int rowc = row > 2046 ? 2046 : row;
            int slot = row & 127;
            float4 v = *(const float4*)&dist[(size_t)rowc * HD + c4];
            *(uint2*)&Er[slot * HST + c4] =
                make_uint2(pack_bf2(v.x, v.y), pack_bf2(v.z, v.w));
        }
        __syncthreads();

        uint32_t ak[4][4];
#pragma unroll
        for (int kk = 0; kk < 4; kk++) ldsm_x4(ak[kk], aK + kk * 32);

        // ---- B2 = K @ E_window^T : 128 cols (warp n-half = 64), 2 passes
#pragma unroll
        for (int p = 0; p < 2; p++) {
            float c[4][4];
#pragma unroll
            for (int ni = 0; ni < 4; ni++)
#pragma unroll
                for (int r = 0; r < 4; r++) c[ni][r] = 0.f;
#pragma unroll
            for (int kk = 0; kk < 4; kk++) {
#pragma unroll
                for (int ni = 0; ni < 4; ni++) {
                    const int j = wn * 64 + p * 32 + ni * 8;
                    const int slot = (dbase + j + brow) & 127;
                    uint32_t bf[2];
                    ldsm_x2(bf, bEbase + slot * (HST * 2) + kk * 32);
                    mma_bf16(c[ni], ak[kk], bf);
                }
            }
#pragma unroll
            for (int ni = 0; ni < 4; ni++) {
                const int col = wn * 64 + p * 32 + ni * 8 + 2 * t4;
                *(uint32_t*)&B2h[li0 * BSTH + col] = pack_bf2(c[ni][0], c[ni][1]);
                *(uint32_t*)&B2h[li1 * BSTH + col] = pack_bf2(c[ni][2], c[ni][3]);
            }
        }

        // ---- B1 new block(s): Q @ E_new^T into ring slots
        const int nblk = (rt == 0) ? 2 : 1;
        for (int blk = 0; blk < nblk; blk++) {
            const int base = (dbase + 64 * blk) & 127;
            float c[4][4];
#pragma unroll
            for (int ni = 0; ni < 4; ni++)
#pragma unroll
                for (int r = 0; r < 4; r++) c[ni][r] = 0.f;
#pragma unroll
            for (int kk = 0; kk < 4; kk++) {
#pragma unroll
                for (int ni = 0; ni < 4; ni++) {
                    const int slot = base + wn * 32 + ni * 8 + brow;
                    uint32_t bf[2];
                    ldsm_x2(bf, bEbase + slot * (HST * 2) + kk * 32);
                    mma_bf16(c[ni], aq[kk], bf);
                }
            }
#pragma unroll
            for (int ni = 0; ni < 4; ni++) {
                const int col = base + wn * 32 + ni * 8 + 2 * t4;
                *(uint32_t*)&B1h[li0 * BSTH + col] = pack_bf2(c[ni][0], c[ni][1]);
                *(uint32_t*)&B1h[li1 * BSTH + col] = pack_bf2(c[ni][2], c[ni][3]);
            }
        }

        // ---- S = Q @ K^T : A operand = Q fragments (aq) -- R7 bug was ak here
        float cS[4][4];
#pragma unroll
        for (int ni = 0; ni < 4; ni++)
#pragma unroll
            for (int r = 0; r < 4; r++) cS[ni][r] = 0.f;
#pragma unroll
        for (int kk = 0; kk < 4; kk++) {
#pragma unroll
            for (int ni = 0; ni < 4; ni++) {
                const int ncol = wn * 32 + ni * 8;
                uint32_t bf[2];
                ldsm_x2(bf, bK + (ncol * HST) * 2 + kk * 32);
                mma_bf16(cS[ni], aq[kk], bf);
            }
        }
        __syncthreads();

        // ---- bias gather + scale + mask
        const int dofs = dbase + 63;
        float vmax0 = -1e30f, vmax1 = -1e30f;
#pragma unroll
        for (int ni = 0; ni < 4; ni++) {
#pragma unroll
            for (int e = 0; e < 2; e++) {
                const int rj = wn * 32 + ni * 8 + 2 * t4 + e;
                const float mv = mg[r0 + rj];
                const int s0 = (dofs + li0 - rj) & 127;
                const int s1 = (dofs + li1 - rj) & 127;
                const int ib0 = li0 - rj + 63;
                const int ib1 = li1 - rj + 63;
                float b1a = __bfloat162float(B1h[li0 * BSTH + s0]);
                float b1b = __bfloat162float(B1h[li1 * BSTH + s1]);
                float b2a = __bfloat162float(B2h[rj * BSTH + ib0]);
                float b2b = __bfloat162float(B2h[rj * BSTH + ib1]);
                float v0 = (cS[ni][e]     + b1a + b2a) * 0.125f + mv;
                float v1 = (cS[ni][2 + e] + b1b + b2b) * 0.125f + mv;
                cS[ni][e]     = v0;
                cS[ni][2 + e] = v1;
                vmax0 = fmaxf(vmax0, v0);
                vmax1 = fmaxf(vmax1, v1);
            }
        }
        vmax0 = fmaxf(vmax0, __shfl_xor_sync(0xffffffffu, vmax0, 1));
        vmax0 = fmaxf(vmax0, __shfl_xor_sync(0xffffffffu, vmax0, 2));
        vmax1 = fmaxf(vmax1, __shfl_xor_sync(0xffffffffu, vmax1, 1));
        vmax1 = fmaxf(vmax1, __shfl_xor_sync(0xffffffffu, vmax1, 2));
        if (t4 == 0) {
            Rmax[wn * 64 + li0] = vmax0;
            Rmax[wn * 64 + li1] = vmax1;
        }
        __syncthreads();
        vmax0 = fmaxf(vmax0, Rmax[(wn ^ 1) * 64 + li0]);
        vmax1 = fmaxf(vmax1, Rmax[(wn ^ 1) * 64 + li1]);

        const float nm0 = fmaxf(mrow[0], vmax0);
        const float nm1 = fmaxf(mrow[1], vmax1);
        const float corr0 = __expf(mrow[0] - nm0);
        const float corr1 = __expf(mrow[1] - nm1);

        float ts0 = 0.f, ts1 = 0.f;
#pragma unroll
        for (int ni = 0; ni < 4; ni++) {
            const int cj = wn * 32 + ni * 8 + 2 * t4;
            float p00 = __expf(cS[ni][0] - nm0);
            float p01 = __expf(cS[ni][1] - nm0);
            float p10 = __expf(cS[ni][2] - nm1);
            float p11 = __expf(cS[ni][3] - nm1);
            *(uint32_t*)&Ph[li0 * HST + cj] = pack_bf2(p00, p01);
            *(uint32_t*)&Ph[li1 * HST + cj] = pack_bf2(p10, p11);
            ts0 += p00 + p01;
            ts1 += p10 + p11;
        }
        ts0 += __shfl_xor_sync(0xffffffffu, ts0, 1);
        ts0 += __shfl_xor_sync(0xffffffffu, ts0, 2);
        ts1 += __shfl_xor_sync(0xffffffffu, ts1, 1);
        ts1 += __shfl_xor_sync(0xffffffffu, ts1, 2);
        if (t4 == 0) {
            Rsum[wn * 64 + li0] = ts0;
            Rsum[wn * 64 + li1] = ts1;
        }
        __syncthreads();
        ts0 += Rsum[(wn ^ 1) * 64 + li0];
        ts1 += Rsum[(wn ^ 1) * 64 + li1];

        lrow[0] = lrow[0] * corr0 + ts0;
        lrow[1] = lrow[1] * corr1 + ts1;
        mrow[0] = nm0;
        mrow[1] = nm1;
#pragma unroll
        for (int ni = 0; ni < 4; ni++) {
            O[ni][0] *= corr0;
            O[ni][1] *= corr0;
            O[ni][2] *= corr1;
            O[ni][3] *= corr1;
        }

        // ---- PV: O += P @ V
#pragma unroll
        for (int kk = 0; kk < 4; kk++) {
            const int kb = kk * 16;
            uint32_t ap[4];
            ldsm_x4(ap, aP + kk * 32);
#pragma unroll
            for (int ni = 0; ni < 4; ni++) {
                const int nbase = wn * 32 + ni * 8;
                uint32_t bf[2];
                ldsm_x2t(bf, bV + (kb * HST + nbase) * 2);
                mma_bf16(O[ni], ap, bf);
            }
        }
    }

    const float hscale = hm[h];
    const float inv0 = hscale / lrow[0];
    const float inv1 = hscale / lrow[1];
#pragma unroll
    for (int ni = 0; ni < 4; ni++) {
        const int col = h * HD + wn * 32 + ni * 8 + 2 * t4;
        const size_t row0g = (size_t)(b * SEQ + l0 + li0) * HID + col;
        const size_t row1g = (size_t)(b * SEQ + l0 + li1) * HID + col;
        float c00 = __uint_as_float(f2tf(O[ni][0] * inv0));
        float c01 = __uint_as_float(f2tf(O[ni][1] * inv0));
        float c10 = __uint_as_float(f2tf(O[ni][2] * inv1));
        float c11 = __uint_as_float(f2tf(O[ni][3] * inv1));
        *(float2*)&ctx[row0g] = make_float2(c00, c01);
        *(float2*)&ctx[row1g] = make_float2(c10, c11);
    }
}

// ---------------- launch ----------------
extern "C" void kernel_launch(void* const* d_in, const int* in_sizes, int n_in,
                              void* d_out, int out_size)
{
    const float* hs   = (const float*)d_in[0];
    const float* mask = (const float*)d_in[1];
    const float* hm   = (const float*)d_in[2];
    const float* Wq   = (const float*)d_in[3];
    const float* bq   = (const float*)d_in[4];
    const float* Wk   = (const float*)d_in[5];
    const float* bk   = (const float*)d_in[6];
    const float* Wv   = (const float*)d_in[7];
    const float* bv   = (const float*)d_in[8];
    const float* dist = (const float*)d_in[9];
    const float* Wo   = (const float*)d_in[10];
    const float* bo   = (const float*)d_in[11];
    const float* ln1g = (const float*)d_in[12];
    const float* ln1b = (const float*)d_in[13];
    const float* Wi   = (const float*)d_in[14];
    const float* bi   = (const float*)d_in[15];
    const float* Wo2  = (const float*)d_in[16];
    const float* bo2  = (const float*)d_in[17];
    const float* ln2g = (const float*)d_in[18];
    const float* ln2b = (const float*)d_in[19];
    float* out = (float*)d_out;

    float *q, *k, *v, *ctx, *tmp, *attnout, *attnout_tf, *inter;
    float *hs_tf, *wq, *wk, *wv, *wo, *wi, *wo2;
    cudaGetSymbolAddress((void**)&q,          g_q);
    cudaGetSymbolAddress((void**)&k,          g_k);
    cudaGetSymbolAddress((void**)&v,          g_v);
    cudaGetSymbolAddress((void**)&ctx,        g_ctx);
    cudaGetSymbolAddress((void**)&tmp,        g_tmp);
    cudaGetSymbolAddress((void**)&attnout,    g_attnout);
    cudaGetSymbolAddress((void**)&attnout_tf, g_attnout_tf);
    cudaGetSymbolAddress((void**)&inter,      g_inter);
    cudaGetSymbolAddress((void**)&hs_tf,      g_hs_tf);
    cudaGetSymbolAddress((void**)&wq,         g_wq);
    cudaGetSymbolAddress((void**)&wk,         g_wk);
    cudaGetSymbolAddress((void**)&wv,         g_wv);
    cudaGetSymbolAddress((void**)&wo,         g_wo);
    cudaGetSymbolAddress((void**)&wi,         g_wi);
    cudaGetSymbolAddress((void**)&wo2,        g_wo2);

    cudaFuncSetAttribute(attn_tc, cudaFuncAttributeMaxDynamicSharedMemorySize,
                         ATTN_SMEM_BYTES);
    cudaFuncSetAttribute((const void*)gemm_db<0,0>,
                         cudaFuncAttributeMaxDynamicSharedMemorySize, GEMM_SMEM_BYTES);
    cudaFuncSetAttribute((const void*)gemm_db<1,1>,
                         cudaFuncAttributeMaxDynamicSharedMemorySize, GEMM_SMEM_BYTES);
    cudaFuncSetAttribute((const void*)qkv_db,
                         cudaFuncAttributeMaxDynamicSharedMemorySize, GEMM_SMEM_BYTES);

    dim3 blk(256);

    const int n4_1m = (HID * HID) / 4;
    const int n4_4m = (NTOK * HID) / 4;
    tf32_round_k<<<(n4_1m + 255) / 256, blk>>>(Wq,  wq,  n4_1m);
    tf32_round_k<<<(n4_1m + 255) / 256, blk>>>(Wk,  wk,  n4_1m);
    tf32_round_k<<<(n4_1m + 255) / 256, blk>>>(Wv,  wv,  n4_1m);
    tf32_round_k<<<(n4_1m + 255) / 256, blk>>>(Wo,  wo,  n4_1m);
    tf32_round_k<<<(n4_4m + 255) / 256, blk>>>(Wi,  wi,  n4_4m);
    tf32_round_k<<<(n4_4m + 255) / 256, blk>>>(Wo2, wo2, n4_4m);
    tf32_round_k<<<(n4_4m + 255) / 256, blk>>>(hs,  hs_tf, n4_4m);

    dim3 g_qkv(HID / 128, NTOK / 128, 3);
    dim3 g_1024(HID / 128, NTOK / 128);
    dim3 g_ff1(FFDIM / 128, NTOK / 128);

    qkv_db<<<g_qkv, blk, GEMM_SMEM_BYTES>>>(hs_tf, wq, wk, wv, bq, bk, bv, q, k, v);

    attn_tc<<<dim3(SEQ / 64, BATCH * NHEAD), blk, ATTN_SMEM_BYTES>>>(
        q, k, v, dist, mask, hm, ctx);

    gemm_db<0,0><<<g_1024, blk, GEMM_SMEM_BYTES>>>(ctx, wo, bo, tmp, NTOK, HID, HID);
    ln_residual<<<NTOK, blk>>>(tmp, hs, ln1g, ln1b, attnout, attnout_tf);

    gemm_db<1,1><<<g_ff1, blk, GEMM_SMEM_BYTES>>>(attnout_tf, wi, bi, inter,
                                                  NTOK, FFDIM, HID);
    gemm_db<0,0><<<g_1024, blk, GEMM_SMEM_BYTES>>>(inter, wo2, bo2, tmp,
                                                   NTOK, HID, FFDIM);
    ln_residual<<<NTOK, blk>>>(tmp, attnout, ln2g, ln2b, out, nullptr);
}

// round 9
// speedup vs baseline: 4.0419x; 1.0759x over previous
#include <cuda_runtime.h>
#include <cuda_bf16.h>
#include <math.h>
#include <stdint.h>

#define HID    1024
#define FFDIM  4096
#define NHEAD  16
#define HD     64
#define BATCH  4
#define SEQ    1024
#define NTOK   (BATCH*SEQ)
#define MAXPOS 1024

// ---------------- scratch ----------------
__device__ __nv_bfloat16 g_qh[NTOK * HID];
__device__ __nv_bfloat16 g_kh[NTOK * HID];
__device__ __nv_bfloat16 g_vh[NTOK * HID];
__device__ __nv_bfloat16 g_disth[(2 * MAXPOS - 1) * HD];
__device__ float g_ctx[NTOK * HID];
__device__ float g_tmp[NTOK * HID];
__device__ float g_attnout[NTOK * HID];
__device__ float g_attnout_tf[NTOK * HID];
__device__ float g_inter[NTOK * FFDIM];
__device__ float g_hs_tf[NTOK * HID];
__device__ float g_wq[HID * HID];
__device__ float g_wk[HID * HID];
__device__ float g_wv[HID * HID];
__device__ float g_wo[HID * HID];
__device__ float g_wi[HID * FFDIM];
__device__ float g_wo2[FFDIM * HID];

// ---------------- helpers ----------------
__device__ __forceinline__ uint32_t f2tf(float f) {
    uint32_t u;
    asm("cvt.rna.tf32.f32 %0, %1;" : "=r"(u) : "f"(f));
    return u;
}

__device__ __forceinline__ uint32_t pack_bf2(float x, float y) {
    __nv_bfloat162 h = __floats2bfloat162_rn(x, y);
    return *(uint32_t*)&h;
}

__device__ __forceinline__ uint32_t smem_u32(const void* p) {
    return (uint32_t)__cvta_generic_to_shared(p);
}

__device__ __forceinline__ void mma_tf32(float c[4], const uint32_t a[4],
                                         const uint32_t b[2]) {
    asm volatile(
        "mma.sync.aligned.m16n8k8.row.col.f32.tf32.tf32.f32 "
        "{%0,%1,%2,%3}, {%4,%5,%6,%7}, {%8,%9}, {%0,%1,%2,%3};"
        : "+f"(c[0]), "+f"(c[1]), "+f"(c[2]), "+f"(c[3])
        : "r"(a[0]), "r"(a[1]), "r"(a[2]), "r"(a[3]), "r"(b[0]), "r"(b[1]));
}

__device__ __forceinline__ void mma_bf16(float c[4], const uint32_t a[4],
                                         const uint32_t b[2]) {
    asm volatile(
        "mma.sync.aligned.m16n8k16.row.col.f32.bf16.bf16.f32 "
        "{%0,%1,%2,%3}, {%4,%5,%6,%7}, {%8,%9}, {%0,%1,%2,%3};"
        : "+f"(c[0]), "+f"(c[1]), "+f"(c[2]), "+f"(c[3])
        : "r"(a[0]), "r"(a[1]), "r"(a[2]), "r"(a[3]), "r"(b[0]), "r"(b[1]));
}

__device__ __forceinline__ void ldsm_x4(uint32_t* r, uint32_t a) {
    asm volatile("ldmatrix.sync.aligned.m8n8.x4.shared.b16 {%0,%1,%2,%3}, [%4];"
        : "=r"(r[0]), "=r"(r[1]), "=r"(r[2]), "=r"(r[3]) : "r"(a));
}
__device__ __forceinline__ void ldsm_x2(uint32_t* r, uint32_t a) {
    asm volatile("ldmatrix.sync.aligned.m8n8.x2.shared.b16 {%0,%1}, [%2];"
        : "=r"(r[0]), "=r"(r[1]) : "r"(a));
}
__device__ __forceinline__ void ldsm_x2t(uint32_t* r, uint32_t a) {
    asm volatile("ldmatrix.sync.aligned.m8n8.x2.trans.shared.b16 {%0,%1}, [%2];"
        : "=r"(r[0]), "=r"(r[1]) : "r"(a));
}

__device__ __forceinline__ void cp16(float* smem, const float* gmem) {
    uint32_t s = (uint32_t)__cvta_generic_to_shared(smem);
    asm volatile("cp.async.cg.shared.global [%0], [%1], 16;" :: "r"(s), "l"(gmem));
}
__device__ __forceinline__ void cp16h(__nv_bfloat16* smem, const __nv_bfloat16* gmem) {
    uint32_t s = (uint32_t)__cvta_generic_to_shared(smem);
    asm volatile("cp.async.cg.shared.global [%0], [%1], 16;" :: "r"(s), "l"(gmem));
}
#define CP_COMMIT() asm volatile("cp.async.commit_group;")
#define CP_WAIT0()  asm volatile("cp.async.wait_group 0;")

// ---------------- conversion kernels ----------------
__global__ void __launch_bounds__(256) tf32_round_k(
    const float* __restrict__ in, float* __restrict__ out, int n4)
{
    int i = blockIdx.x * blockDim.x + threadIdx.x;
    if (i < n4) {
        float4 v = ((const float4*)in)[i];
        v.x = __uint_as_float(f2tf(v.x));
        v.y = __uint_as_float(f2tf(v.y));
        v.z = __uint_as_float(f2tf(v.z));
        v.w = __uint_as_float(f2tf(v.w));
        ((float4*)out)[i] = v;
    }
}

__global__ void __launch_bounds__(256) bf16_cvt_k(
    const float* __restrict__ in, __nv_bfloat16* __restrict__ out, int n2)
{
    int i = blockIdx.x * blockDim.x + threadIdx.x;
    if (i < n2) {
        float2 v = ((const float2*)in)[i];
        ((uint32_t*)out)[i] = pack_bf2(v.x, v.y);
    }
}

// ---------------- double-buffered tf32 GEMM ----------------------------------
#define GA(s,r,c) ((( (s)*128 + (r) )*36) + (c))
#define GB(s,r,c) ((( (s)*32  + (r) )*136) + (c))
#define GEMM_SMEM_BYTES ((2*128*36 + 2*32*136) * 4)

template <int GELU, int ROUND, int BFOUT>
__device__ __forceinline__ void gemm_body(
    const float* __restrict__ A, const float* __restrict__ Bm,
    const float* __restrict__ bias, void* __restrict__ Cout,
    int M, int N, int K, float* sm)
{
    float* As = sm;
    float* Bs = sm + 2 * 128 * 36;

    const int tid = threadIdx.x;
    const int w   = tid >> 5;
    const int l   = tid & 31;
    const int wr  = w >> 2;
    const int wc  = w & 3;
    const int m0  = blockIdx.y * 128;
    const int n0  = blockIdx.x * 128;
    const int g   = l >> 2;
    const int t4  = l & 3;

    const int ar = tid >> 3;
    const int ac = (tid & 7) << 2;
    const int br = tid >> 5;
    const int bc = (tid & 31) << 2;

    float c[4][4][4];
#pragma unroll
    for (int mi = 0; mi < 4; mi++)
#pragma unroll
        for (int ni = 0; ni < 4; ni++)
#pragma unroll
            for (int r = 0; r < 4; r++) c[mi][ni][r] = 0.f;

#pragma unroll
    for (int i = 0; i < 4; i++)
        cp16(&As[GA(0, ar + 32 * i, ac)], &A[(size_t)(m0 + ar + 32 * i) * K + ac]);
#pragma unroll
    for (int i = 0; i < 4; i++)
        cp16(&Bs[GB(0, br + 8 * i, bc)], &Bm[(size_t)(br + 8 * i) * N + n0 + bc]);
    CP_COMMIT();

    for (int k0 = 0; k0 < K; k0 += 32) {
        const int s = (k0 >> 5) & 1;
        CP_WAIT0();
        __syncthreads();
        if (k0 + 32 < K) {
            const int ns = s ^ 1;
            const int nk = k0 + 32;
#pragma unroll
            for (int i = 0; i < 4; i++)
                cp16(&As[GA(ns, ar + 32 * i, ac)],
                     &A[(size_t)(m0 + ar + 32 * i) * K + nk + ac]);
#pragma unroll
            for (int i = 0; i < 4; i++)
                cp16(&Bs[GB(ns, br + 8 * i, bc)],
                     &Bm[(size_t)(nk + br + 8 * i) * N + n0 + bc]);
            CP_COMMIT();
        }

#pragma unroll
        for (int kk = 0; kk < 4; kk++) {
            const int kb = kk * 8;
            uint32_t a[4][4], b[4][2];
#pragma unroll
            for (int mi = 0; mi < 4; mi++) {
                const int mrow = wr * 64 + mi * 16 + g;
                a[mi][0] = __float_as_uint(As[GA(s, mrow,     kb + t4)]);
                a[mi][1] = __float_as_uint(As[GA(s, mrow + 8, kb + t4)]);
                a[mi][2] = __float_as_uint(As[GA(s, mrow,     kb + t4 + 4)]);
                a[mi][3] = __float_as_uint(As[GA(s, mrow + 8, kb + t4 + 4)]);
            }
#pragma unroll
            for (int ni = 0; ni < 4; ni++) {
                const int ncol = wc * 32 + ni * 8 + g;
                b[ni][0] = __float_as_uint(Bs[GB(s, kb + t4,     ncol)]);
                b[ni][1] = __float_as_uint(Bs[GB(s, kb + t4 + 4, ncol)]);
            }
#pragma unroll
            for (int mi = 0; mi < 4; mi++)
#pragma unroll
                for (int ni = 0; ni < 4; ni++)
                    mma_tf32(c[mi][ni], a[mi], b[ni]);
        }
    }

#pragma unroll
    for (int mi = 0; mi < 4; mi++) {
#pragma unroll
        for (int ni = 0; ni < 4; ni++) {
            const int row = m0 + wr * 64 + mi * 16 + g;
            const int col = n0 + wc * 32 + ni * 8 + t4 * 2;
            const float b0 = bias[col], b1 = bias[col + 1];
            float v0 = c[mi][ni][0] + b0;
            float v1 = c[mi][ni][1] + b1;
            float v2 = c[mi][ni][2] + b0;
            float v3 = c[mi][ni][3] + b1;
            if (GELU) {
                v0 = 0.5f * v0 * (1.0f + erff(v0 * 0.70710678118654752f));
                v1 = 0.5f * v1 * (1.0f + erff(v1 * 0.70710678118654752f));
                v2 = 0.5f * v2 * (1.0f + erff(v2 * 0.70710678118654752f));
                v3 = 0.5f * v3 * (1.0f + erff(v3 * 0.70710678118654752f));
            }
            if (BFOUT) {
                __nv_bfloat16* C = (__nv_bfloat16*)Cout;
                *(uint32_t*)&C[(size_t)row * N + col]       = pack_bf2(v0, v1);
                *(uint32_t*)&C[(size_t)(row + 8) * N + col] = pack_bf2(v2, v3);
            } else {
                float* C = (float*)Cout;
                if (ROUND) {
                    v0 = __uint_as_float(f2tf(v0));
                    v1 = __uint_as_float(f2tf(v1));
                    v2 = __uint_as_float(f2tf(v2));
                    v3 = __uint_as_float(f2tf(v3));
                }
                *(float2*)&C[(size_t)row * N + col]       = make_float2(v0, v1);
                *(float2*)&C[(size_t)(row + 8) * N + col] = make_float2(v2, v3);
            }
        }
    }
}

template <int GELU, int ROUND>
__global__ void __launch_bounds__(256) gemm_db(
    const float* __restrict__ A, const float* __restrict__ Bm,
    const float* __restrict__ bias, float* __restrict__ C,
    int M, int N, int K)
{
    extern __shared__ float sm[];
    gemm_body<GELU, ROUND, 0>(A, Bm, bias, C, M, N, K, sm);
}

__global__ void __launch_bounds__(256) qkv_db(
    const float* __restrict__ A,
    const float* __restrict__ W0, const float* __restrict__ W1, const float* __restrict__ W2,
    const float* __restrict__ b0, const float* __restrict__ b1, const float* __restrict__ b2,
    __nv_bfloat16* __restrict__ o0, __nv_bfloat16* __restrict__ o1,
    __nv_bfloat16* __restrict__ o2)
{
    extern __shared__ float sm[];
    const int z = blockIdx.z;
    const float* W = (z == 0) ? W0 : (z == 1) ? W1 : W2;
    const float* bb = (z == 0) ? b0 : (z == 1) ? b1 : b2;
    __nv_bfloat16* O = (z == 0) ? o0 : (z == 1) ? o1 : o2;
    gemm_body<0, 0, 1>(A, W, bb, O, NTOK, HID, HID, sm);
}

// ---------------- LayerNorm(x + res) * g + b, float4, optional tf copy -------
__global__ void __launch_bounds__(256) ln_residual(
    const float* __restrict__ x, const float* __restrict__ res,
    const float* __restrict__ g, const float* __restrict__ b,
    float* __restrict__ out, float* __restrict__ out_tf)
{
    __shared__ float red[8];
    const int row = blockIdx.x;
    const int tid = threadIdx.x;
    const size_t base = (size_t)row * HID + tid * 4;

    float4 xv = *(const float4*)&x[base];
    float4 rv = *(const float4*)&res[base];
    float v0 = xv.x + rv.x, v1 = xv.y + rv.y, v2 = xv.z + rv.z, v3 = xv.w + rv.w;

    float s = v0 + v1 + v2 + v3;
#pragma unroll
    for (int o = 16; o; o >>= 1) s += __shfl_xor_sync(0xffffffffu, s, o);
    if ((tid & 31) == 0) red[tid >> 5] = s;
    __syncthreads();
    if (tid < 8) {
        s = red[tid];
#pragma unroll
        for (int o = 4; o; o >>= 1) s += __shfl_xor_sync(0xffu, s, o, 8);
        if (tid == 0) red[0] = s;
    }
    __syncthreads();
    const float mean = red[0] * (1.0f / HID);
    __syncthreads();

    float d0 = v0 - mean, d1 = v1 - mean, d2 = v2 - mean, d3 = v3 - mean;
    float vs = d0 * d0 + d1 * d1 + d2 * d2 + d3 * d3;
#pragma unroll
    for (int o = 16; o; o >>= 1) vs += __shfl_xor_sync(0xffffffffu, vs, o);
    if ((tid & 31) == 0) red[tid >> 5] = vs;
    __syncthreads();
    if (tid < 8) {
        vs = red[tid];
#pragma unroll
        for (int o = 4; o; o >>= 1) vs += __shfl_xor_sync(0xffu, vs, o, 8);
        if (tid == 0) red[0] = vs;
    }
    __syncthreads();
    const float inv = rsqrtf(red[0] * (1.0f / HID) + 1e-12f);

    float4 gv = *(const float4*)&g[tid * 4];
    float4 bv = *(const float4*)&b[tid * 4];
    float4 ov;
    ov.x = d0 * inv * gv.x + bv.x;
    ov.y = d1 * inv * gv.y + bv.y;
    ov.z = d2 * inv * gv.z + bv.z;
    ov.w = d3 * inv * gv.w + bv.w;
    *(float4*)&out[base] = ov;
    if (out_tf) {
        float4 tv;
        tv.x = __uint_as_float(f2tf(ov.x));
        tv.y = __uint_as_float(f2tf(ov.y));
        tv.z = __uint_as_float(f2tf(ov.z));
        tv.w = __uint_as_float(f2tf(ov.w));
        *(float4*)&out_tf[base] = tv;
    }
}

// ---------------- bf16 TC attention: cp.async staging + K/V double buffer ----
#define HST 72
#define BSTH 132
// Q 9216 + K 2x9216 + Ering 18432 + V 2x9216 + B1 16896 + B2 16896 + P 9216 + red 1024
#define ATTN_SMEM_BYTES 108544

__global__ void __launch_bounds__(256, 2) attn_tc(
    const __nv_bfloat16* __restrict__ Q, const __nv_bfloat16* __restrict__ K,
    const __nv_bfloat16* __restrict__ V, const __nv_bfloat16* __restrict__ disth,
    const float* __restrict__ mask, const float* __restrict__ hm,
    float* __restrict__ ctx)
{
    extern __shared__ char smb[];
    __nv_bfloat16* Qh  = (__nv_bfloat16*)smb;       // [64][HST]
    __nv_bfloat16* Kh  = Qh + 64 * HST;             // [2][64][HST]
    __nv_bfloat16* Er  = Kh + 2 * 64 * HST;         // [128][HST] ring
    __nv_bfloat16* Vh  = Er + 128 * HST;            // [2][64][HST]
    __nv_bfloat16* B1h = Vh + 2 * 64 * HST;         // [64][BSTH]
    __nv_bfloat16* B2h = B1h + 64 * BSTH;           // [64][BSTH]
    __nv_bfloat16* Ph  = B2h + 64 * BSTH;           // [64][HST]
    float*         Rmax = (float*)(Ph + 64 * HST);  // [2][64]
    float*         Rsum = Rmax + 128;               // [2][64]

    const int tid = threadIdx.x;
    const int w   = tid >> 5;
    const int wm  = w & 3;
    const int wn  = w >> 2;
    const int l   = tid & 31;
    const int g   = l >> 2;
    const int t4  = l & 3;
    const int bh  = blockIdx.y;
    const int b   = bh >> 4;
    const int h   = bh & 15;
    const int l0  = blockIdx.x * 64;

    const int li0 = 16 * wm + g;
    const int li1 = li0 + 8;

    const int arow = 16 * wm + (l & 15);
    const int acol = (l >> 4) << 3;
    const uint32_t aQ = smem_u32(&Qh[arow * HST + acol]);
    const uint32_t aP = smem_u32(&Ph[arow * HST + acol]);
    const uint32_t aKb[2] = { smem_u32(&Kh[arow * HST + acol]),
                              smem_u32(&Kh[64 * HST + arow * HST + acol]) };
    const int brow = l & 7;
    const int bcol = ((l >> 3) & 1) << 3;
    const uint32_t bKb[2] = { smem_u32(&Kh[brow * HST + bcol]),
                              smem_u32(&Kh[64 * HST + brow * HST + bcol]) };
    const uint32_t bEbase = smem_u32(Er) + bcol * 2;
    const uint32_t bVb[2] = { smem_u32(&Vh[(l & 15) * HST]),
                              smem_u32(&Vh[64 * HST + (l & 15) * HST]) };

    const __nv_bfloat16* Qg = Q + (size_t)(b * SEQ + l0) * HID + h * HD;
    const __nv_bfloat16* Kg = K + (size_t)(b * SEQ) * HID + h * HD;
    const __nv_bfloat16* Vg = V + (size_t)(b * SEQ) * HID + h * HD;
    const float* mg = mask + b * SEQ;

    // ---- prologue: stage Q, E window (128 rows), K/V tile 0 via cp.async
    for (int idx = tid; idx < 512; idx += 256) {
        int r = idx >> 3, c8 = (idx & 7) << 3;
        cp16h(&Qh[r * HST + c8], &Qg[(size_t)r * HID + c8]);
    }
    {
        const int dbase0 = l0 + 960;
        for (int idx = tid; idx < 1024; idx += 256) {
            int r = idx >> 3, c8 = (idx & 7) << 3;
            int row = dbase0 + r;
            int rowc = row > 2046 ? 2046 : row;   // slot unread this iter
            cp16h(&Er[(row & 127) * HST + c8], &disth[(size_t)rowc * HD + c8]);
        }
        for (int idx = tid; idx < 512; idx += 256) {
            int r = idx >> 3, c8 = (idx & 7) << 3;
            cp16h(&Kh[r * HST + c8], &Kg[(size_t)r * HID + c8]);
            cp16h(&Vh[r * HST + c8], &Vg[(size_t)r * HID + c8]);
        }
    }
    CP_COMMIT();
    CP_WAIT0();
    __syncthreads();

    uint32_t aq[4][4];
#pragma unroll
    for (int kk = 0; kk < 4; kk++) ldsm_x4(aq[kk], aQ + kk * 32);

    float O[4][4];
#pragma unroll
    for (int ni = 0; ni < 4; ni++)
#pragma unroll
        for (int r = 0; r < 4; r++) O[ni][r] = 0.f;
    float mrow[2] = {-1e30f, -1e30f};
    float lrow[2] = {0.f, 0.f};

    for (int rt = 0; rt < 16; rt++) {
        const int r0 = rt * 64;
        const int dbase = l0 - r0 + 960;
        const int buf = rt & 1;
        if (rt) {
            CP_WAIT0();        // staged K/V/E for this iter
            __syncthreads();   // visible to all; also orders prev PV vs Ph overwrite
        }

        uint32_t ak[4][4];
#pragma unroll
        for (int kk = 0; kk < 4; kk++) ldsm_x4(ak[kk], aKb[buf] + kk * 32);

        // ---- B2 = K @ E_window^T : 128 cols (warp n-half = 64), 2 passes
#pragma unroll
        for (int p = 0; p < 2; p++) {
            float c[4][4];
#pragma unroll
            for (int ni = 0; ni < 4; ni++)
#pragma unroll
                for (int r = 0; r < 4; r++) c[ni][r] = 0.f;
#pragma unroll
            for (int kk = 0; kk < 4; kk++) {
#pragma unroll
                for (int ni = 0; ni < 4; ni++) {
                    const int j = wn * 64 + p * 32 + ni * 8;
                    const int slot = (dbase + j + brow) & 127;
                    uint32_t bf[2];
                    ldsm_x2(bf, bEbase + slot * (HST * 2) + kk * 32);
                    mma_bf16(c[ni], ak[kk], bf);
                }
            }
#pragma unroll
            for (int ni = 0; ni < 4; ni++) {
                const int col = wn * 64 + p * 32 + ni * 8 + 2 * t4;
                *(uint32_t*)&B2h[li0 * BSTH + col] = pack_bf2(c[ni][0], c[ni][1]);
                *(uint32_t*)&B2h[li1 * BSTH + col] = pack_bf2(c[ni][2], c[ni][3]);
            }
        }

        // ---- B1 new block(s): Q @ E_new^T
        const int nblk = (rt == 0) ? 2 : 1;
        for (int blk = 0; blk < nblk; blk++) {
            const int base = (dbase + 64 * blk) & 127;
            float c[4][4];
#pragma unroll
            for (int ni = 0; ni < 4; ni++)
#pragma unroll
                for (int r = 0; r < 4; r++) c[ni][r] = 0.f;
#pragma unroll
            for (int kk = 0; kk < 4; kk++) {
#pragma unroll
                for (int ni = 0; ni < 4; ni++) {
                    const int slot = base + wn * 32 + ni * 8 + brow;
                    uint32_t bf[2];
                    ldsm_x2(bf, bEbase + slot * (HST * 2) + kk * 32);
                    mma_bf16(c[ni], aq[kk], bf);
                }
            }
#pragma unroll
            for (int ni = 0; ni < 4; ni++) {
                const int col = base + wn * 32 + ni * 8 + 2 * t4;
                *(uint32_t*)&B1h[li0 * BSTH + col] = pack_bf2(c[ni][0], c[ni][1]);
                *(uint32_t*)&B1h[li1 * BSTH + col] = pack_bf2(c[ni][2], c[ni][3]);
            }
        }

        // ---- S = Q @ K^T
        float cS[4][4];
#pragma unroll
        for (int ni = 0; ni < 4; ni++)
#pragma unroll
            for (int r = 0; r < 4; r++) cS[ni][r] = 0.f;
#pragma unroll
        for (int kk = 0; kk < 4; kk++) {
#pragma unroll
            for (int ni = 0; ni < 4; ni++) {
                const int ncol = wn * 32 + ni * 8;
                uint32_t bf[2];
                ldsm_x2(bf, bKb[buf] + (ncol * HST) * 2 + kk * 32);
                mma_bf16(cS[ni], aq[kk], bf);
            }
        }
        __syncthreads();   // B1/B2 visible; all E-ring + K-tile reads done

        // ---- prefetch next tile (K/V into buf^1, E new rows into freed slots)
        if (rt < 15) {
            const int nbuf = buf ^ 1;
            const int nr0 = r0 + 64;
            const int ndbase = dbase - 64;
            for (int idx = tid; idx < 512; idx += 256) {
                int r = idx >> 3, c8 = (idx & 7) << 3;
                cp16h(&Kh[nbuf * 64 * HST + r * HST + c8],
                      &Kg[(size_t)(nr0 + r) * HID + c8]);
                cp16h(&Vh[nbuf * 64 * HST + r * HST + c8],
                      &Vg[(size_t)(nr0 + r) * HID + c8]);
            }
            for (int idx = tid; idx < 512; idx += 256) {
                int r = idx >> 3, c8 = (idx & 7) << 3;
                int row = ndbase + r;   // always <= 2046 for rt >= 0
                cp16h(&Er[(row & 127) * HST + c8], &disth[(size_t)row * HD + c8]);
            }
            CP_COMMIT();
        }

        // ---- bias gather + scale + mask
        const int dofs = dbase + 63;
        float vmax0 = -1e30f, vmax1 = -1e30f;
#pragma unroll
        for (int ni = 0; ni < 4; ni++) {
#pragma unroll
            for (int e = 0; e < 2; e++) {
                const int rj = wn * 32 + ni * 8 + 2 * t4 + e;
                const float mv = mg[r0 + rj];
                const int s0 = (dofs + li0 - rj) & 127;
                const int s1 = (dofs + li1 - rj) & 127;
                const int ib0 = li0 - rj + 63;
                const int ib1 = li1 - rj + 63;
                float b1a = __bfloat162float(B1h[li0 * BSTH + s0]);
                float b1b = __bfloat162float(B1h[li1 * BSTH + s1]);
                float b2a = __bfloat162float(B2h[rj * BSTH + ib0]);
                float b2b = __bfloat162float(B2h[rj * BSTH + ib1]);
                float v0 = (cS[ni][e]     + b1a + b2a) * 0.125f + mv;
                float v1 = (cS[ni][2 + e] + b1b + b2b) * 0.125f + mv;
                cS[ni][e]     = v0;
                cS[ni][2 + e] = v1;
                vmax0 = fmaxf(vmax0, v0);
                vmax1 = fmaxf(vmax1, v1);
            }
        }
        vmax0 = fmaxf(vmax0, __shfl_xor_sync(0xffffffffu, vmax0, 1));
        vmax0 = fmaxf(vmax0, __shfl_xor_sync(0xffffffffu, vmax0, 2));
        vmax1 = fmaxf(vmax1, __shfl_xor_sync(0xffffffffu, vmax1, 1));
        vmax1 = fmaxf(vmax1, __shfl_xor_sync(0xffffffffu, vmax1, 2));
        if (t4 == 0) {
            Rmax[wn * 64 + li0] = vmax0;
            Rmax[wn * 64 + li1] = vmax1;
        }
        __syncthreads();
        vmax0 = fmaxf(vmax0, Rmax[(wn ^ 1) * 64 + li0]);
        vmax1 = fmaxf(vmax1, Rmax[(wn ^ 1) * 64 + li1]);

        const float nm0 = fmaxf(mrow[0], vmax0);
        const float nm1 = fmaxf(mrow[1], vmax1);
        const float corr0 = __expf(mrow[0] - nm0);
        const float corr1 = __expf(mrow[1] - nm1);

        float ts0 = 0.f, ts1 = 0.f;
#pragma unroll
        for (int ni = 0; ni < 4; ni++) {
            const int cj = wn * 32 + ni * 8 + 2 * t4;
            float p00 = __expf(cS[ni][0] - nm0);
            float p01 = __expf(cS[ni][1] - nm0);
            float p10 = __expf(cS[ni][2] - nm1);
            float p11 = __expf(cS[ni][3] - nm1);
            *(uint32_t*)&Ph[li0 * HST + cj] = pack_bf2(p00, p01);
            *(uint32_t*)&Ph[li1 * HST + cj] = pack_bf2(p10, p11);
            ts0 += p00 + p01;
            ts1 += p10 + p11;
        }
        ts0 += __shfl_xor_sync(0xffffffffu, ts0, 1);
        ts0 += __shfl_xor_sync(0xffffffffu, ts0, 2);
        ts1 += __shfl_xor_sync(0xffffffffu, ts1, 1);
        ts1 += __shfl_xor_sync(0xffffffffu, ts1, 2);
        if (t4 == 0) {
            Rsum[wn * 64 + li0] = ts0;
            Rsum[wn * 64 + li1] = ts1;
        }
        __syncthreads();   // Rsum + P visible
        ts0 += Rsum[(wn ^ 1) * 64 + li0];
        ts1 += Rsum[(wn ^ 1) * 64 + li1];

        lrow[0] = lrow[0] * corr0 + ts0;
        lrow[1] = lrow[1] * corr1 + ts1;
        mrow[0] = nm0;
        mrow[1] = nm1;
#pragma unroll
        for (int ni = 0; ni < 4; ni++) {
            O[ni][0] *= corr0;
            O[ni][1] *= corr0;
            O[ni][2] *= corr1;
            O[ni][3] *= corr1;
        }

        // ---- PV: O += P @ V
#pragma unroll
        for (int kk = 0; kk < 4; kk++) {
            const int kb = kk * 16;
            uint32_t ap[4];
            ldsm_x4(ap, aP + kk * 32);
#pragma unroll
            for (int ni = 0; ni < 4; ni++) {
                const int nbase = wn * 32 + ni * 8;
                uint32_t bf[2];
                ldsm_x2t(bf, bVb[buf] + (kb * HST + nbase) * 2);
                mma_bf16(O[ni], ap, bf);
            }
        }
    }

    const float hscale = hm[h];
    const float inv0 = hscale / lrow[0];
    const float inv1 = hscale / lrow[1];
#pragma unroll
    for (int ni = 0; ni < 4; ni++) {
        const int col = h * HD + wn * 32 + ni * 8 + 2 * t4;
        const size_t row0g = (size_t)(b * SEQ + l0 + li0) * HID + col;
        const size_t row1g = (size_t)(b * SEQ + l0 + li1) * HID + col;
        float c00 = __uint_as_float(f2tf(O[ni][0] * inv0));
        float c01 = __uint_as_float(f2tf(O[ni][1] * inv0));
        float c10 = __uint_as_float(f2tf(O[ni][2] * inv1));
        float c11 = __uint_as_float(f2tf(O[ni][3] * inv1));
        *(float2*)&ctx[row0g] = make_float2(c00, c01);
        *(float2*)&ctx[row1g] = make_float2(c10, c11);
    }
}

// ---------------- launch ----------------
extern "C" void kernel_launch(void* const* d_in, const int* in_sizes, int n_in,
                              void* d_out, int out_size)
{
    const float* hs   = (const float*)d_in[0];
    const float* mask = (const float*)d_in[1];
    const float* hm   = (const float*)d_in[2];
    const float* Wq   = (const float*)d_in[3];
    const float* bq   = (const float*)d_in[4];
    const float* Wk   = (const float*)d_in[5];
    const float* bk   = (const float*)d_in[6];
    const float* Wv   = (const float*)d_in[7];
    const float* bv   = (const float*)d_in[8];
    const float* dist = (const float*)d_in[9];
    const float* Wo   = (const float*)d_in[10];
    const float* bo   = (const float*)d_in[11];
    const float* ln1g = (const float*)d_in[12];
    const float* ln1b = (const float*)d_in[13];
    const float* Wi   = (const float*)d_in[14];
    const float* bi   = (const float*)d_in[15];
    const float* Wo2  = (const float*)d_in[16];
    const float* bo2  = (const float*)d_in[17];
    const float* ln2g = (const float*)d_in[18];
    const float* ln2b = (const float*)d_in[19];
    float* out = (float*)d_out;

    __nv_bfloat16 *qh, *kh, *vh, *disth;
    float *ctx, *tmp, *attnout, *attnout_tf, *inter;
    float *hs_tf, *wq, *wk, *wv, *wo, *wi, *wo2;
    cudaGetSymbolAddress((void**)&qh,         g_qh);
    cudaGetSymbolAddress((void**)&kh,         g_kh);
    cudaGetSymbolAddress((void**)&vh,         g_vh);
    cudaGetSymbolAddress((void**)&disth,      g_disth);
    cudaGetSymbolAddress((void**)&ctx,        g_ctx);
    cudaGetSymbolAddress((void**)&tmp,        g_tmp);
    cudaGetSymbolAddress((void**)&attnout,    g_attnout);
    cudaGetSymbolAddress((void**)&attnout_tf, g_attnout_tf);
    cudaGetSymbolAddress((void**)&inter,      g_inter);
    cudaGetSymbolAddress((void**)&hs_tf,      g_hs_tf);
    cudaGetSymbolAddress((void**)&wq,         g_wq);
    cudaGetSymbolAddress((void**)&wk,         g_wk);
    cudaGetSymbolAddress((void**)&wv,         g_wv);
    cudaGetSymbolAddress((void**)&wo,         g_wo);
    cudaGetSymbolAddress((void**)&wi,         g_wi);
    cudaGetSymbolAddress((void**)&wo2,        g_wo2);

    cudaFuncSetAttribute(attn_tc, cudaFuncAttributeMaxDynamicSharedMemorySize,
                         ATTN_SMEM_BYTES);
    cudaFuncSetAttribute((const void*)gemm_db<0,0>,
                         cudaFuncAttributeMaxDynamicSharedMemorySize, GEMM_SMEM_BYTES);
    cudaFuncSetAttribute((const void*)gemm_db<1,1>,
                         cudaFuncAttributeMaxDynamicSharedMemorySize, GEMM_SMEM_BYTES);
    cudaFuncSetAttribute((const void*)qkv_db,
                         cudaFuncAttributeMaxDynamicSharedMemorySize, GEMM_SMEM_BYTES);

    dim3 blk(256);

    const int n4_1m = (HID * HID) / 4;
    const int n4_4m = (NTOK * HID) / 4;
    const int n2_d  = ((2 * MAXPOS - 1) * HD) / 2;
    tf32_round_k<<<(n4_1m + 255) / 256, blk>>>(Wq,  wq,  n4_1m);
    tf32_round_k<<<(n4_1m + 255) / 256, blk>>>(Wk,  wk,  n4_1m);
    tf32_round_k<<<(n4_1m + 255) / 256, blk>>>(Wv,  wv,  n4_1m);
    tf32_round_k<<<(n4_1m + 255) / 256, blk>>>(Wo,  wo,  n4_1m);
    tf32_round_k<<<(n4_4m + 255) / 256, blk>>>(Wi,  wi,  n4_4m);
    tf32_round_k<<<(n4_4m + 255) / 256, blk>>>(Wo2, wo2, n4_4m);
    tf32_round_k<<<(n4_4m + 255) / 256, blk>>>(hs,  hs_tf, n4_4m);
    bf16_cvt_k<<<(n2_d + 255) / 256, blk>>>(dist, disth, n2_d);

    dim3 g_qkv(HID / 128, NTOK / 128, 3);
    dim3 g_1024(HID / 128, NTOK / 128);
    dim3 g_ff1(FFDIM / 128, NTOK / 128);

    qkv_db<<<g_qkv, blk, GEMM_SMEM_BYTES>>>(hs_tf, wq, wk, wv, bq, bk, bv,
                                            qh, kh, vh);

    attn_tc<<<dim3(SEQ / 64, BATCH * NHEAD), blk, ATTN_SMEM_BYTES>>>(
        qh, kh, vh, disth, mask, hm, ctx);

    gemm_db<0,0><<<g_1024, blk, GEMM_SMEM_BYTES>>>(ctx, wo, bo, tmp, NTOK, HID, HID);
    ln_residual<<<NTOK, blk>>>(tmp, hs, ln1g, ln1b, attnout, attnout_tf);

    gemm_db<1,1><<<g_ff1, blk, GEMM_SMEM_BYTES>>>(attnout_tf, wi, bi, inter,
                                                  NTOK, FFDIM, HID);
    gemm_db<0,0><<<g_1024, blk, GEMM_SMEM_BYTES>>>(inter, wo2, bo2, tmp,
                                                   NTOK, HID, FFDIM);
    ln_residual<<<NTOK, blk>>>(tmp, attnout, ln2g, ln2b, out, nullptr);
}

// round 10
// speedup vs baseline: 4.1588x; 1.0289x over previous
#include <cuda_runtime.h>
#include <cuda_bf16.h>
#include <math.h>
#include <stdint.h>

#define HID    1024
#define FFDIM  4096
#define NHEAD  16
#define HD     64
#define BATCH  4
#define SEQ    1024
#define NTOK   (BATCH*SEQ)
#define MAXPOS 1024

// ---------------- scratch ----------------
__device__ __nv_bfloat16 g_qh[NTOK * HID];
__device__ __nv_bfloat16 g_kh[NTOK * HID];
__device__ __nv_bfloat16 g_vh[NTOK * HID];
__device__ __nv_bfloat16 g_disth[(2 * MAXPOS - 1) * HD];
__device__ float g_ctx[NTOK * HID];
__device__ float g_tmp[NTOK * HID];
__device__ float g_attnout[NTOK * HID];
__device__ float g_attnout_tf[NTOK * HID];
__device__ float g_inter[NTOK * FFDIM];
__device__ float g_hs_tf[NTOK * HID];
__device__ float g_wq[HID * HID];
__device__ float g_wk[HID * HID];
__device__ float g_wv[HID * HID];
__device__ float g_wo[HID * HID];
__device__ float g_wi[HID * FFDIM];
__device__ float g_wo2[FFDIM * HID];

// ---------------- helpers ----------------
__device__ __forceinline__ uint32_t f2tf(float f) {
    uint32_t u;
    asm("cvt.rna.tf32.f32 %0, %1;" : "=r"(u) : "f"(f));
    return u;
}

__device__ __forceinline__ uint32_t pack_bf2(float x, float y) {
    __nv_bfloat162 h = __floats2bfloat162_rn(x, y);
    return *(uint32_t*)&h;
}

__device__ __forceinline__ uint32_t smem_u32(const void* p) {
    return (uint32_t)__cvta_generic_to_shared(p);
}

__device__ __forceinline__ void mma_tf32(float c[4], const uint32_t a[4],
                                         const uint32_t b[2]) {
    asm volatile(
        "mma.sync.aligned.m16n8k8.row.col.f32.tf32.tf32.f32 "
        "{%0,%1,%2,%3}, {%4,%5,%6,%7}, {%8,%9}, {%0,%1,%2,%3};"
        : "+f"(c[0]), "+f"(c[1]), "+f"(c[2]), "+f"(c[3])
        : "r"(a[0]), "r"(a[1]), "r"(a[2]), "r"(a[3]), "r"(b[0]), "r"(b[1]));
}

__device__ __forceinline__ void mma_bf16(float c[4], const uint32_t a[4],
                                         const uint32_t b[2]) {
    asm volatile(
        "mma.sync.aligned.m16n8k16.row.col.f32.bf16.bf16.f32 "
        "{%0,%1,%2,%3}, {%4,%5,%6,%7}, {%8,%9}, {%0,%1,%2,%3};"
        : "+f"(c[0]), "+f"(c[1]), "+f"(c[2]), "+f"(c[3])
        : "r"(a[0]), "r"(a[1]), "r"(a[2]), "r"(a[3]), "r"(b[0]), "r"(b[1]));
}

__device__ __forceinline__ void ldsm_x4(uint32_t* r, uint32_t a) {
    asm volatile("ldmatrix.sync.aligned.m8n8.x4.shared.b16 {%0,%1,%2,%3}, [%4];"
        : "=r"(r[0]), "=r"(r[1]), "=r"(r[2]), "=r"(r[3]) : "r"(a));
}
__device__ __forceinline__ void ldsm_x2(uint32_t* r, uint32_t a) {
    asm volatile("ldmatrix.sync.aligned.m8n8.x2.shared.b16 {%0,%1}, [%2];"
        : "=r"(r[0]), "=r"(r[1]) : "r"(a));
}
__device__ __forceinline__ void ldsm_x2t(uint32_t* r, uint32_t a) {
    asm volatile("ldmatrix.sync.aligned.m8n8.x2.trans.shared.b16 {%0,%1}, [%2];"
        : "=r"(r[0]), "=r"(r[1]) : "r"(a));
}

__device__ __forceinline__ void cp16(float* smem, const float* gmem) {
    uint32_t s = (uint32_t)__cvta_generic_to_shared(smem);
    asm volatile("cp.async.cg.shared.global [%0], [%1], 16;" :: "r"(s), "l"(gmem));
}
__device__ __forceinline__ void cp16h(__nv_bfloat16* smem, const __nv_bfloat16* gmem) {
    uint32_t s = (uint32_t)__cvta_generic_to_shared(smem);
    asm volatile("cp.async.cg.shared.global [%0], [%1], 16;" :: "r"(s), "l"(gmem));
}
#define CP_COMMIT() asm volatile("cp.async.commit_group;")
#define CP_WAIT0()  asm volatile("cp.async.wait_group 0;")

// ---------------- fused conversion kernel -------------------------------------
// segments (float4 units): 4 x 262144 (Wq,Wk,Wv,Wo), 3 x 1048576 (Wi,Wo2,hs),
// then 32752 float4 of dist -> bf16.
#define CVT_W1   262144
#define CVT_W4   1048576
#define CVT_SEG1 (4 * CVT_W1)                 // 1048576
#define CVT_SEG2 (CVT_SEG1 + 3 * CVT_W4)      // 4194304
#define CVT_DIST 32752
#define CVT_TOTAL (CVT_SEG2 + CVT_DIST)       // 4227056

__global__ void __launch_bounds__(256) fused_cvt_k(
    const float* __restrict__ Wq, const float* __restrict__ Wk,
    const float* __restrict__ Wv, const float* __restrict__ Wo,
    const float* __restrict__ Wi, const float* __restrict__ Wo2,
    const float* __restrict__ hs, const float* __restrict__ dist,
    float* __restrict__ wq, float* __restrict__ wk,
    float* __restrict__ wv, float* __restrict__ wo,
    float* __restrict__ wi, float* __restrict__ wo2,
    float* __restrict__ hs_tf, __nv_bfloat16* __restrict__ disth)
{
    int idx = blockIdx.x * blockDim.x + threadIdx.x;
    if (idx < CVT_SEG1) {
        const int which = idx >> 18;            // 262144 = 2^18
        const int rel   = idx & (CVT_W1 - 1);
        const float* in = (which == 0) ? Wq : (which == 1) ? Wk
                         : (which == 2) ? Wv : Wo;
        float* out      = (which == 0) ? wq : (which == 1) ? wk
                         : (which == 2) ? wv : wo;
        float4 v = ((const float4*)in)[rel];
        v.x = __uint_as_float(f2tf(v.x));
        v.y = __uint_as_float(f2tf(v.y));
        v.z = __uint_as_float(f2tf(v.z));
        v.w = __uint_as_float(f2tf(v.w));
        ((float4*)out)[rel] = v;
    } else if (idx < CVT_SEG2) {
        const int j     = idx - CVT_SEG1;
        const int which = j >> 20;              // 1048576 = 2^20
        const int rel   = j & (CVT_W4 - 1);
        const float* in = (which == 0) ? Wi : (which == 1) ? Wo2 : hs;
        float* out      = (which == 0) ? wi : (which == 1) ? wo2 : hs_tf;
        float4 v = ((const float4*)in)[rel];
        v.x = __uint_as_float(f2tf(v.x));
        v.y = __uint_as_float(f2tf(v.y));
        v.z = __uint_as_float(f2tf(v.z));
        v.w = __uint_as_float(f2tf(v.w));
        ((float4*)out)[rel] = v;
    } else if (idx < CVT_TOTAL) {
        const int rel = idx - CVT_SEG2;
        float4 v = ((const float4*)dist)[rel];
        uint2 o = make_uint2(pack_bf2(v.x, v.y), pack_bf2(v.z, v.w));
        ((uint2*)disth)[rel] = o;
    }
}

// ---------------- double-buffered tf32 GEMM ----------------------------------
#define GA(s,r,c) ((( (s)*128 + (r) )*36) + (c))
#define GB(s,r,c) ((( (s)*32  + (r) )*136) + (c))
#define GEMM_SMEM_BYTES ((2*128*36 + 2*32*136) * 4)

template <int GELU, int ROUND, int BFOUT>
__device__ __forceinline__ void gemm_body(
    const float* __restrict__ A, const float* __restrict__ Bm,
    const float* __restrict__ bias, void* __restrict__ Cout,
    int M, int N, int K, float* sm)
{
    float* As = sm;
    float* Bs = sm + 2 * 128 * 36;

    const int tid = threadIdx.x;
    const int w   = tid >> 5;
    const int l   = tid & 31;
    const int wr  = w >> 2;
    const int wc  = w & 3;
    const int m0  = blockIdx.y * 128;
    const int n0  = blockIdx.x * 128;
    const int g   = l >> 2;
    const int t4  = l & 3;

    const int ar = tid >> 3;
    const int ac = (tid & 7) << 2;
    const int br = tid >> 5;
    const int bc = (tid & 31) << 2;

    float c[4][4][4];
#pragma unroll
    for (int mi = 0; mi < 4; mi++)
#pragma unroll
        for (int ni = 0; ni < 4; ni++)
#pragma unroll
            for (int r = 0; r < 4; r++) c[mi][ni][r] = 0.f;

#pragma unroll
    for (int i = 0; i < 4; i++)
        cp16(&As[GA(0, ar + 32 * i, ac)], &A[(size_t)(m0 + ar + 32 * i) * K + ac]);
#pragma unroll
    for (int i = 0; i < 4; i++)
        cp16(&Bs[GB(0, br + 8 * i, bc)], &Bm[(size_t)(br + 8 * i) * N + n0 + bc]);
    CP_COMMIT();

    for (int k0 = 0; k0 < K; k0 += 32) {
        const int s = (k0 >> 5) & 1;
        CP_WAIT0();
        __syncthreads();
        if (k0 + 32 < K) {
            const int ns = s ^ 1;
            const int nk = k0 + 32;
#pragma unroll
            for (int i = 0; i < 4; i++)
                cp16(&As[GA(ns, ar + 32 * i, ac)],
                     &A[(size_t)(m0 + ar + 32 * i) * K + nk + ac]);
#pragma unroll
            for (int i = 0; i < 4; i++)
                cp16(&Bs[GB(ns, br + 8 * i, bc)],
                     &Bm[(size_t)(nk + br + 8 * i) * N + n0 + bc]);
            CP_COMMIT();
        }

#pragma unroll
        for (int kk = 0; kk < 4; kk++) {
            const int kb = kk * 8;
            uint32_t a[4][4], b[4][2];
#pragma unroll
            for (int mi = 0; mi < 4; mi++) {
                const int mrow = wr * 64 + mi * 16 + g;
                a[mi][0] = __float_as_uint(As[GA(s, mrow,     kb + t4)]);
                a[mi][1] = __float_as_uint(As[GA(s, mrow + 8, kb + t4)]);
                a[mi][2] = __float_as_uint(As[GA(s, mrow,     kb + t4 + 4)]);
                a[mi][3] = __float_as_uint(As[GA(s, mrow + 8, kb + t4 + 4)]);
            }
#pragma unroll
            for (int ni = 0; ni < 4; ni++) {
                const int ncol = wc * 32 + ni * 8 + g;
                b[ni][0] = __float_as_uint(Bs[GB(s, kb + t4,     ncol)]);
                b[ni][1] = __float_as_uint(Bs[GB(s, kb + t4 + 4, ncol)]);
            }
#pragma unroll
            for (int mi = 0; mi < 4; mi++)
#pragma unroll
                for (int ni = 0; ni < 4; ni++)
                    mma_tf32(c[mi][ni], a[mi], b[ni]);
        }
    }

#pragma unroll
    for (int mi = 0; mi < 4; mi++) {
#pragma unroll
        for (int ni = 0; ni < 4; ni++) {
            const int row = m0 + wr * 64 + mi * 16 + g;
            const int col = n0 + wc * 32 + ni * 8 + t4 * 2;
            const float b0 = bias[col], b1 = bias[col + 1];
            float v0 = c[mi][ni][0] + b0;
            float v1 = c[mi][ni][1] + b1;
            float v2 = c[mi][ni][2] + b0;
            float v3 = c[mi][ni][3] + b1;
            if (GELU) {
                v0 = 0.5f * v0 * (1.0f + erff(v0 * 0.70710678118654752f));
                v1 = 0.5f * v1 * (1.0f + erff(v1 * 0.70710678118654752f));
                v2 = 0.5f * v2 * (1.0f + erff(v2 * 0.70710678118654752f));
                v3 = 0.5f * v3 * (1.0f + erff(v3 * 0.70710678118654752f));
            }
            if (BFOUT) {
                __nv_bfloat16* C = (__nv_bfloat16*)Cout;
                *(uint32_t*)&C[(size_t)row * N + col]       = pack_bf2(v0, v1);
                *(uint32_t*)&C[(size_t)(row + 8) * N + col] = pack_bf2(v2, v3);
            } else {
                float* C = (float*)Cout;
                if (ROUND) {
                    v0 = __uint_as_float(f2tf(v0));
                    v1 = __uint_as_float(f2tf(v1));
                    v2 = __uint_as_float(f2tf(v2));
                    v3 = __uint_as_float(f2tf(v3));
                }
                *(float2*)&C[(size_t)row * N + col]       = make_float2(v0, v1);
                *(float2*)&C[(size_t)(row + 8) * N + col] = make_float2(v2, v3);
            }
        }
    }
}

template <int GELU, int ROUND>
__global__ void __launch_bounds__(256) gemm_db(
    const float* __restrict__ A, const float* __restrict__ Bm,
    const float* __restrict__ bias, float* __restrict__ C,
    int M, int N, int K)
{
    extern __shared__ float sm[];
    gemm_body<GELU, ROUND, 0>(A, Bm, bias, C, M, N, K, sm);
}

__global__ void __launch_bounds__(256) qkv_db(
    const float* __restrict__ A,
    const float* __restrict__ W0, const float* __restrict__ W1, const float* __restrict__ W2,
    const float* __restrict__ b0, const float* __restrict__ b1, const float* __restrict__ b2,
    __nv_bfloat16* __restrict__ o0, __nv_bfloat16* __restrict__ o1,
    __nv_bfloat16* __restrict__ o2)
{
    extern __shared__ float sm[];
    const int z = blockIdx.z;
    const float* W = (z == 0) ? W0 : (z == 1) ? W1 : W2;
    const float* bb = (z == 0) ? b0 : (z == 1) ? b1 : b2;
    __nv_bfloat16* O = (z == 0) ? o0 : (z == 1) ? o1 : o2;
    gemm_body<0, 0, 1>(A, W, bb, O, NTOK, HID, HID, sm);
}

// ---------------- LayerNorm(x + res) * g + b, float4, optional tf copy -------
__global__ void __launch_bounds__(256) ln_residual(
    const float* __restrict__ x, const float* __restrict__ res,
    const float* __restrict__ g, const float* __restrict__ b,
    float* __restrict__ out, float* __restrict__ out_tf)
{
    __shared__ float red[8];
    const int row = blockIdx.x;
    const int tid = threadIdx.x;
    const size_t base = (size_t)row * HID + tid * 4;

    float4 xv = *(const float4*)&x[base];
    float4 rv = *(const float4*)&res[base];
    float v0 = xv.x + rv.x, v1 = xv.y + rv.y, v2 = xv.z + rv.z, v3 = xv.w + rv.w;

    float s = v0 + v1 + v2 + v3;
#pragma unroll
    for (int o = 16; o; o >>= 1) s += __shfl_xor_sync(0xffffffffu, s, o);
    if ((tid & 31) == 0) red[tid >> 5] = s;
    __syncthreads();
    if (tid < 8) {
        s = red[tid];
#pragma unroll
        for (int o = 4; o; o >>= 1) s += __shfl_xor_sync(0xffu, s, o, 8);
        if (tid == 0) red[0] = s;
    }
    __syncthreads();
    const float mean = red[0] * (1.0f / HID);
    __syncthreads();

    float d0 = v0 - mean, d1 = v1 - mean, d2 = v2 - mean, d3 = v3 - mean;
    float vs = d0 * d0 + d1 * d1 + d2 * d2 + d3 * d3;
#pragma unroll
    for (int o = 16; o; o >>= 1) vs += __shfl_xor_sync(0xffffffffu, vs, o);
    if ((tid & 31) == 0) red[tid >> 5] = vs;
    __syncthreads();
    if (tid < 8) {
        vs = red[tid];
#pragma unroll
        for (int o = 4; o; o >>= 1) vs += __shfl_xor_sync(0xffu, vs, o, 8);
        if (tid == 0) red[0] = vs;
    }
    __syncthreads();
    const float inv = rsqrtf(red[0] * (1.0f / HID) + 1e-12f);

    float4 gv = *(const float4*)&g[tid * 4];
    float4 bv = *(const float4*)&b[tid * 4];
    float4 ov;
    ov.x = d0 * inv * gv.x + bv.x;
    ov.y = d1 * inv * gv.y + bv.y;
    ov.z = d2 * inv * gv.z + bv.z;
    ov.w = d3 * inv * gv.w + bv.w;
    *(float4*)&out[base] = ov;
    if (out_tf) {
        float4 tv;
        tv.x = __uint_as_float(f2tf(ov.x));
        tv.y = __uint_as_float(f2tf(ov.y));
        tv.z = __uint_as_float(f2tf(ov.z));
        tv.w = __uint_as_float(f2tf(ov.w));
        *(float4*)&out_tf[base] = tv;
    }
}

// ---------------- bf16 TC attention: ring + double buffer + B2 trim ----------
#define HST 72
#define BSTH 132
#define ATTN_SMEM_BYTES 108544

__global__ void __launch_bounds__(256, 2) attn_tc(
    const __nv_bfloat16* __restrict__ Q, const __nv_bfloat16* __restrict__ K,
    const __nv_bfloat16* __restrict__ V, const __nv_bfloat16* __restrict__ disth,
    const float* __restrict__ mask, const float* __restrict__ hm,
    float* __restrict__ ctx)
{
    extern __shared__ char smb[];
    __nv_bfloat16* Qh  = (__nv_bfloat16*)smb;       // [64][HST]
    __nv_bfloat16* Kh  = Qh + 64 * HST;             // [2][64][HST]
    __nv_bfloat16* Er  = Kh + 2 * 64 * HST;         // [128][HST] ring
    __nv_bfloat16* Vh  = Er + 128 * HST;            // [2][64][HST]
    __nv_bfloat16* B1h = Vh + 2 * 64 * HST;         // [64][BSTH]
    __nv_bfloat16* B2h = B1h + 64 * BSTH;           // [64][BSTH]
    __nv_bfloat16* Ph  = B2h + 64 * BSTH;           // [64][HST]
    float*         Rmax = (float*)(Ph + 64 * HST);  // [2][64]
    float*         Rsum = Rmax + 128;               // [2][64]

    const int tid = threadIdx.x;
    const int w   = tid >> 5;
    const int wm  = w & 3;
    const int wn  = w >> 2;
    const int l   = tid & 31;
    const int g   = l >> 2;
    const int t4  = l & 3;
    const int bh  = blockIdx.y;
    const int b   = bh >> 4;
    const int h   = bh & 15;
    const int l0  = blockIdx.x * 64;

    const int li0 = 16 * wm + g;
    const int li1 = li0 + 8;

    const int arow = 16 * wm + (l & 15);
    const int acol = (l >> 4) << 3;
    const uint32_t aQ = smem_u32(&Qh[arow * HST + acol]);
    const uint32_t aP = smem_u32(&Ph[arow * HST + acol]);
    const uint32_t aKb[2] = { smem_u32(&Kh[arow * HST + acol]),
                              smem_u32(&Kh[64 * HST + arow * HST + acol]) };
    const int brow = l & 7;
    const int bcol = ((l >> 3) & 1) << 3;
    const uint32_t bKb[2] = { smem_u32(&Kh[brow * HST + bcol]),
                              smem_u32(&Kh[64 * HST + brow * HST + bcol]) };
    const uint32_t bEbase = smem_u32(Er) + bcol * 2;
    const uint32_t bVb[2] = { smem_u32(&Vh[(l & 15) * HST]),
                              smem_u32(&Vh[64 * HST + (l & 15) * HST]) };

    const __nv_bfloat16* Qg = Q + (size_t)(b * SEQ + l0) * HID + h * HD;
    const __nv_bfloat16* Kg = K + (size_t)(b * SEQ) * HID + h * HD;
    const __nv_bfloat16* Vg = V + (size_t)(b * SEQ) * HID + h * HD;
    const float* mg = mask + b * SEQ;

    // ---- prologue
    for (int idx = tid; idx < 512; idx += 256) {
        int r = idx >> 3, c8 = (idx & 7) << 3;
        cp16h(&Qh[r * HST + c8], &Qg[(size_t)r * HID + c8]);
    }
    {
        const int dbase0 = l0 + 960;
        for (int idx = tid; idx < 1024; idx += 256) {
            int r = idx >> 3, c8 = (idx & 7) << 3;
            int row = dbase0 + r;
            int rowc = row > 2046 ? 2046 : row;   // pos-127 value unread
            cp16h(&Er[(row & 127) * HST + c8], &disth[(size_t)rowc * HD + c8]);
        }
        for (int idx = tid; idx < 512; idx += 256) {
            int r = idx >> 3, c8 = (idx & 7) << 3;
            cp16h(&Kh[r * HST + c8], &Kg[(size_t)r * HID + c8]);
            cp16h(&Vh[r * HST + c8], &Vg[(size_t)r * HID + c8]);
        }
    }
    CP_COMMIT();
    CP_WAIT0();
    __syncthreads();

    uint32_t aq[4][4];
#pragma unroll
    for (int kk = 0; kk < 4; kk++) ldsm_x4(aq[kk], aQ + kk * 32);

    float O[4][4];
#pragma unroll
    for (int ni = 0; ni < 4; ni++)
#pragma unroll
        for (int r = 0; r < 4; r++) O[ni][r] = 0.f;
    float mrow[2] = {-1e30f, -1e30f};
    float lrow[2] = {0.f, 0.f};

    // needed B2 window-col range for warp wm's rows: [48-16wm, 127-16wm)
    const int j0 = 48 - 16 * wm + wn * 40;

    for (int rt = 0; rt < 16; rt++) {
        const int r0 = rt * 64;
        const int dbase = l0 - r0 + 960;
        const int buf = rt & 1;
        if (rt) {
            CP_WAIT0();
            __syncthreads();
        }

        // ---- early K/V prefetch into dead buffer (overlaps all MMA below)
        if (rt < 15) {
            const int nbuf = buf ^ 1;
            const int nr0 = r0 + 64;
            for (int idx = tid; idx < 512; idx += 256) {
                int r = idx >> 3, c8 = (idx & 7) << 3;
                cp16h(&Kh[nbuf * 64 * HST + r * HST + c8],
                      &Kg[(size_t)(nr0 + r) * HID + c8]);
                cp16h(&Vh[nbuf * 64 * HST + r * HST + c8],
                      &Vg[(size_t)(nr0 + r) * HID + c8]);
            }
            CP_COMMIT();
        }

        uint32_t ak[4][4];
#pragma unroll
        for (int kk = 0; kk < 4; kk++) ldsm_x4(ak[kk], aKb[buf] + kk * 32);

        // ---- B2 = K @ E^T, trimmed to the needed band (5 tiles per warp)
        {
            float c[5][4];
#pragma unroll
            for (int ni = 0; ni < 5; ni++)
#pragma unroll
                for (int r = 0; r < 4; r++) c[ni][r] = 0.f;
#pragma unroll
            for (int kk = 0; kk < 4; kk++) {
#pragma unroll
                for (int ni = 0; ni < 5; ni++) {
                    const int j = j0 + ni * 8;
                    const int slot = (dbase + j + brow) & 127;
                    uint32_t bf[2];
                    ldsm_x2(bf, bEbase + slot * (HST * 2) + kk * 32);
                    mma_bf16(c[ni], ak[kk], bf);
                }
            }
#pragma unroll
            for (int ni = 0; ni < 5; ni++) {
                const int col = j0 + ni * 8 + 2 * t4;
                *(uint32_t*)&B2h[li0 * BSTH + col] = pack_bf2(c[ni][0], c[ni][1]);
                *(uint32_t*)&B2h[li1 * BSTH + col] = pack_bf2(c[ni][2], c[ni][3]);
            }
        }

        // ---- B1 new block(s): Q @ E_new^T
        const int nblk = (rt == 0) ? 2 : 1;
        for (int blk = 0; blk < nblk; blk++) {
            const int base = (dbase + 64 * blk) & 127;
            float c[4][4];
#pragma unroll
            for (int ni = 0; ni < 4; ni++)
#pragma unroll
                for (int r = 0; r < 4; r++) c[ni][r] = 0.f;
#pragma unroll
            for (int kk = 0; kk < 4; kk++) {
#pragma unroll
                for (int ni = 0; ni < 4; ni++) {
                    const int slot = base + wn * 32 + ni * 8 + brow;
                    uint32_t bf[2];
                    ldsm_x2(bf, bEbase + slot * (HST * 2) + kk * 32);
                    mma_bf16(c[ni], aq[kk], bf);
                }
            }
#pragma unroll
            for (int ni = 0; ni < 4; ni++) {
                const int col = base + wn * 32 + ni * 8 + 2 * t4;
                *(uint32_t*)&B1h[li0 * BSTH + col] = pack_bf2(c[ni][0], c[ni][1]);
                *(uint32_t*)&B1h[li1 * BSTH + col] = pack_bf2(c[ni][2], c[ni][3]);
            }
        }

        // ---- S = Q @ K^T
        float cS[4][4];
#pragma unroll
        for (int ni = 0; ni < 4; ni++)
#pragma unroll
            for (int r = 0; r < 4; r++) cS[ni][r] = 0.f;
#pragma unroll
        for (int kk = 0; kk < 4; kk++) {
#pragma unroll
            for (int ni = 0; ni < 4; ni++) {
                const int ncol = wn * 32 + ni * 8;
                uint32_t bf[2];
                ldsm_x2(bf, bKb[buf] + (ncol * HST) * 2 + kk * 32);
                mma_bf16(cS[ni], aq[kk], bf);
            }
        }
        __syncthreads();   // B1/B2 visible; E-ring reads done

        // ---- E prefetch into freed ring slots
        if (rt < 15) {
            const int ndbase = dbase - 64;
            for (int idx = tid; idx < 512; idx += 256) {
                int r = idx >> 3, c8 = (idx & 7) << 3;
                int row = ndbase + r;
                cp16h(&Er[(row & 127) * HST + c8], &disth[(size_t)row * HD + c8]);
            }
            CP_COMMIT();
        }

        // ---- bias gather + scale + mask
        const int dofs = dbase + 63;
        float vmax0 = -1e30f, vmax1 = -1e30f;
#pragma unroll
        for (int ni = 0; ni < 4; ni++) {
#pragma unroll
            for (int e = 0; e < 2; e++) {
                const int rj = wn * 32 + ni * 8 + 2 * t4 + e;
                const float mv = mg[r0 + rj];
                const int s0 = (dofs + li0 - rj) & 127;
                const int s1 = (dofs + li1 - rj) & 127;
                const int ib0 = li0 - rj + 63;
                const int ib1 = li1 - rj + 63;
                float b1a = __bfloat162float(B1h[li0 * BSTH + s0]);
                float b1b = __bfloat162float(B1h[li1 * BSTH + s1]);
                float b2a = __bfloat162float(B2h[rj * BSTH + ib0]);
                float b2b = __bfloat162float(B2h[rj * BSTH + ib1]);
                float v0 = (cS[ni][e]     + b1a + b2a) * 0.125f + mv;
                float v1 = (cS[ni][2 + e] + b1b + b2b) * 0.125f + mv;
                cS[ni][e]     = v0;
                cS[ni][2 + e] = v1;
                vmax0 = fmaxf(vmax0, v0);
                vmax1 = fmaxf(vmax1, v1);
            }
        }
        vmax0 = fmaxf(vmax0, __shfl_xor_sync(0xffffffffu, vmax0, 1));
        vmax0 = fmaxf(vmax0, __shfl_xor_sync(0xffffffffu, vmax0, 2));
        vmax1 = fmaxf(vmax1, __shfl_xor_sync(0xffffffffu, vmax1, 1));
        vmax1 = fmaxf(vmax1, __shfl_xor_sync(0xffffffffu, vmax1, 2));
        if (t4 == 0) {
            Rmax[wn * 64 + li0] = vmax0;
            Rmax[wn * 64 + li1] = vmax1;
        }
        __syncthreads();
        vmax0 = fmaxf(vmax0, Rmax[(wn ^ 1) * 64 + li0]);
        vmax1 = fmaxf(vmax1, Rmax[(wn ^ 1) * 64 + li1]);

        const float nm0 = fmaxf(mrow[0], vmax0);
        const float nm1 = fmaxf(mrow[1], vmax1);
        const float corr0 = __expf(mrow[0] - nm0);
        const float corr1 = __expf(mrow[1] - nm1);

        float ts0 = 0.f, ts1 = 0.f;
#pragma unroll
        for (int ni = 0; ni < 4; ni++) {
            const int cj = wn * 32 + ni * 8 + 2 * t4;
            float p00 = __expf(cS[ni][0] - nm0);
            float p01 = __expf(cS[ni][1] - nm0);
            float p10 = __expf(cS[ni][2] - nm1);
            float p11 = __expf(cS[ni][3] - nm1);
            *(uint32_t*)&Ph[li0 * HST + cj] = pack_bf2(p00, p01);
            *(uint32_t*)&Ph[li1 * HST + cj] = pack_bf2(p10, p11);
            ts0 += p00 + p01;
            ts1 += p10 + p11;
        }
        ts0 += __shfl_xor_sync(0xffffffffu, ts0, 1);
        ts0 += __shfl_xor_sync(0xffffffffu, ts0, 2);
        ts1 += __shfl_xor_sync(0xffffffffu, ts1, 1);
        ts1 += __shfl_xor_sync(0xffffffffu, ts1, 2);
        if (t4 == 0) {
            Rsum[wn * 64 + li0] = ts0;
            Rsum[wn * 64 + li1] = ts1;
        }
        __syncthreads();
        ts0 += Rsum[(wn ^ 1) * 64 + li0];
        ts1 += Rsum[(wn ^ 1) * 64 + li1];

        lrow[0] = lrow[0] * corr0 + ts0;
        lrow[1] = lrow[1] * corr1 + ts1;
        mrow[0] = nm0;
        mrow[1] = nm1;
#pragma unroll
        for (int ni = 0; ni < 4; ni++) {
            O[ni][0] *= corr0;
            O[ni][1] *= corr0;
            O[ni][2] *= corr1;
            O[ni][3] *= corr1;
        }

        // ---- PV: O += P @ V
#pragma unroll
        for (int kk = 0; kk < 4; kk++) {
            const int kb = kk * 16;
            uint32_t ap[4];
            ldsm_x4(ap, aP + kk * 32);
#pragma unroll
            for (int ni = 0; ni < 4; ni++) {
                const int nbase = wn * 32 + ni * 8;
                uint32_t bf[2];
                ldsm_x2t(bf, bVb[buf] + (kb * HST + nbase) * 2);
                mma_bf16(O[ni], ap, bf);
            }
        }
    }

    const float hscale = hm[h];
    const float inv0 = hscale / lrow[0];
    const float inv1 = hscale / lrow[1];
#pragma unroll
    for (int ni = 0; ni < 4; ni++) {
        const int col = h * HD + wn * 32 + ni * 8 + 2 * t4;
        const size_t row0g = (size_t)(b * SEQ + l0 + li0) * HID + col;
        const size_t row1g = (size_t)(b * SEQ + l0 + li1) * HID + col;
        float c00 = __uint_as_float(f2tf(O[ni][0] * inv0));
        float c01 = __uint_as_float(f2tf(O[ni][1] * inv0));
        float c10 = __uint_as_float(f2tf(O[ni][2] * inv1));
        float c11 = __uint_as_float(f2tf(O[ni][3] * inv1));
        *(float2*)&ctx[row0g] = make_float2(c00, c01);
        *(float2*)&ctx[row1g] = make_float2(c10, c11);
    }
}

// ---------------- launch ----------------
extern "C" void kernel_launch(void* const* d_in, const int* in_sizes, int n_in,
                              void* d_out, int out_size)
{
    const float* hs   = (const float*)d_in[0];
    const float* mask = (const float*)d_in[1];
    const float* hm   = (const float*)d_in[2];
    const float* Wq   = (const float*)d_in[3];
    const float* bq   = (const float*)d_in[4];
    const float* Wk   = (const float*)d_in[5];
    const float* bk   = (const float*)d_in[6];
    const float* Wv   = (const float*)d_in[7];
    const float* bv   = (const float*)d_in[8];
    const float* dist = (const float*)d_in[9];
    const float* Wo   = (const float*)d_in[10];
    const float* bo   = (const float*)d_in[11];
    const float* ln1g = (const float*)d_in[12];
    const float* ln1b = (const float*)d_in[13];
    const float* Wi   = (const float*)d_in[14];
    const float* bi   = (const float*)d_in[15];
    const float* Wo2  = (const float*)d_in[16];
    const float* bo2  = (const float*)d_in[17];
    const float* ln2g = (const float*)d_in[18];
    const float* ln2b = (const float*)d_in[19];
    float* out = (float*)d_out;

    __nv_bfloat16 *qh, *kh, *vh, *disth;
    float *ctx, *tmp, *attnout, *attnout_tf, *inter;
    float *hs_tf, *wq, *wk, *wv, *wo, *wi, *wo2;
    cudaGetSymbolAddress((void**)&qh,         g_qh);
    cudaGetSymbolAddress((void**)&kh,         g_kh);
    cudaGetSymbolAddress((void**)&vh,         g_vh);
    cudaGetSymbolAddress((void**)&disth,      g_disth);
    cudaGetSymbolAddress((void**)&ctx,        g_ctx);
    cudaGetSymbolAddress((void**)&tmp,        g_tmp);
    cudaGetSymbolAddress((void**)&attnout,    g_attnout);
    cudaGetSymbolAddress((void**)&attnout_tf, g_attnout_tf);
    cudaGetSymbolAddress((void**)&inter,      g_inter);
    cudaGetSymbolAddress((void**)&hs_tf,      g_hs_tf);
    cudaGetSymbolAddress((void**)&wq,         g_wq);
    cudaGetSymbolAddress((void**)&wk,         g_wk);
    cudaGetSymbolAddress((void**)&wv,         g_wv);
    cudaGetSymbolAddress((void**)&wo,         g_wo);
    cudaGetSymbolAddress((void**)&wi,         g_wi);
    cudaGetSymbolAddress((void**)&wo2,        g_wo2);

    cudaFuncSetAttribute(attn_tc, cudaFuncAttributeMaxDynamicSharedMemorySize,
                         ATTN_SMEM_BYTES);
    cudaFuncSetAttribute((const void*)gemm_db<0,0>,
                         cudaFuncAttributeMaxDynamicSharedMemorySize, GEMM_SMEM_BYTES);
    cudaFuncSetAttribute((const void*)gemm_db<1,1>,
                         cudaFuncAttributeMaxDynamicSharedMemorySize, GEMM_SMEM_BYTES);
    cudaFuncSetAttribute((const void*)qkv_db,
                         cudaFuncAttributeMaxDynamicSharedMemorySize, GEMM_SMEM_BYTES);

    dim3 blk(256);

    fused_cvt_k<<<(CVT_TOTAL + 255) / 256, blk>>>(
        Wq, Wk, Wv, Wo, Wi, Wo2, hs, dist,
        wq, wk, wv, wo, wi, wo2, hs_tf, disth);

    dim3 g_qkv(HID / 128, NTOK / 128, 3);
    dim3 g_1024(HID / 128, NTOK / 128);
    dim3 g_ff1(FFDIM / 128, NTOK / 128);

    qkv_db<<<g_qkv, blk, GEMM_SMEM_BYTES>>>(hs_tf, wq, wk, wv, bq, bk, bv,
                                            qh, kh, vh);

    attn_tc<<<dim3(SEQ / 64, BATCH * NHEAD), blk, ATTN_SMEM_BYTES>>>(
        qh, kh, vh, disth, mask, hm, ctx);

    gemm_db<0,0><<<g_1024, blk, GEMM_SMEM_BYTES>>>(ctx, wo, bo, tmp, NTOK, HID, HID);
    ln_residual<<<NTOK, blk>>>(tmp, hs, ln1g, ln1b, attnout, attnout_tf);

    gemm_db<1,1><<<g_ff1, blk, GEMM_SMEM_BYTES>>>(attnout_tf, wi, bi, inter,
                                                  NTOK, FFDIM, HID);
    gemm_db<0,0><<<g_1024, blk, GEMM_SMEM_BYTES>>>(inter, wo2, bo2, tmp,
                                                   NTOK, HID, FFDIM);
    ln_residual<<<NTOK, blk>>>(tmp, attnout, ln2g, ln2b, out, nullptr);
}